// round 2
// baseline (speedup 1.0000x reference)
#include <cuda_runtime.h>
#include <math.h>

#define Bn 2
#define Cn 96
#define Hn 128
#define Wn 256
#define WFn 129
#define HWn (Hn*Wn)
#define AUXn 101
#define MIDn 24
#define DMIDn 50
#define NTOT (Bn*Cn*HWn)
#define NF (Bn*Cn*Hn*WFn)
#define CDIV(a,b) (((a)+(b)-1)/(b))

// ------------------------- scratch (static device memory) -------------------
static __device__ float2 g_fft[(size_t)NF];
static __device__ float g_mag[NF];
static __device__ float g_t1[NF];
static __device__ float g_t2[NF];
static __device__ float g_fe[Bn*Hn*WFn];
static __device__ float g_fem[Bn*Hn*WFn];
static __device__ float g_gvec[Bn*3*Cn];
static __device__ float g_ca[Bn*Cn];
static __device__ float g_s0[Bn*3*HWn];
static __device__ float g_s1[Bn*3*HWn];
static __device__ float g_sa[Bn*HWn];
static __device__ float g_y[NTOT];
static __device__ float g_aux[(size_t)Bn*AUXn*HWn];
static __device__ float g_offb[Bn*18*HWn];
static __device__ float g_dg1o[(size_t)Bn*DMIDn*HWn];
static __device__ float g_gate[Bn*HWn];
static __device__ float g_ybase[NTOT];
static __device__ float g_z[NTOT];
static __device__ float g_defwt[9*96*96];
static __device__ float g_mu[Cn];
static __device__ float g_istd[Cn];

// ------------------------- FFT kernels --------------------------------------
// 256-pt complex FFT of a real row; keep bins 0..128.
__global__ void fft_rows_k(const float* __restrict__ in) {
    __shared__ float re[256], im[256];
    int row = blockIdx.x;                 // (b*C+c)*H + h
    const float* rp = in + (size_t)row * Wn;
    int tid = threadIdx.x;                // 128
    for (int i = tid; i < 256; i += 128) {
        int j = __brev((unsigned)i) >> 24;
        re[j] = rp[i];
        im[j] = 0.f;
    }
    __syncthreads();
    #pragma unroll
    for (int s = 1; s <= 8; s++) {
        int half = 1 << (s - 1);
        int i = tid;
        int off = i & (half - 1);
        int a = ((i >> (s - 1)) << s) + off;
        int bb = a + half;
        float ang = -6.2831853071795864f * (float)off / (float)(1 << s);
        float sn, cs; sincosf(ang, &sn, &cs);
        float br = re[bb], bi = im[bb];
        float ar = re[a],  ai = im[a];
        float xr = br*cs - bi*sn;
        float xi = br*sn + bi*cs;
        re[a] = ar + xr; im[a] = ai + xi;
        re[bb] = ar - xr; im[bb] = ai - xi;
        __syncthreads();
    }
    float2* op = g_fft + (size_t)row * WFn;
    for (int k = tid; k < WFn; k += 128)
        op[k] = make_float2(re[k], im[k]);
}

// 128-pt complex FFT down each column; write |.|/sqrt(H*W) into g_mag
__global__ void fft_cols_k() {
    __shared__ float re[128], im[128];
    int bx = blockIdx.x;                  // bc*WF + k
    int bc = bx / WFn, k = bx - bc*WFn;
    int tid = threadIdx.x;                // 64
    for (int h = tid; h < 128; h += 64) {
        float2 v = g_fft[((size_t)bc*Hn + h)*WFn + k];
        int j = __brev((unsigned)h) >> 25;
        re[j] = v.x; im[j] = v.y;
    }
    __syncthreads();
    #pragma unroll
    for (int s = 1; s <= 7; s++) {
        int half = 1 << (s - 1);
        int i = tid;
        int off = i & (half - 1);
        int a = ((i >> (s - 1)) << s) + off;
        int bb = a + half;
        float ang = -6.2831853071795864f * (float)off / (float)(1 << s);
        float sn, cs; sincosf(ang, &sn, &cs);
        float br = re[bb], bi = im[bb], ar = re[a], ai = im[a];
        float xr = br*cs - bi*sn, xi = br*sn + bi*cs;
        re[a] = ar + xr; im[a] = ai + xi;
        re[bb] = ar - xr; im[bb] = ai - xi;
        __syncthreads();
    }
    const float sc = 0.0055242717280199026f;  // 1/sqrt(128*256)
    for (int h = tid; h < 128; h += 64)
        g_mag[((size_t)bc*Hn + h)*WFn + k] = sqrtf(re[h]*re[h] + im[h]*im[h]) * sc;
}

// mean over channels of g_mag -> out[b][h][k]
__global__ void chan_mean_k(float* __restrict__ out) {
    int i = blockIdx.x*blockDim.x + threadIdx.x;
    if (i >= Bn*Hn*WFn) return;
    int b = i / (Hn*WFn); int r = i - b*Hn*WFn;
    float s = 0.f;
    #pragma unroll 4
    for (int c = 0; c < Cn; c++) s += g_mag[(size_t)(b*Cn + c)*Hn*WFn + r];
    out[i] = s * (1.f/Cn);
}

// ------------------------- frequency depthwise 7-tap convs ------------------
__global__ void dwfreq_h_k(const float* __restrict__ w7, const float* __restrict__ b7) {
    int i = blockIdx.x*blockDim.x + threadIdx.x;
    if (i >= NF) return;
    int k = i % WFn; int t = i / WFn; int h = t % Hn; int bc = t / Hn; int c = bc % Cn;
    float a = b7[c];
    #pragma unroll
    for (int d = 0; d < 7; d++) {
        int hh = h + d - 3;
        if (hh >= 0 && hh < Hn) a += w7[c*7+d] * g_mag[((size_t)bc*Hn + hh)*WFn + k];
    }
    g_t1[i] = a;
}

__global__ void dwfreq_w_k(const float* __restrict__ w7, const float* __restrict__ b7) {
    int i = blockIdx.x*blockDim.x + threadIdx.x;
    if (i >= NF) return;
    int k = i % WFn; int t = i / WFn; int bc = t / Hn; int c = bc % Cn;
    float a = b7[c];
    #pragma unroll
    for (int d = 0; d < 7; d++) {
        int kk = k + d - 3;
        if (kk >= 0 && kk < WFn) a += w7[c*7+d] * g_t1[(size_t)t*WFn + kk];
    }
    g_t2[i] = a;
}

// ------------------------- global pooled stats g1/g2/g3 ---------------------
__global__ void gpool_k() {
    __shared__ float S[4][WFn];
    __shared__ float bins[21];
    int bc = blockIdx.x; int b = bc / Cn, c = bc - b*Cn;
    int tid = threadIdx.x;                // 160
    if (tid < WFn) {
        float q0=0,q1=0,q2=0,q3=0;
        const float* tp = g_t2 + (size_t)bc*Hn*WFn + tid;
        for (int h = 0;  h < 32;  h++) q0 += tp[h*WFn];
        for (int h = 32; h < 64;  h++) q1 += tp[h*WFn];
        for (int h = 64; h < 96;  h++) q2 += tp[h*WFn];
        for (int h = 96; h < 128; h++) q3 += tp[h*WFn];
        S[0][tid]=q0; S[1][tid]=q1; S[2][tid]=q2; S[3][tid]=q3;
    }
    __syncthreads();
    if (tid < 16) {              // 4x4 adaptive bins (overlapping w bins!)
        int i = tid >> 2, j = tid & 3;
        int ws = (j*WFn)/4, we = ((j+1)*WFn + 3)/4;
        float s = 0;
        for (int k = ws; k < we; k++) s += S[i][k];
        bins[tid] = s / (32.f * (float)(we - ws));
    } else if (tid < 20) {       // 2x2 adaptive bins
        int t2 = tid - 16; int i = t2 >> 1, j = t2 & 1;
        int ws = (j*WFn)/2, we = ((j+1)*WFn + 1)/2;
        float s = 0;
        for (int k = ws; k < we; k++) s += S[2*i][k] + S[2*i+1][k];
        bins[tid] = s / (64.f * (float)(we - ws));
    } else if (tid == 20) {      // global mean
        float s = 0;
        for (int k = 0; k < WFn; k++) s += S[0][k]+S[1][k]+S[2][k]+S[3][k];
        bins[20] = s / (128.f*129.f);
    }
    __syncthreads();
    if (tid == 0) {
        float g2 = bins[16]+bins[17]+bins[18]+bins[19];
        float g3 = 0;
        for (int m = 0; m < 16; m++) g3 += bins[m];
        g_gvec[b*288 + c]        = bins[20];
        g_gvec[b*288 + Cn + c]   = g2 * 0.25f;
        g_gvec[b*288 + 2*Cn + c] = g3 * 0.0625f;
    }
}

// ------------------------- channel-attention MLP ----------------------------
__global__ void ca_mlp_k(const float* __restrict__ w1, const float* __restrict__ b1,
                         const float* __restrict__ w2, const float* __restrict__ b2) {
    __shared__ float gs[288], hs[MIDn];
    int b = blockIdx.x, tid = threadIdx.x;   // 96 threads
    for (int i = tid; i < 288; i += 96) gs[i] = g_gvec[b*288 + i];
    __syncthreads();
    if (tid < MIDn) {
        float a = b1[tid];
        for (int k = 0; k < 288; k++) a += w1[tid*288 + k]*gs[k];
        hs[tid] = fmaxf(a, 0.f);
    }
    __syncthreads();
    float a = b2[tid];
    #pragma unroll
    for (int m = 0; m < MIDn; m++) a += w2[tid*MIDn + m]*hs[m];
    g_ca[b*Cn + tid] = 1.f/(1.f + expf(-a));
}

// ------------------------- spatial branch -----------------------------------
__global__ void spatial_in_k(const float* __restrict__ x) {
    int i = blockIdx.x*blockDim.x + threadIdx.x;
    if (i >= Bn*HWn) return;
    int b = i / HWn; int hw = i - b*HWn; int h = hw / Wn; int w = hw - h*Wn;
    const float* xp = x + (size_t)b*Cn*HWn + hw;
    float s = 0.f, s2 = 0.f;
    #pragma unroll 4
    for (int c = 0; c < Cn; c++) { float v = xp[(size_t)c*HWn]; s += v; s2 += v*v; }
    float mean = s * (1.f/Cn);
    float l2 = sqrtf(s2 * (1.f/Cn) + 1e-6f);
    // bilinear upsample of g_fe (129->256, half-pixel + edge-clamp)
    float src = ((float)w + 0.5f)*(129.f/256.f) - 0.5f;
    float f0 = floorf(src); int i0 = (int)f0; float fr = src - f0;
    int ia = min(max(i0, 0), WFn-1), ib = min(max(i0+1, 0), WFn-1);
    const float* fp = g_fe + (size_t)b*Hn*WFn + h*WFn;
    float fv = fp[ia]*(1.f - fr) + fp[ib]*fr;
    g_s0[((size_t)(b*3+0))*HWn + hw] = mean;
    g_s0[((size_t)(b*3+1))*HWn + hw] = l2;
    g_s0[((size_t)(b*3+2))*HWn + hw] = fv;
}

__global__ void dwsp_h_k(const float* __restrict__ w15, const float* __restrict__ b15) {
    int i = blockIdx.x*blockDim.x + threadIdx.x;
    if (i >= Bn*3*HWn) return;
    int w = i % Wn; int t = i / Wn; int h = t % Hn; int bc = t / Hn; int ch = bc % 3;
    float a = b15[ch];
    #pragma unroll
    for (int d = 0; d < 15; d++) {
        int hh = h + d - 7;
        if (hh >= 0 && hh < Hn) a += w15[ch*15+d]*g_s0[((size_t)bc*Hn + hh)*Wn + w];
    }
    g_s1[i] = a;
}

__global__ void dwsp_w_k(const float* __restrict__ w15, const float* __restrict__ b15) {
    int i = blockIdx.x*blockDim.x + threadIdx.x;
    if (i >= Bn*3*HWn) return;
    int w = i % Wn; int t = i / Wn; int bc = t / Hn; int ch = bc % 3;
    float a = b15[ch];
    #pragma unroll
    for (int d = 0; d < 15; d++) {
        int ww = w + d - 7;
        if (ww >= 0 && ww < Wn) a += w15[ch*15+d]*g_s1[(size_t)t*Wn + ww];
    }
    g_s0[i] = a;   // overwrite s0 with filtered map
}

__global__ void sr_k(const float* __restrict__ sr1w, const float* __restrict__ sr1b,
                     const float* __restrict__ sr2w, const float* __restrict__ sr2b) {
    int i = blockIdx.x*blockDim.x + threadIdx.x;
    if (i >= Bn*HWn) return;
    int b = i / HWn; int hw = i - b*HWn; int h = hw / Wn; int w = hw - h*Wn;
    float acc = sr2b[0];
    #pragma unroll
    for (int g3 = 0; g3 < 3; g3++) {
        float v = sr1b[g3];
        #pragma unroll
        for (int ky = 0; ky < 3; ky++) {
            int hh = h + ky - 1; if (hh < 0 || hh >= Hn) continue;
            #pragma unroll
            for (int kx = 0; kx < 3; kx++) {
                int ww = w + kx - 1; if (ww < 0 || ww >= Wn) continue;
                v += sr1w[g3*9 + ky*3 + kx]*g_s0[((size_t)(b*3+g3)*Hn + hh)*Wn + ww];
            }
        }
        acc += sr2w[g3]*fmaxf(v, 0.f);
    }
    g_sa[i] = 1.f/(1.f + expf(-acc));
}

__global__ void ymul_k(const float* __restrict__ x) {
    int i = blockIdx.x*blockDim.x + threadIdx.x;
    if (i >= NTOT) return;
    int hw = i % HWn; int bc = i / HWn; int b = bc / Cn;
    g_y[i] = x[i] * g_ca[bc] * g_sa[b*HWn + hw];
}

// ------------------------- aux tensor for DCN -------------------------------
__global__ void yc2aux_k() {
    int i = blockIdx.x*blockDim.x + threadIdx.x;
    if (i >= NTOT) return;
    int hw = i % HWn; int bc = i / HWn; int b = bc / Cn; int c = bc - b*Cn;
    g_aux[((size_t)(b*AUXn + c))*HWn + hw] = g_y[i];
}

__global__ void auxmisc_k() {
    int i = blockIdx.x*blockDim.x + threadIdx.x;
    if (i >= Bn*HWn) return;
    int b = i / HWn; int hw = i - b*HWn; int h = hw / Wn; int w = hw - h*Wn;
    float theta = -3.14159265358979324f + (float)w * (6.2831853071795864f/255.f);
    float phi   = -1.57079632679489662f + (float)h * (3.14159265358979324f/127.f);
    size_t base = (size_t)b*AUXn*HWn + hw;
    g_aux[base + (size_t)96*HWn] = sinf(theta);
    g_aux[base + (size_t)97*HWn] = cosf(theta);
    g_aux[base + (size_t)98*HWn] = sinf(phi);
    g_aux[base + (size_t)99*HWn] = cosf(phi);
    float src = ((float)w + 0.5f)*(129.f/256.f) - 0.5f;
    float f0 = floorf(src); int i0 = (int)f0; float fr = src - f0;
    int ia = min(max(i0, 0), WFn-1), ib = min(max(i0+1, 0), WFn-1);
    const float* fp = g_fem + (size_t)b*Hn*WFn + h*WFn;
    g_aux[base + (size_t)100*HWn] = fp[ia]*(1.f - fr) + fp[ib]*fr;
}

// ------------------------- tiled 3x3 conv (implicit GEMM) -------------------
template<int CIN, int COUT, bool RELU>
__global__ __launch_bounds__(128)
void conv3x3_k(const float* __restrict__ in, const float* __restrict__ wgt,
               const float* __restrict__ bias, float* __restrict__ out) {
    constexpr int NO = (COUT + 31) / 32;
    constexpr int CB = 8;
    __shared__ float tile[CB][3][36];
    __shared__ float wsh[CB][COUT*9];
    int bx = blockIdx.x;
    int seg = bx & 7; int h = (bx >> 3) & (Hn - 1); int b = bx >> 10;
    int w0 = seg * 32;
    int tid = threadIdx.x;
    int pg = tid & 3, og = tid >> 2;
    float acc[NO][8];
    #pragma unroll
    for (int k = 0; k < NO; k++)
        #pragma unroll
        for (int p = 0; p < 8; p++) acc[k][p] = 0.f;
    const float* inb = in + (size_t)b*CIN*HWn;
    for (int c0 = 0; c0 < CIN; c0 += CB) {
        for (int m = tid; m < CB*3*34; m += 128) {
            int ci = m / 102; int rem = m - ci*102; int r = rem / 34; int cc = rem - r*34;
            int hh = h + r - 1, ww = w0 + cc - 1;
            float v = 0.f;
            if (c0 + ci < CIN && hh >= 0 && hh < Hn && ww >= 0 && ww < Wn)
                v = inb[(size_t)(c0 + ci)*HWn + hh*Wn + ww];
            tile[ci][r][cc] = v;
        }
        for (int m = tid; m < CB*COUT*9; m += 128) {
            int ci = m / (COUT*9); int rem = m - ci*(COUT*9);
            float v = 0.f;
            if (c0 + ci < CIN) {
                int o = rem / 9, j = rem - o*9;
                v = wgt[((size_t)o*CIN + c0 + ci)*9 + j];
            }
            wsh[ci][rem] = v;
        }
        __syncthreads();
        #pragma unroll 2
        for (int ci = 0; ci < CB; ci++) {
            float tv[3][10];
            #pragma unroll
            for (int r = 0; r < 3; r++) {
                const float* trow = &tile[ci][r][pg*8];
                float4 v0 = *(const float4*)(trow);
                float4 v1 = *(const float4*)(trow + 4);
                tv[r][0]=v0.x; tv[r][1]=v0.y; tv[r][2]=v0.z; tv[r][3]=v0.w;
                tv[r][4]=v1.x; tv[r][5]=v1.y; tv[r][6]=v1.z; tv[r][7]=v1.w;
                tv[r][8]=trow[8]; tv[r][9]=trow[9];
            }
            #pragma unroll
            for (int k = 0; k < NO; k++) {
                int o = og + 32*k;
                if ((COUT & 31) && o >= COUT) break;
                const float* wp = &wsh[ci][o*9];
                float w00=wp[0],w01=wp[1],w02=wp[2],
                      w10=wp[3],w11=wp[4],w12=wp[5],
                      w20=wp[6],w21=wp[7],w22=wp[8];
                #pragma unroll
                for (int p = 0; p < 8; p++) {
                    float a = acc[k][p];
                    a += w00*tv[0][p]; a += w01*tv[0][p+1]; a += w02*tv[0][p+2];
                    a += w10*tv[1][p]; a += w11*tv[1][p+1]; a += w12*tv[1][p+2];
                    a += w20*tv[2][p]; a += w21*tv[2][p+1]; a += w22*tv[2][p+2];
                    acc[k][p] = a;
                }
            }
        }
        __syncthreads();
    }
    #pragma unroll
    for (int k = 0; k < NO; k++) {
        int o = og + 32*k;
        if ((COUT & 31) && o >= COUT) break;
        float bb = bias[o];
        float* op = out + ((size_t)(b*COUT + o))*HWn + h*Wn + w0 + pg*8;
        #pragma unroll
        for (int p = 0; p < 8; p++) {
            float v = acc[k][p] + bb;
            if (RELU) v = fmaxf(v, 0.f);
            op[p] = v;
        }
    }
}

// ------------------------- gate head ----------------------------------------
__global__ void gate_k(const float* __restrict__ w2, const float* __restrict__ b2) {
    int i = blockIdx.x*blockDim.x + threadIdx.x;
    if (i >= Bn*HWn) return;
    int b = i / HWn; int hw = i - b*HWn;
    float a = b2[0];
    #pragma unroll 5
    for (int m = 0; m < DMIDn; m++)
        a += w2[m]*g_dg1o[((size_t)(b*DMIDn + m))*HWn + hw];
    g_gate[i] = 1.f/(1.f + expf(-a));
}

// ------------------------- def_w transpose ----------------------------------
__global__ void transpose_defw_k(const float* __restrict__ w) {
    int i = blockIdx.x*blockDim.x + threadIdx.x;
    if (i >= 9*96*96) return;
    int o = i % 96; int c = (i / 96) % 96; int t = i / (96*96);
    g_defwt[i] = w[((size_t)o*96 + c)*9 + t];
}

// ------------------------- deformable sampling + GEMM + combine -------------
__global__ __launch_bounds__(128)
void deform_combine_k(const float* __restrict__ defb) {
    __shared__ int   s_idx[9][32][4];
    __shared__ float s_w[9][32][4];
    __shared__ float samp[8][32];
    __shared__ float wsh2[8][96];
    int bx = blockIdx.x;
    int seg = bx & 7; int h = (bx >> 3) & (Hn - 1); int b = bx >> 10;
    int w0 = seg * 32;
    int tid = threadIdx.x;
    int pg = tid & 3, og = tid >> 2;

    // stage 1: tap indices/weights for 9 offsets x 32 pixels
    for (int e = tid; e < 288; e += 128) {
        int t9 = e >> 5, p = e & 31;
        int wpx = w0 + p;
        size_t obase = ((size_t)b*18)*HWn + (size_t)h*Wn + wpx;
        float ox = g_offb[obase + (size_t)(2*t9)*HWn];
        float oy = g_offb[obase + (size_t)(2*t9+1)*HWn];
        float px = (float)wpx + ox;
        float py = (float)h + oy;
        float x0 = floorf(px), y0 = floorf(py);
        float fx = px - x0, fy = py - y0;
        #pragma unroll
        for (int j = 0; j < 4; j++) {
            float xj = x0 + (float)(j & 1);
            float yj = y0 + (float)(j >> 1);
            float valid = (xj >= 0.f && xj <= 255.f && yj >= 0.f && yj <= 127.f) ? 1.f : 0.f;
            float xc = fminf(fmaxf(xj, 0.f), 255.f);
            float yc = fminf(fmaxf(yj, 0.f), 127.f);
            s_idx[t9][p][j] = (int)yc * Wn + (int)xc;
            float wx = (j & 1) ? fx : (1.f - fx);
            float wy = (j >> 1) ? fy : (1.f - fy);
            s_w[t9][p][j] = wx * wy * valid;
        }
    }

    float acc[3][8];
    #pragma unroll
    for (int k = 0; k < 3; k++)
        #pragma unroll
        for (int p = 0; p < 8; p++) acc[k][p] = 0.f;

    for (int t9 = 0; t9 < 9; t9++) {
        for (int c0 = 0; c0 < 96; c0 += 8) {
            __syncthreads();
            for (int e = tid; e < 768; e += 128) {
                int c = e / 96; int o = e - c*96;
                wsh2[c][o] = g_defwt[((size_t)(t9*96) + c0 + c)*96 + o];
            }
            for (int e = tid; e < 256; e += 128) {
                int c = e >> 5, p = e & 31;
                const float* yp = g_y + ((size_t)(b*Cn + c0 + c))*HWn;
                const int* ip = s_idx[t9][p];
                const float* wp = s_w[t9][p];
                samp[c][p] = wp[0]*yp[ip[0]] + wp[1]*yp[ip[1]]
                           + wp[2]*yp[ip[2]] + wp[3]*yp[ip[3]];
            }
            __syncthreads();
            #pragma unroll
            for (int c = 0; c < 8; c++) {
                const float4* sp = (const float4*)&samp[c][pg*8];
                float4 a0 = sp[0], a1 = sp[1];
                float sv[8] = {a0.x,a0.y,a0.z,a0.w,a1.x,a1.y,a1.z,a1.w};
                #pragma unroll
                for (int k = 0; k < 3; k++) {
                    float wv = wsh2[c][og + 32*k];
                    #pragma unroll
                    for (int p = 0; p < 8; p++) acc[k][p] += wv * sv[p];
                }
            }
        }
    }
    // epilogue: z = (1-gate)*y_base + gate*(acc + def_b)
    #pragma unroll
    for (int k = 0; k < 3; k++) {
        int o = og + 32*k;
        float bb = defb[o];
        #pragma unroll
        for (int p = 0; p < 8; p++) {
            int col = w0 + pg*8 + p;
            size_t oidx = ((size_t)(b*Cn + o))*HWn + (size_t)h*Wn + col;
            float gt = g_gate[(size_t)b*HWn + h*Wn + col];
            float ydef = acc[k][p] + bb;
            g_z[oidx] = (1.f - gt)*g_ybase[oidx] + gt*ydef;
        }
    }
}

// ------------------------- batchnorm ----------------------------------------
__global__ void bn_stats_k() {
    __shared__ float ss[256], ss2[256];
    int c = blockIdx.x, tid = threadIdx.x;
    float s = 0.f, s2 = 0.f;
    for (int i = tid; i < Bn*HWn; i += 256) {
        int b = i / HWn, hw = i - b*HWn;
        float v = g_z[((size_t)(b*Cn + c))*HWn + hw];
        s += v; s2 += v*v;
    }
    ss[tid] = s; ss2[tid] = s2;
    __syncthreads();
    for (int st = 128; st > 0; st >>= 1) {
        if (tid < st) { ss[tid] += ss[tid+st]; ss2[tid] += ss2[tid+st]; }
        __syncthreads();
    }
    if (tid == 0) {
        float inv = 1.f/(float)(Bn*HWn);
        float mu = ss[0]*inv;
        float var = ss2[0]*inv - mu*mu;
        g_mu[c] = mu;
        g_istd[c] = rsqrtf(var + 1e-5f);
    }
}

__global__ void bn_apply_k(const float* __restrict__ x,
                           const float* __restrict__ gam, const float* __restrict__ bet,
                           float* __restrict__ out) {
    int i = blockIdx.x*blockDim.x + threadIdx.x;
    if (i >= NTOT) return;
    int c = (i / HWn) % Cn;
    float zn = (g_z[i] - g_mu[c]) * g_istd[c] * gam[c] + bet[c];
    out[i] = fmaxf(zn + x[i], 0.f);
}

// ------------------------- launch -------------------------------------------
extern "C" void kernel_launch(void* const* d_in, const int* in_sizes, int n_in,
                              void* d_out, int out_size) {
    const float* x     = (const float*)d_in[0];
    const float* fdh_w = (const float*)d_in[1];
    const float* fdh_b = (const float*)d_in[2];
    const float* fdw_w = (const float*)d_in[3];
    const float* fdw_b = (const float*)d_in[4];
    const float* cp1_w = (const float*)d_in[5];
    const float* cp1_b = (const float*)d_in[6];
    const float* cp2_w = (const float*)d_in[7];
    const float* cp2_b = (const float*)d_in[8];
    const float* sdh_w = (const float*)d_in[9];
    const float* sdh_b = (const float*)d_in[10];
    const float* sdw_w = (const float*)d_in[11];
    const float* sdw_b = (const float*)d_in[12];
    const float* sr1_w = (const float*)d_in[13];
    const float* sr1_b = (const float*)d_in[14];
    const float* sr2_w = (const float*)d_in[15];
    const float* sr2_b = (const float*)d_in[16];
    const float* off_w = (const float*)d_in[17];
    const float* off_b = (const float*)d_in[18];
    const float* dg1_w = (const float*)d_in[19];
    const float* dg1_b = (const float*)d_in[20];
    const float* dg2_w = (const float*)d_in[21];
    const float* dg2_b = (const float*)d_in[22];
    const float* base_w = (const float*)d_in[23];
    const float* base_b = (const float*)d_in[24];
    const float* def_w = (const float*)d_in[25];
    const float* def_b = (const float*)d_in[26];
    const float* bn_g  = (const float*)d_in[27];
    const float* bn_b  = (const float*)d_in[28];
    float* out = (float*)d_out;

    float *p_y, *p_fe, *p_fem, *p_aux, *p_offb, *p_dg1o, *p_ybase;
    cudaGetSymbolAddress((void**)&p_y, g_y);
    cudaGetSymbolAddress((void**)&p_fe, g_fe);
    cudaGetSymbolAddress((void**)&p_fem, g_fem);
    cudaGetSymbolAddress((void**)&p_aux, g_aux);
    cudaGetSymbolAddress((void**)&p_offb, g_offb);
    cudaGetSymbolAddress((void**)&p_dg1o, g_dg1o);
    cudaGetSymbolAddress((void**)&p_ybase, g_ybase);

    // ---- FFT(x) -> mag, fe ----
    fft_rows_k<<<Bn*Cn*Hn, 128>>>(x);
    fft_cols_k<<<Bn*Cn*WFn, 64>>>();
    chan_mean_k<<<CDIV(Bn*Hn*WFn,256), 256>>>(p_fe);
    // ---- freq depthwise + pooled stats + channel MLP ----
    dwfreq_h_k<<<CDIV(NF,256), 256>>>(fdh_w, fdh_b);
    dwfreq_w_k<<<CDIV(NF,256), 256>>>(fdw_w, fdw_b);
    gpool_k<<<Bn*Cn, 160>>>();
    ca_mlp_k<<<Bn, 96>>>(cp1_w, cp1_b, cp2_w, cp2_b);
    // ---- spatial branch ----
    spatial_in_k<<<CDIV(Bn*HWn,256), 256>>>(x);
    dwsp_h_k<<<CDIV(Bn*3*HWn,256), 256>>>(sdh_w, sdh_b);
    dwsp_w_k<<<CDIV(Bn*3*HWn,256), 256>>>(sdw_w, sdw_b);
    sr_k<<<CDIV(Bn*HWn,256), 256>>>(sr1_w, sr1_b, sr2_w, sr2_b);
    ymul_k<<<CDIV(NTOT,256), 256>>>(x);
    // ---- FFT(y) -> mag, fem ----
    fft_rows_k<<<Bn*Cn*Hn, 128>>>(p_y);
    fft_cols_k<<<Bn*Cn*WFn, 64>>>();
    chan_mean_k<<<CDIV(Bn*Hn*WFn,256), 256>>>(p_fem);
    // ---- aux assembly ----
    yc2aux_k<<<CDIV(NTOT,256), 256>>>();
    auxmisc_k<<<CDIV(Bn*HWn,256), 256>>>();
    // ---- convs ----
    conv3x3_k<AUXn,18,false><<<2048, 128>>>(p_aux, off_w, off_b, p_offb);
    conv3x3_k<AUXn,50,true><<<2048, 128>>>(p_aux, dg1_w, dg1_b, p_dg1o);
    gate_k<<<CDIV(Bn*HWn,256), 256>>>(dg2_w, dg2_b);
    conv3x3_k<Cn,96,false><<<2048, 128>>>(p_y, base_w, base_b, p_ybase);
    // ---- deformable ----
    transpose_defw_k<<<CDIV(9*96*96,256), 256>>>(def_w);
    deform_combine_k<<<2048, 128>>>(def_b);
    // ---- BN + residual relu ----
    bn_stats_k<<<Cn, 256>>>();
    bn_apply_k<<<CDIV(NTOT,256), 256>>>(x, bn_g, bn_b, out);
}

// round 3
// speedup vs baseline: 1.0092x; 1.0092x over previous
#include <cuda_runtime.h>
#include <math.h>

#define Bn 2
#define Cn 96
#define Hn 128
#define Wn 256
#define WFn 129
#define HWn (Hn*Wn)
#define AUXn 101
#define MIDn 24
#define DMIDn 50
#define NTOT (Bn*Cn*HWn)
#define NF (Bn*Cn*Hn*WFn)
#define CDIV(a,b) (((a)+(b)-1)/(b))

// ------------------------- scratch (static device memory) -------------------
static __device__ float2 g_tw[128];
static __device__ float2 g_fft[(size_t)NF];
static __device__ float g_mag[NF];
static __device__ float g_t1[NF];
static __device__ float g_t2[NF];
static __device__ float g_fe[Bn*Hn*WFn];
static __device__ float g_fem[Bn*Hn*WFn];
static __device__ float g_gvec[Bn*3*Cn];
static __device__ float g_ca[Bn*Cn];
static __device__ float g_s0[Bn*3*HWn];
static __device__ float g_s1[Bn*3*HWn];
static __device__ float g_sa[Bn*HWn];
static __device__ float g_aux[(size_t)Bn*AUXn*HWn];
static __device__ float g_offb[Bn*18*HWn];
static __device__ float g_gate[Bn*HWn];
static __device__ float g_ybase[NTOT];
static __device__ float g_z[NTOT];
static __device__ float g_defwt[9*96*96];
static __device__ float g_mu[Cn];
static __device__ float g_istd[Cn];

// ------------------------- twiddle init -------------------------------------
__global__ void tw_init_k() {
    int j = threadIdx.x;           // 128
    float ang = -6.2831853071795864f * (float)j / 256.f;
    float s, c; sincosf(ang, &s, &c);
    g_tw[j] = make_float2(c, s);
}

// ------------------------- FFT kernels --------------------------------------
// Two real rows packed into one 256-pt complex FFT; unpack to two spectra.
__global__ void fft_rows_k(const float* __restrict__ in, int cstride) {
    __shared__ float re[256], im[256];
    __shared__ float2 tws[128];
    int h0 = blockIdx.x * 2;
    int c = blockIdx.y, b = blockIdx.z;
    const float* r0 = in + ((size_t)(b*cstride + c)*Hn + h0)*Wn;
    const float* r1 = r0 + Wn;
    int tid = threadIdx.x;                // 128
    tws[tid] = g_tw[tid];
    for (int i = tid; i < 256; i += 128) {
        int j = __brev((unsigned)i) >> 24;
        re[j] = r0[i];
        im[j] = r1[i];
    }
    __syncthreads();
    #pragma unroll
    for (int s = 1; s <= 8; s++) {
        int half = 1 << (s - 1);
        int i = tid;
        int off = i & (half - 1);
        int a = ((i >> (s - 1)) << s) + off;
        int bb = a + half;
        float2 tw = tws[off << (8 - s)];
        float br = re[bb], bi = im[bb];
        float ar = re[a],  ai = im[a];
        float xr = br*tw.x - bi*tw.y;
        float xi = br*tw.y + bi*tw.x;
        re[a] = ar + xr; im[a] = ai + xi;
        re[bb] = ar - xr; im[bb] = ai - xi;
        __syncthreads();
    }
    float2* out0 = g_fft + ((size_t)(b*Cn + c)*Hn + h0)*WFn;
    float2* out1 = out0 + WFn;
    int k = tid;
    float zr = re[k], zi = im[k];
    int km = (256 - k) & 255;
    float wr = re[km], wi = im[km];
    out0[k] = make_float2(0.5f*(zr + wr), 0.5f*(zi - wi));
    out1[k] = make_float2(0.5f*(zi + wi), -0.5f*(zr - wr));
    if (tid == 0) {
        out0[128] = make_float2(re[128], 0.f);
        out1[128] = make_float2(im[128], 0.f);
    }
}

// 128-pt FFT down columns, 16 columns per block (coalesced), |.| * 1/sqrt(HW)
__global__ void fft_cols_k() {
    __shared__ float cre[16][129];
    __shared__ float cim[16][129];
    __shared__ float2 tws[128];
    int kb = blockIdx.x;                  // 0..8
    int c = blockIdx.y, b = blockIdx.z;
    int bc = b*Cn + c;
    int k0 = kb * 16;
    int ncols = (kb < 8) ? 16 : 1;
    int lg = (kb < 8) ? 4 : 0;
    int tid = threadIdx.x;                // 128
    tws[tid] = g_tw[tid];
    int kk = tid & 15, ht = tid >> 4;
    const float2* src = g_fft + (size_t)bc*Hn*WFn;
    for (int hb = 0; hb < 16; hb++) {
        int h = hb*8 + ht;
        if (kk < ncols) {
            float2 v = src[(size_t)h*WFn + k0 + kk];
            int j = __brev((unsigned)h) >> 25;
            cre[kk][j] = v.x; cim[kk][j] = v.y;
        }
    }
    __syncthreads();
    #pragma unroll
    for (int s = 1; s <= 7; s++) {
        int half = 1 << (s - 1);
        int total = ncols << 6;
        for (int e = tid; e < total; e += 128) {
            int col = e & (ncols - 1);
            int i = e >> lg;
            int off = i & (half - 1);
            int a = ((i >> (s - 1)) << s) + off;
            int bb = a + half;
            float2 tw = tws[off << (8 - s)];
            float br = cre[col][bb], bi = cim[col][bb];
            float ar = cre[col][a],  ai = cim[col][a];
            float xr = br*tw.x - bi*tw.y;
            float xi = br*tw.y + bi*tw.x;
            cre[col][a] = ar + xr; cim[col][a] = ai + xi;
            cre[col][bb] = ar - xr; cim[col][bb] = ai - xi;
        }
        __syncthreads();
    }
    const float sc = 0.0055242717280199026f;  // 1/sqrt(128*256)
    float* dst = g_mag + (size_t)bc*Hn*WFn;
    int total = ncols << 7;
    for (int e = tid; e < total; e += 128) {
        int col = e & (ncols - 1);
        int h = e >> lg;
        float r = cre[col][h], m = cim[col][h];
        dst[(size_t)h*WFn + k0 + col] = sqrtf(r*r + m*m) * sc;
    }
}

// mean over channels of g_mag -> out[b][h][k]
__global__ void chan_mean_k(float* __restrict__ out) {
    int h = blockIdx.x, b = blockIdx.y;
    for (int k = threadIdx.x; k < WFn; k += 160) {
        float s = 0.f;
        const float* p = g_mag + ((size_t)(b*Cn)*Hn + h)*WFn + k;
        #pragma unroll 4
        for (int c = 0; c < Cn; c++) s += p[(size_t)c*Hn*WFn];
        out[(size_t)(b*Hn + h)*WFn + k] = s * (1.f/Cn);
    }
}

// ------------------------- frequency depthwise 7-tap convs ------------------
__global__ void dwfreq_h_k(const float* __restrict__ w7, const float* __restrict__ b7) {
    int h = blockIdx.x, c = blockIdx.y, b = blockIdx.z;
    int bc = b*Cn + c;
    float wv[7];
    #pragma unroll
    for (int d = 0; d < 7; d++) wv[d] = w7[c*7+d];
    float bias = b7[c];
    const float* base = g_mag + (size_t)bc*Hn*WFn;
    for (int k = threadIdx.x; k < WFn; k += 160) {
        float a = bias;
        #pragma unroll
        for (int d = 0; d < 7; d++) {
            int hh = h + d - 3;
            if (hh >= 0 && hh < Hn) a += wv[d]*base[(size_t)hh*WFn + k];
        }
        g_t1[(size_t)bc*Hn*WFn + (size_t)h*WFn + k] = a;
    }
}

__global__ void dwfreq_w_k(const float* __restrict__ w7, const float* __restrict__ b7) {
    __shared__ float row[WFn];
    int h = blockIdx.x, c = blockIdx.y, b = blockIdx.z;
    int bc = b*Cn + c;
    float wv[7];
    #pragma unroll
    for (int d = 0; d < 7; d++) wv[d] = w7[c*7+d];
    float bias = b7[c];
    size_t rbase = (size_t)bc*Hn*WFn + (size_t)h*WFn;
    for (int k = threadIdx.x; k < WFn; k += 160) row[k] = g_t1[rbase + k];
    __syncthreads();
    for (int k = threadIdx.x; k < WFn; k += 160) {
        float a = bias;
        #pragma unroll
        for (int d = 0; d < 7; d++) {
            int kk = k + d - 3;
            if (kk >= 0 && kk < WFn) a += wv[d]*row[kk];
        }
        g_t2[rbase + k] = a;
    }
}

// ------------------------- global pooled stats g1/g2/g3 ---------------------
__global__ void gpool_k() {
    __shared__ float S[4][WFn];
    __shared__ float bins[21];
    int bc = blockIdx.x; int b = bc / Cn, c = bc - b*Cn;
    int tid = threadIdx.x;                // 160
    if (tid < WFn) {
        float q0=0,q1=0,q2=0,q3=0;
        const float* tp = g_t2 + (size_t)bc*Hn*WFn + tid;
        for (int h = 0;  h < 32;  h++) q0 += tp[h*WFn];
        for (int h = 32; h < 64;  h++) q1 += tp[h*WFn];
        for (int h = 64; h < 96;  h++) q2 += tp[h*WFn];
        for (int h = 96; h < 128; h++) q3 += tp[h*WFn];
        S[0][tid]=q0; S[1][tid]=q1; S[2][tid]=q2; S[3][tid]=q3;
    }
    __syncthreads();
    if (tid < 16) {
        int i = tid >> 2, j = tid & 3;
        int ws = (j*WFn)/4, we = ((j+1)*WFn + 3)/4;
        float s = 0;
        for (int k = ws; k < we; k++) s += S[i][k];
        bins[tid] = s / (32.f * (float)(we - ws));
    } else if (tid < 20) {
        int t2 = tid - 16; int i = t2 >> 1, j = t2 & 1;
        int ws = (j*WFn)/2, we = ((j+1)*WFn + 1)/2;
        float s = 0;
        for (int k = ws; k < we; k++) s += S[2*i][k] + S[2*i+1][k];
        bins[tid] = s / (64.f * (float)(we - ws));
    } else if (tid == 20) {
        float s = 0;
        for (int k = 0; k < WFn; k++) s += S[0][k]+S[1][k]+S[2][k]+S[3][k];
        bins[20] = s / (128.f*129.f);
    }
    __syncthreads();
    if (tid == 0) {
        float g2 = bins[16]+bins[17]+bins[18]+bins[19];
        float g3 = 0;
        for (int m = 0; m < 16; m++) g3 += bins[m];
        g_gvec[b*288 + c]        = bins[20];
        g_gvec[b*288 + Cn + c]   = g2 * 0.25f;
        g_gvec[b*288 + 2*Cn + c] = g3 * 0.0625f;
    }
}

// ------------------------- channel-attention MLP ----------------------------
__global__ void ca_mlp_k(const float* __restrict__ w1, const float* __restrict__ b1,
                         const float* __restrict__ w2, const float* __restrict__ b2) {
    __shared__ float gs[288], hs[MIDn];
    int b = blockIdx.x, tid = threadIdx.x;   // 96 threads
    for (int i = tid; i < 288; i += 96) gs[i] = g_gvec[b*288 + i];
    __syncthreads();
    if (tid < MIDn) {
        float a = b1[tid];
        for (int k = 0; k < 288; k++) a += w1[tid*288 + k]*gs[k];
        hs[tid] = fmaxf(a, 0.f);
    }
    __syncthreads();
    float a = b2[tid];
    #pragma unroll
    for (int m = 0; m < MIDn; m++) a += w2[tid*MIDn + m]*hs[m];
    g_ca[b*Cn + tid] = 1.f/(1.f + expf(-a));
}

// ------------------------- spatial branch -----------------------------------
__global__ void spatial_in_k(const float* __restrict__ x) {
    int h = blockIdx.x, b = blockIdx.y;
    int w = threadIdx.x;                  // 256
    int hw = h*Wn + w;
    const float* xp = x + (size_t)b*Cn*HWn + hw;
    float s = 0.f, s2 = 0.f;
    #pragma unroll 4
    for (int c = 0; c < Cn; c++) { float v = xp[(size_t)c*HWn]; s += v; s2 += v*v; }
    float mean = s * (1.f/Cn);
    float l2 = sqrtf(s2 * (1.f/Cn) + 1e-6f);
    float src = ((float)w + 0.5f)*(129.f/256.f) - 0.5f;
    float f0 = floorf(src); int i0 = (int)f0; float fr = src - f0;
    int ia = min(max(i0, 0), WFn-1), ib = min(max(i0+1, 0), WFn-1);
    const float* fp = g_fe + (size_t)(b*Hn + h)*WFn;
    float fv = fp[ia]*(1.f - fr) + fp[ib]*fr;
    g_s0[((size_t)(b*3+0))*HWn + hw] = mean;
    g_s0[((size_t)(b*3+1))*HWn + hw] = l2;
    g_s0[((size_t)(b*3+2))*HWn + hw] = fv;
}

__global__ void dwsp_h_k(const float* __restrict__ w15, const float* __restrict__ b15) {
    int i = blockIdx.x*blockDim.x + threadIdx.x;
    if (i >= Bn*3*HWn) return;
    int w = i & (Wn-1); int t = i >> 8; int h = t & (Hn-1); int bc = t >> 7; int ch = bc % 3;
    float a = b15[ch];
    #pragma unroll
    for (int d = 0; d < 15; d++) {
        int hh = h + d - 7;
        if (hh >= 0 && hh < Hn) a += w15[ch*15+d]*g_s0[((size_t)bc*Hn + hh)*Wn + w];
    }
    g_s1[i] = a;
}

__global__ void dwsp_w_k(const float* __restrict__ w15, const float* __restrict__ b15) {
    int i = blockIdx.x*blockDim.x + threadIdx.x;
    if (i >= Bn*3*HWn) return;
    int w = i & (Wn-1); int t = i >> 8; int bc = t >> 7; int ch = bc % 3;
    float a = b15[ch];
    #pragma unroll
    for (int d = 0; d < 15; d++) {
        int ww = w + d - 7;
        if (ww >= 0 && ww < Wn) a += w15[ch*15+d]*g_s1[(size_t)t*Wn + ww];
    }
    g_s0[i] = a;
}

__global__ void sr_k(const float* __restrict__ sr1w, const float* __restrict__ sr1b,
                     const float* __restrict__ sr2w, const float* __restrict__ sr2b) {
    int i = blockIdx.x*blockDim.x + threadIdx.x;
    if (i >= Bn*HWn) return;
    int b = i >> 15; int hw = i & (HWn-1); int h = hw >> 8; int w = hw & (Wn-1);
    float acc = sr2b[0];
    #pragma unroll
    for (int g3 = 0; g3 < 3; g3++) {
        float v = sr1b[g3];
        #pragma unroll
        for (int ky = 0; ky < 3; ky++) {
            int hh = h + ky - 1; if (hh < 0 || hh >= Hn) continue;
            #pragma unroll
            for (int kx = 0; kx < 3; kx++) {
                int ww = w + kx - 1; if (ww < 0 || ww >= Wn) continue;
                v += sr1w[g3*9 + ky*3 + kx]*g_s0[((size_t)(b*3+g3)*Hn + hh)*Wn + ww];
            }
        }
        acc += sr2w[g3]*fmaxf(v, 0.f);
    }
    g_sa[i] = 1.f/(1.f + expf(-acc));
}

// y = x*ca*sa written directly into aux channels [0..95]
__global__ void ymul_k(const float* __restrict__ x) {
    int hw = blockIdx.x*256 + threadIdx.x;
    int c = blockIdx.y, b = blockIdx.z;
    float v = x[((size_t)(b*Cn + c))*HWn + hw] * g_ca[b*Cn + c] * g_sa[(size_t)b*HWn + hw];
    g_aux[((size_t)(b*AUXn + c))*HWn + hw] = v;
}

__global__ void auxmisc_k() {
    int h = blockIdx.x, b = blockIdx.y;
    int w = threadIdx.x;                 // 256
    int hw = h*Wn + w;
    float theta = -3.14159265358979324f + (float)w * (6.2831853071795864f/255.f);
    float phi   = -1.57079632679489662f + (float)h * (3.14159265358979324f/127.f);
    size_t base = (size_t)b*AUXn*HWn + hw;
    g_aux[base + (size_t)96*HWn] = sinf(theta);
    g_aux[base + (size_t)97*HWn] = cosf(theta);
    g_aux[base + (size_t)98*HWn] = sinf(phi);
    g_aux[base + (size_t)99*HWn] = cosf(phi);
    float src = ((float)w + 0.5f)*(129.f/256.f) - 0.5f;
    float f0 = floorf(src); int i0 = (int)f0; float fr = src - f0;
    int ia = min(max(i0, 0), WFn-1), ib = min(max(i0+1, 0), WFn-1);
    const float* fp = g_fem + (size_t)(b*Hn + h)*WFn;
    g_aux[base + (size_t)100*HWn] = fp[ia]*(1.f - fr) + fp[ib]*fr;
}

// ------------------------- tiled 3x3 conv (implicit GEMM) -------------------
template<int CIN, int CSTRIDE, int COUT, bool RELU>
__global__ __launch_bounds__(128)
void conv3x3_k(const float* __restrict__ in, const float* __restrict__ wgt,
               const float* __restrict__ bias, float* __restrict__ out) {
    constexpr int NO = (COUT + 31) / 32;
    constexpr int CB = 8;
    __shared__ float tile[CB][3][36];
    __shared__ float wsh[CB][COUT*9];
    int bx = blockIdx.x;
    int seg = bx & 7; int h = (bx >> 3) & (Hn - 1); int b = bx >> 10;
    int w0 = seg * 32;
    int tid = threadIdx.x;
    int pg = tid & 3, og = tid >> 2;
    float acc[NO][8];
    #pragma unroll
    for (int k = 0; k < NO; k++)
        #pragma unroll
        for (int p = 0; p < 8; p++) acc[k][p] = 0.f;
    const float* inb = in + (size_t)b*CSTRIDE*HWn;
    for (int c0 = 0; c0 < CIN; c0 += CB) {
        for (int m = tid; m < CB*3*34; m += 128) {
            int ci = m / 102; int rem = m - ci*102; int r = rem / 34; int cc = rem - r*34;
            int hh = h + r - 1, ww = w0 + cc - 1;
            float v = 0.f;
            if (c0 + ci < CIN && hh >= 0 && hh < Hn && ww >= 0 && ww < Wn)
                v = inb[(size_t)(c0 + ci)*HWn + hh*Wn + ww];
            tile[ci][r][cc] = v;
        }
        for (int m = tid; m < CB*COUT*9; m += 128) {
            int ci = m / (COUT*9); int rem = m - ci*(COUT*9);
            float v = 0.f;
            if (c0 + ci < CIN) {
                int o = rem / 9, j = rem - o*9;
                v = wgt[((size_t)o*CIN + c0 + ci)*9 + j];
            }
            wsh[ci][rem] = v;
        }
        __syncthreads();
        #pragma unroll 2
        for (int ci = 0; ci < CB; ci++) {
            float tv[3][10];
            #pragma unroll
            for (int r = 0; r < 3; r++) {
                const float* trow = &tile[ci][r][pg*8];
                float4 v0 = *(const float4*)(trow);
                float4 v1 = *(const float4*)(trow + 4);
                tv[r][0]=v0.x; tv[r][1]=v0.y; tv[r][2]=v0.z; tv[r][3]=v0.w;
                tv[r][4]=v1.x; tv[r][5]=v1.y; tv[r][6]=v1.z; tv[r][7]=v1.w;
                tv[r][8]=trow[8]; tv[r][9]=trow[9];
            }
            #pragma unroll
            for (int k = 0; k < NO; k++) {
                int o = og + 32*k;
                if ((COUT & 31) && o >= COUT) break;
                const float* wp = &wsh[ci][o*9];
                float w00=wp[0],w01=wp[1],w02=wp[2],
                      w10=wp[3],w11=wp[4],w12=wp[5],
                      w20=wp[6],w21=wp[7],w22=wp[8];
                #pragma unroll
                for (int p = 0; p < 8; p++) {
                    float a = acc[k][p];
                    a += w00*tv[0][p]; a += w01*tv[0][p+1]; a += w02*tv[0][p+2];
                    a += w10*tv[1][p]; a += w11*tv[1][p+1]; a += w12*tv[1][p+2];
                    a += w20*tv[2][p]; a += w21*tv[2][p+1]; a += w22*tv[2][p+2];
                    acc[k][p] = a;
                }
            }
        }
        __syncthreads();
    }
    #pragma unroll
    for (int k = 0; k < NO; k++) {
        int o = og + 32*k;
        if ((COUT & 31) && o >= COUT) break;
        float bb = bias[o];
        float* op = out + ((size_t)(b*COUT + o))*HWn + h*Wn + w0 + pg*8;
        #pragma unroll
        for (int p = 0; p < 8; p++) {
            float v = acc[k][p] + bb;
            if (RELU) v = fmaxf(v, 0.f);
            op[p] = v;
        }
    }
}

// ------------- merged offset(18) + dg1(50) conv with fused gate head --------
__global__ __launch_bounds__(128)
void convoffdg_k(const float* __restrict__ offw, const float* __restrict__ offbias,
                 const float* __restrict__ dg1w, const float* __restrict__ dg1b,
                 const float* __restrict__ dg2w, const float* __restrict__ dg2b) {
    constexpr int COUT = 68;
    constexpr int NO = 3;
    constexpr int CB = 8;
    __shared__ float tile[CB][3][36];
    __shared__ float wsh[CB][COUT*9];
    __shared__ float sgate[32][32];
    int bx = blockIdx.x;
    int seg = bx & 7; int h = (bx >> 3) & (Hn - 1); int b = bx >> 10;
    int w0 = seg * 32;
    int tid = threadIdx.x;
    int pg = tid & 3, og = tid >> 2;
    float acc[NO][8];
    #pragma unroll
    for (int k = 0; k < NO; k++)
        #pragma unroll
        for (int p = 0; p < 8; p++) acc[k][p] = 0.f;
    const float* inb = g_aux + (size_t)b*AUXn*HWn;
    for (int c0 = 0; c0 < AUXn; c0 += CB) {
        for (int m = tid; m < CB*3*34; m += 128) {
            int ci = m / 102; int rem = m - ci*102; int r = rem / 34; int cc = rem - r*34;
            int hh = h + r - 1, ww = w0 + cc - 1;
            float v = 0.f;
            if (c0 + ci < AUXn && hh >= 0 && hh < Hn && ww >= 0 && ww < Wn)
                v = inb[(size_t)(c0 + ci)*HWn + hh*Wn + ww];
            tile[ci][r][cc] = v;
        }
        for (int m = tid; m < CB*COUT*9; m += 128) {
            int ci = m / (COUT*9); int rem = m - ci*(COUT*9);
            float v = 0.f;
            if (c0 + ci < AUXn) {
                int o = rem / 9, j = rem - o*9;
                if (o < 18) v = offw[((size_t)o*AUXn + c0 + ci)*9 + j];
                else        v = dg1w[((size_t)(o-18)*AUXn + c0 + ci)*9 + j];
            }
            wsh[ci][rem] = v;
        }
        __syncthreads();
        #pragma unroll 2
        for (int ci = 0; ci < CB; ci++) {
            float tv[3][10];
            #pragma unroll
            for (int r = 0; r < 3; r++) {
                const float* trow = &tile[ci][r][pg*8];
                float4 v0 = *(const float4*)(trow);
                float4 v1 = *(const float4*)(trow + 4);
                tv[r][0]=v0.x; tv[r][1]=v0.y; tv[r][2]=v0.z; tv[r][3]=v0.w;
                tv[r][4]=v1.x; tv[r][5]=v1.y; tv[r][6]=v1.z; tv[r][7]=v1.w;
                tv[r][8]=trow[8]; tv[r][9]=trow[9];
            }
            #pragma unroll
            for (int k = 0; k < NO; k++) {
                int o = og + 32*k;
                if (o >= COUT) break;
                const float* wp = &wsh[ci][o*9];
                float w00=wp[0],w01=wp[1],w02=wp[2],
                      w10=wp[3],w11=wp[4],w12=wp[5],
                      w20=wp[6],w21=wp[7],w22=wp[8];
                #pragma unroll
                for (int p = 0; p < 8; p++) {
                    float a = acc[k][p];
                    a += w00*tv[0][p]; a += w01*tv[0][p+1]; a += w02*tv[0][p+2];
                    a += w10*tv[1][p]; a += w11*tv[1][p+1]; a += w12*tv[1][p+2];
                    a += w20*tv[2][p]; a += w21*tv[2][p+1]; a += w22*tv[2][p+2];
                    acc[k][p] = a;
                }
            }
        }
        __syncthreads();
    }
    float part[8];
    #pragma unroll
    for (int p = 0; p < 8; p++) part[p] = 0.f;
    #pragma unroll
    for (int k = 0; k < NO; k++) {
        int o = og + 32*k;
        if (o >= COUT) break;
        if (o < 18) {
            float bb = offbias[o];
            float* op = g_offb + ((size_t)(b*18 + o))*HWn + h*Wn + w0 + pg*8;
            #pragma unroll
            for (int p = 0; p < 8; p++) op[p] = acc[k][p] + bb;
        } else {
            float bb = dg1b[o-18];
            float wv = dg2w[o-18];
            #pragma unroll
            for (int p = 0; p < 8; p++) part[p] += wv * fmaxf(acc[k][p] + bb, 0.f);
        }
    }
    #pragma unroll
    for (int p = 0; p < 8; p++) sgate[og][pg*8 + p] = part[p];
    __syncthreads();
    if (tid < 32) {
        float s = dg2b[0];
        #pragma unroll 8
        for (int o2 = 0; o2 < 32; o2++) s += sgate[o2][tid];
        g_gate[(size_t)b*HWn + h*Wn + w0 + tid] = 1.f/(1.f + expf(-s));
    }
}

// ------------------------- def_w transpose ----------------------------------
__global__ void transpose_defw_k(const float* __restrict__ w) {
    int i = blockIdx.x*blockDim.x + threadIdx.x;
    if (i >= 9*96*96) return;
    int o = i % 96; int c = (i / 96) % 96; int t = i / (96*96);
    g_defwt[i] = w[((size_t)o*96 + c)*9 + t];
}

// ------------------------- deformable sampling + GEMM + combine -------------
__global__ __launch_bounds__(128)
void deform_combine_k(const float* __restrict__ defb) {
    __shared__ int   s_idx[9][32][4];
    __shared__ float s_w[9][32][4];
    __shared__ float samp[8][32];
    __shared__ float wsh2[8][96];
    int bx = blockIdx.x;
    int seg = bx & 7; int h = (bx >> 3) & (Hn - 1); int b = bx >> 10;
    int w0 = seg * 32;
    int tid = threadIdx.x;
    int pg = tid & 3, og = tid >> 2;

    for (int e = tid; e < 288; e += 128) {
        int t9 = e >> 5, p = e & 31;
        int wpx = w0 + p;
        size_t obase = ((size_t)b*18)*HWn + (size_t)h*Wn + wpx;
        float ox = g_offb[obase + (size_t)(2*t9)*HWn];
        float oy = g_offb[obase + (size_t)(2*t9+1)*HWn];
        float px = (float)wpx + ox;
        float py = (float)h + oy;
        float x0 = floorf(px), y0 = floorf(py);
        float fx = px - x0, fy = py - y0;
        #pragma unroll
        for (int j = 0; j < 4; j++) {
            float xj = x0 + (float)(j & 1);
            float yj = y0 + (float)(j >> 1);
            float valid = (xj >= 0.f && xj <= 255.f && yj >= 0.f && yj <= 127.f) ? 1.f : 0.f;
            float xc = fminf(fmaxf(xj, 0.f), 255.f);
            float yc = fminf(fmaxf(yj, 0.f), 127.f);
            s_idx[t9][p][j] = (int)yc * Wn + (int)xc;
            float wx = (j & 1) ? fx : (1.f - fx);
            float wy = (j >> 1) ? fy : (1.f - fy);
            s_w[t9][p][j] = wx * wy * valid;
        }
    }

    float acc[3][8];
    #pragma unroll
    for (int k = 0; k < 3; k++)
        #pragma unroll
        for (int p = 0; p < 8; p++) acc[k][p] = 0.f;

    for (int t9 = 0; t9 < 9; t9++) {
        for (int c0 = 0; c0 < 96; c0 += 8) {
            __syncthreads();
            for (int e = tid; e < 768; e += 128) {
                int c = e / 96; int o = e - c*96;
                wsh2[c][o] = g_defwt[((size_t)(t9*96) + c0 + c)*96 + o];
            }
            for (int e = tid; e < 256; e += 128) {
                int c = e >> 5, p = e & 31;
                const float* yp = g_aux + ((size_t)(b*AUXn + c0 + c))*HWn;
                const int* ip = s_idx[t9][p];
                const float* wp = s_w[t9][p];
                samp[c][p] = wp[0]*yp[ip[0]] + wp[1]*yp[ip[1]]
                           + wp[2]*yp[ip[2]] + wp[3]*yp[ip[3]];
            }
            __syncthreads();
            #pragma unroll
            for (int c = 0; c < 8; c++) {
                const float4* sp = (const float4*)&samp[c][pg*8];
                float4 a0 = sp[0], a1 = sp[1];
                float sv[8] = {a0.x,a0.y,a0.z,a0.w,a1.x,a1.y,a1.z,a1.w};
                #pragma unroll
                for (int k = 0; k < 3; k++) {
                    float wv = wsh2[c][og + 32*k];
                    #pragma unroll
                    for (int p = 0; p < 8; p++) acc[k][p] += wv * sv[p];
                }
            }
        }
    }
    #pragma unroll
    for (int k = 0; k < 3; k++) {
        int o = og + 32*k;
        float bb = defb[o];
        #pragma unroll
        for (int p = 0; p < 8; p++) {
            int col = w0 + pg*8 + p;
            size_t oidx = ((size_t)(b*Cn + o))*HWn + (size_t)h*Wn + col;
            float gt = g_gate[(size_t)b*HWn + h*Wn + col];
            float ydef = acc[k][p] + bb;
            g_z[oidx] = (1.f - gt)*g_ybase[oidx] + gt*ydef;
        }
    }
}

// ------------------------- batchnorm ----------------------------------------
__global__ void bn_stats_k() {
    __shared__ float ss[256], ss2[256];
    int c = blockIdx.x, tid = threadIdx.x;
    float s = 0.f, s2 = 0.f;
    for (int i = tid; i < Bn*HWn; i += 256) {
        int b = i >> 15, hw = i & (HWn-1);
        float v = g_z[((size_t)(b*Cn + c))*HWn + hw];
        s += v; s2 += v*v;
    }
    ss[tid] = s; ss2[tid] = s2;
    __syncthreads();
    for (int st = 128; st > 0; st >>= 1) {
        if (tid < st) { ss[tid] += ss[tid+st]; ss2[tid] += ss2[tid+st]; }
        __syncthreads();
    }
    if (tid == 0) {
        float inv = 1.f/(float)(Bn*HWn);
        float mu = ss[0]*inv;
        float var = ss2[0]*inv - mu*mu;
        g_mu[c] = mu;
        g_istd[c] = rsqrtf(var + 1e-5f);
    }
}

__global__ void bn_apply_k(const float* __restrict__ x,
                           const float* __restrict__ gam, const float* __restrict__ bet,
                           float* __restrict__ out) {
    int hw = blockIdx.x*256 + threadIdx.x;
    int c = blockIdx.y, b = blockIdx.z;
    size_t i = ((size_t)(b*Cn + c))*HWn + hw;
    float zn = (g_z[i] - g_mu[c]) * g_istd[c] * gam[c] + bet[c];
    out[i] = fmaxf(zn + x[i], 0.f);
}

// ------------------------- launch -------------------------------------------
extern "C" void kernel_launch(void* const* d_in, const int* in_sizes, int n_in,
                              void* d_out, int out_size) {
    const float* x     = (const float*)d_in[0];
    const float* fdh_w = (const float*)d_in[1];
    const float* fdh_b = (const float*)d_in[2];
    const float* fdw_w = (const float*)d_in[3];
    const float* fdw_b = (const float*)d_in[4];
    const float* cp1_w = (const float*)d_in[5];
    const float* cp1_b = (const float*)d_in[6];
    const float* cp2_w = (const float*)d_in[7];
    const float* cp2_b = (const float*)d_in[8];
    const float* sdh_w = (const float*)d_in[9];
    const float* sdh_b = (const float*)d_in[10];
    const float* sdw_w = (const float*)d_in[11];
    const float* sdw_b = (const float*)d_in[12];
    const float* sr1_w = (const float*)d_in[13];
    const float* sr1_b = (const float*)d_in[14];
    const float* sr2_w = (const float*)d_in[15];
    const float* sr2_b = (const float*)d_in[16];
    const float* off_w = (const float*)d_in[17];
    const float* off_b = (const float*)d_in[18];
    const float* dg1_w = (const float*)d_in[19];
    const float* dg1_b = (const float*)d_in[20];
    const float* dg2_w = (const float*)d_in[21];
    const float* dg2_b = (const float*)d_in[22];
    const float* base_w = (const float*)d_in[23];
    const float* base_b = (const float*)d_in[24];
    const float* def_w = (const float*)d_in[25];
    const float* def_b = (const float*)d_in[26];
    const float* bn_g  = (const float*)d_in[27];
    const float* bn_b  = (const float*)d_in[28];
    float* out = (float*)d_out;

    float *p_fe, *p_fem, *p_aux, *p_ybase;
    cudaGetSymbolAddress((void**)&p_fe, g_fe);
    cudaGetSymbolAddress((void**)&p_fem, g_fem);
    cudaGetSymbolAddress((void**)&p_aux, g_aux);
    cudaGetSymbolAddress((void**)&p_ybase, g_ybase);

    tw_init_k<<<1, 128>>>();
    transpose_defw_k<<<CDIV(9*96*96,256), 256>>>(def_w);

    // ---- FFT(x) -> mag, fe ----
    fft_rows_k<<<dim3(Hn/2, Cn, Bn), 128>>>(x, Cn);
    fft_cols_k<<<dim3(9, Cn, Bn), 128>>>();
    chan_mean_k<<<dim3(Hn, Bn), 160>>>(p_fe);
    // ---- freq depthwise + pooled stats + channel MLP ----
    dwfreq_h_k<<<dim3(Hn, Cn, Bn), 160>>>(fdh_w, fdh_b);
    dwfreq_w_k<<<dim3(Hn, Cn, Bn), 160>>>(fdw_w, fdw_b);
    gpool_k<<<Bn*Cn, 160>>>();
    ca_mlp_k<<<Bn, 96>>>(cp1_w, cp1_b, cp2_w, cp2_b);
    // ---- spatial branch ----
    spatial_in_k<<<dim3(Hn, Bn), 256>>>(x);
    dwsp_h_k<<<CDIV(Bn*3*HWn,256), 256>>>(sdh_w, sdh_b);
    dwsp_w_k<<<CDIV(Bn*3*HWn,256), 256>>>(sdw_w, sdw_b);
    sr_k<<<CDIV(Bn*HWn,256), 256>>>(sr1_w, sr1_b, sr2_w, sr2_b);
    ymul_k<<<dim3(HWn/256, Cn, Bn), 256>>>(x);
    // ---- FFT(y) -> mag, fem ----
    fft_rows_k<<<dim3(Hn/2, Cn, Bn), 128>>>(p_aux, AUXn);
    fft_cols_k<<<dim3(9, Cn, Bn), 128>>>();
    chan_mean_k<<<dim3(Hn, Bn), 160>>>(p_fem);
    // ---- aux misc channels ----
    auxmisc_k<<<dim3(Hn, Bn), 256>>>();
    // ---- convs (merged offset+dg1+gate; base) ----
    convoffdg_k<<<2048, 128>>>(off_w, off_b, dg1_w, dg1_b, dg2_w, dg2_b);
    conv3x3_k<Cn,AUXn,96,false><<<2048, 128>>>(p_aux, base_w, base_b, p_ybase);
    // ---- deformable ----
    deform_combine_k<<<2048, 128>>>(def_b);
    // ---- BN + residual relu ----
    bn_stats_k<<<Cn, 256>>>();
    bn_apply_k<<<dim3(HWn/256, Cn, Bn), 256>>>(x, bn_g, bn_b, out);
}

// round 4
// speedup vs baseline: 1.1986x; 1.1876x over previous
#include <cuda_runtime.h>
#include <math.h>

#define Bn 2
#define Cn 96
#define Hn 128
#define Wn 256
#define WFn 129
#define HWn (Hn*Wn)
#define AUXn 101
#define MIDn 24
#define DMIDn 50
#define NTOT (Bn*Cn*HWn)
#define NF (Bn*Cn*Hn*WFn)
#define CDIV(a,b) (((a)+(b)-1)/(b))

typedef unsigned long long u64;

__device__ __forceinline__ u64 ffma2(u64 a, u64 b, u64 c) {
    u64 d;
    asm("fma.rn.f32x2 %0, %1, %2, %3;" : "=l"(d) : "l"(a), "l"(b), "l"(c));
    return d;
}
__device__ __forceinline__ u64 pack2(float x, float y) {
    u64 d; asm("mov.b64 %0, {%1, %2};" : "=l"(d) : "f"(x), "f"(y)); return d;
}
__device__ __forceinline__ float2 unpack2(u64 v) {
    float2 d; asm("mov.b64 {%0, %1}, %2;" : "=f"(d.x), "=f"(d.y) : "l"(v)); return d;
}

// ------------------------- scratch (static device memory) -------------------
static __device__ float2 g_tw[128];
static __device__ float g_mag[NF];
static __device__ float g_fe[Bn*Hn*WFn];
static __device__ float g_fem[Bn*Hn*WFn];
static __device__ float g_gvec[Bn*3*Cn];
static __device__ float g_ca[Bn*Cn];
static __device__ float g_s0[Bn*3*HWn];
static __device__ float g_s1[Bn*3*HWn];
static __device__ float g_sa[Bn*HWn];
static __device__ float g_aux[(size_t)Bn*AUXn*HWn];
static __device__ float g_offb[Bn*18*HWn];
static __device__ float g_gate[Bn*HWn];
static __device__ float g_ybase[NTOT];
static __device__ float g_z[NTOT];
static __device__ float g_defwt[9*96*96];
static __device__ float g_mu[Cn];
static __device__ float g_istd[Cn];

// ------------------------- prep: twiddles + def_w transpose -----------------
__global__ void prep_k(const float* __restrict__ defw) {
    int i = blockIdx.x*256 + threadIdx.x;
    if (i < 128) {
        float ang = -6.2831853071795864f * (float)i / 256.f;
        float s, c; sincosf(ang, &s, &c);
        g_tw[i] = make_float2(c, s);
    }
    if (i < 9*96*96) {
        int o = i % 96; int c = (i / 96) % 96; int t = i / (96*96);
        g_defwt[i] = defw[((size_t)o*96 + c)*9 + t];
    }
}

// ------------------------- fused 2D FFT -> |.| ------------------------------
// One block per (b,c). Full plane in smem. 512 threads.
// smem: sre[129][132] + sim[129][132] + row workspace 4 pairs x 256 re/im
__global__ __launch_bounds__(512)
void fft2d_k(const float* __restrict__ in, int cstride) {
    extern __shared__ float fs[];
    float* sre = fs;                       // 129*132
    float* sim = fs + 17028;               // 129*132
    float* rwre_base = fs + 34056;         // 4*256
    float* rwim_base = fs + 35080;         // 4*256
    int c = blockIdx.x, b = blockIdx.y;
    const float* plane = in + ((size_t)(b*cstride + c))*HWn;
    int tid = threadIdx.x;
    int pr = tid >> 7;                    // 0..3
    int l  = tid & 127;
    float* rwre = rwre_base + pr*256;
    float* rwim = rwim_base + pr*256;

    // ---- row FFTs: 64 packed pairs, 4 at a time ----
    for (int ob = 0; ob < 16; ob++) {
        int h0 = (ob*4 + pr)*2;
        const float* r0 = plane + (size_t)h0*Wn;
        const float* r1 = r0 + Wn;
        __syncthreads();
        for (int i = l; i < 256; i += 128) {
            int j = __brev((unsigned)i) >> 24;
            rwre[j] = r0[i]; rwim[j] = r1[i];
        }
        __syncthreads();
        #pragma unroll
        for (int s = 1; s <= 8; s++) {
            int half = 1 << (s-1);
            int off = l & (half-1);
            int a = ((l >> (s-1)) << s) + off;
            int bb = a + half;
            float2 tw = g_tw[off << (8-s)];
            float br = rwre[bb], bi = rwim[bb], ar = rwre[a], ai = rwim[a];
            float xr = br*tw.x - bi*tw.y, xi = br*tw.y + bi*tw.x;
            rwre[a] = ar+xr; rwim[a] = ai+xi;
            rwre[bb] = ar-xr; rwim[bb] = ai-xi;
            __syncthreads();
        }
        // unpack two real spectra into columns h0, h0+1
        {
            int k = l;
            float zr = rwre[k], zi = rwim[k];
            int km = (256-k)&255;
            float wr = rwre[km], wi = rwim[km];
            sre[k*132 + h0]   = 0.5f*(zr+wr);
            sim[k*132 + h0]   = 0.5f*(zi-wi);
            sre[k*132 + h0+1] = 0.5f*(zi+wi);
            sim[k*132 + h0+1] = -0.5f*(zr-wr);
            if (l == 0) {
                sre[128*132 + h0] = rwre[128];   sim[128*132 + h0] = 0.f;
                sre[128*132 + h0+1] = rwim[128]; sim[128*132 + h0+1] = 0.f;
            }
        }
    }
    __syncthreads();
    // ---- column FFTs (128-pt) on all 129 columns ----
    // bit-reversal permutation
    for (int e = tid; e < 129*128; e += 512) {
        int col = e >> 7, hh = e & 127;
        int j = __brev((unsigned)hh) >> 25;
        if (hh < j) {
            float t = sre[col*132+hh]; sre[col*132+hh] = sre[col*132+j]; sre[col*132+j] = t;
            t = sim[col*132+hh]; sim[col*132+hh] = sim[col*132+j]; sim[col*132+j] = t;
        }
    }
    __syncthreads();
    #pragma unroll
    for (int s = 1; s <= 7; s++) {
        int half = 1 << (s-1);
        for (int e = tid; e < 129*64; e += 512) {
            int i = e & 63, col = e >> 6;
            int off = i & (half-1);
            int a = ((i >> (s-1)) << s) + off;
            int bb = a + half;
            float2 tw = g_tw[off << (8-s)];
            float* cr = sre + col*132; float* ci2 = sim + col*132;
            float br = cr[bb], bi = ci2[bb], ar = cr[a], ai = ci2[a];
            float xr = br*tw.x - bi*tw.y, xi = br*tw.y + bi*tw.x;
            cr[a]=ar+xr; ci2[a]=ai+xi; cr[bb]=ar-xr; ci2[bb]=ai-xi;
        }
        __syncthreads();
    }
    const float sc = 0.0055242717280199026f;  // 1/sqrt(128*256)
    float* mout = g_mag + (size_t)(b*Cn + c)*Hn*WFn;
    for (int e = tid; e < 128*129; e += 512) {
        int hh = e / 129, col = e - hh*129;
        float r = sre[col*132+hh], m = sim[col*132+hh];
        mout[e] = sqrtf(r*r + m*m)*sc;
    }
}

// mean over channels of g_mag -> out[b][h][k]
__global__ void chan_mean_k(float* __restrict__ out) {
    int h = blockIdx.x, b = blockIdx.y;
    for (int k = threadIdx.x; k < WFn; k += 160) {
        float s = 0.f;
        const float* p = g_mag + ((size_t)(b*Cn)*Hn + h)*WFn + k;
        #pragma unroll 4
        for (int c = 0; c < Cn; c++) s += p[(size_t)c*Hn*WFn];
        out[(size_t)(b*Hn + h)*WFn + k] = s * (1.f/Cn);
    }
}

// --------- fused freq branch: dwfreq_h + dwfreq_w + adaptive pools ----------
__global__ __launch_bounds__(160)
void freq_fused_k(const float* __restrict__ w7h, const float* __restrict__ b7h,
                  const float* __restrict__ w7w, const float* __restrict__ b7w) {
    extern __shared__ float A[];          // [128][132]
    __shared__ float rowbuf[136];
    __shared__ float S[4][132];
    __shared__ float bins[21];
    int c = blockIdx.x, b = blockIdx.y;
    int bc = b*Cn + c;
    int tid = threadIdx.x;
    const float* mp = g_mag + (size_t)bc*Hn*WFn;
    for (int h = 0; h < 128; h++)
        if (tid < 129) A[h*132+tid] = mp[h*129+tid];
    if (tid < 4) { rowbuf[tid] = 0.f; rowbuf[131+tid] = 0.f; }
    float wh[7], ww[7];
    #pragma unroll
    for (int d = 0; d < 7; d++) { wh[d] = w7h[c*7+d]; ww[d] = w7w[c*7+d]; }
    float bh = b7h[c], bw = b7w[c];
    __syncthreads();
    for (int band = 0; band < 4; band++) {
        float acc = 0.f;
        for (int hh = 0; hh < 32; hh++) {
            int h = band*32 + hh;
            float t1 = bh;
            if (tid < 129) {
                #pragma unroll
                for (int d = 0; d < 7; d++) {
                    int h2 = h + d - 3;
                    if (h2 >= 0 && h2 < 128) t1 += wh[d]*A[h2*132 + tid];
                }
            }
            __syncthreads();
            if (tid < 129) rowbuf[3 + tid] = t1;
            __syncthreads();
            if (tid < 129) {
                float t2 = bw;
                #pragma unroll
                for (int d = 0; d < 7; d++) t2 += ww[d]*rowbuf[tid + d];
                acc += t2;
            }
        }
        if (tid < 129) S[band][tid] = acc;
        __syncthreads();
    }
    if (tid < 16) {
        int i = tid >> 2, j = tid & 3;
        int ws = (j*WFn)/4, we = ((j+1)*WFn + 3)/4;
        float s = 0;
        for (int k = ws; k < we; k++) s += S[i][k];
        bins[tid] = s / (32.f * (float)(we - ws));
    } else if (tid < 20) {
        int t2 = tid - 16; int i = t2 >> 1, j = t2 & 1;
        int ws = (j*WFn)/2, we = ((j+1)*WFn + 1)/2;
        float s = 0;
        for (int k = ws; k < we; k++) s += S[2*i][k] + S[2*i+1][k];
        bins[tid] = s / (64.f * (float)(we - ws));
    } else if (tid == 20) {
        float s = 0;
        for (int k = 0; k < WFn; k++) s += S[0][k]+S[1][k]+S[2][k]+S[3][k];
        bins[20] = s / (128.f*129.f);
    }
    __syncthreads();
    if (tid == 0) {
        float g2 = bins[16]+bins[17]+bins[18]+bins[19];
        float g3 = 0;
        for (int m = 0; m < 16; m++) g3 += bins[m];
        g_gvec[b*288 + c]        = bins[20];
        g_gvec[b*288 + Cn + c]   = g2 * 0.25f;
        g_gvec[b*288 + 2*Cn + c] = g3 * 0.0625f;
    }
}

// ------------------------- channel-attention MLP ----------------------------
__global__ void ca_mlp_k(const float* __restrict__ w1, const float* __restrict__ b1,
                         const float* __restrict__ w2, const float* __restrict__ b2) {
    __shared__ float gs[288], hs[MIDn];
    int b = blockIdx.x, tid = threadIdx.x;   // 96 threads
    for (int i = tid; i < 288; i += 96) gs[i] = g_gvec[b*288 + i];
    __syncthreads();
    if (tid < MIDn) {
        float a = b1[tid];
        for (int k = 0; k < 288; k++) a += w1[tid*288 + k]*gs[k];
        hs[tid] = fmaxf(a, 0.f);
    }
    __syncthreads();
    float a = b2[tid];
    #pragma unroll
    for (int m = 0; m < MIDn; m++) a += w2[tid*MIDn + m]*hs[m];
    g_ca[b*Cn + tid] = 1.f/(1.f + expf(-a));
}

// ------------------------- spatial branch -----------------------------------
__global__ void spatial_in_k(const float* __restrict__ x) {
    int h = blockIdx.x, b = blockIdx.y;
    int w = threadIdx.x;                  // 256
    int hw = h*Wn + w;
    const float* xp = x + (size_t)b*Cn*HWn + hw;
    float s = 0.f, s2 = 0.f;
    #pragma unroll 4
    for (int c = 0; c < Cn; c++) { float v = xp[(size_t)c*HWn]; s += v; s2 += v*v; }
    float mean = s * (1.f/Cn);
    float l2 = sqrtf(s2 * (1.f/Cn) + 1e-6f);
    float src = ((float)w + 0.5f)*(129.f/256.f) - 0.5f;
    float f0 = floorf(src); int i0 = (int)f0; float fr = src - f0;
    int ia = min(max(i0, 0), WFn-1), ib = min(max(i0+1, 0), WFn-1);
    const float* fp = g_fe + (size_t)(b*Hn + h)*WFn;
    float fv = fp[ia]*(1.f - fr) + fp[ib]*fr;
    g_s0[((size_t)(b*3+0))*HWn + hw] = mean;
    g_s0[((size_t)(b*3+1))*HWn + hw] = l2;
    g_s0[((size_t)(b*3+2))*HWn + hw] = fv;
}

__global__ void dwsp_h_k(const float* __restrict__ w15, const float* __restrict__ b15) {
    int i = blockIdx.x*blockDim.x + threadIdx.x;
    if (i >= Bn*3*HWn) return;
    int w = i & (Wn-1); int t = i >> 8; int h = t & (Hn-1); int bc = t >> 7; int ch = bc % 3;
    float a = b15[ch];
    #pragma unroll
    for (int d = 0; d < 15; d++) {
        int hh = h + d - 7;
        if (hh >= 0 && hh < Hn) a += w15[ch*15+d]*g_s0[((size_t)bc*Hn + hh)*Wn + w];
    }
    g_s1[i] = a;
}

__global__ void dwsp_w_k(const float* __restrict__ w15, const float* __restrict__ b15) {
    int i = blockIdx.x*blockDim.x + threadIdx.x;
    if (i >= Bn*3*HWn) return;
    int w = i & (Wn-1); int t = i >> 8; int bc = t >> 7; int ch = bc % 3;
    float a = b15[ch];
    #pragma unroll
    for (int d = 0; d < 15; d++) {
        int ww = w + d - 7;
        if (ww >= 0 && ww < Wn) a += w15[ch*15+d]*g_s1[(size_t)t*Wn + ww];
    }
    g_s0[i] = a;
}

__global__ void sr_k(const float* __restrict__ sr1w, const float* __restrict__ sr1b,
                     const float* __restrict__ sr2w, const float* __restrict__ sr2b) {
    int i = blockIdx.x*blockDim.x + threadIdx.x;
    if (i >= Bn*HWn) return;
    int b = i >> 15; int hw = i & (HWn-1); int h = hw >> 8; int w = hw & (Wn-1);
    float acc = sr2b[0];
    #pragma unroll
    for (int g3 = 0; g3 < 3; g3++) {
        float v = sr1b[g3];
        #pragma unroll
        for (int ky = 0; ky < 3; ky++) {
            int hh = h + ky - 1; if (hh < 0 || hh >= Hn) continue;
            #pragma unroll
            for (int kx = 0; kx < 3; kx++) {
                int ww = w + kx - 1; if (ww < 0 || ww >= Wn) continue;
                v += sr1w[g3*9 + ky*3 + kx]*g_s0[((size_t)(b*3+g3)*Hn + hh)*Wn + ww];
            }
        }
        acc += sr2w[g3]*fmaxf(v, 0.f);
    }
    g_sa[i] = 1.f/(1.f + expf(-acc));
}

// y = x*ca*sa written directly into aux channels [0..95]
__global__ void ymul_k(const float* __restrict__ x) {
    int hw = blockIdx.x*256 + threadIdx.x;
    int c = blockIdx.y, b = blockIdx.z;
    float v = x[((size_t)(b*Cn + c))*HWn + hw] * g_ca[b*Cn + c] * g_sa[(size_t)b*HWn + hw];
    g_aux[((size_t)(b*AUXn + c))*HWn + hw] = v;
}

__global__ void auxmisc_k() {
    int h = blockIdx.x, b = blockIdx.y;
    int w = threadIdx.x;                 // 256
    int hw = h*Wn + w;
    float theta = -3.14159265358979324f + (float)w * (6.2831853071795864f/255.f);
    float phi   = -1.57079632679489662f + (float)h * (3.14159265358979324f/127.f);
    size_t base = (size_t)b*AUXn*HWn + hw;
    g_aux[base + (size_t)96*HWn] = sinf(theta);
    g_aux[base + (size_t)97*HWn] = cosf(theta);
    g_aux[base + (size_t)98*HWn] = sinf(phi);
    g_aux[base + (size_t)99*HWn] = cosf(phi);
    float src = ((float)w + 0.5f)*(129.f/256.f) - 0.5f;
    float f0 = floorf(src); int i0 = (int)f0; float fr = src - f0;
    int ia = min(max(i0, 0), WFn-1), ib = min(max(i0+1, 0), WFn-1);
    const float* fp = g_fem + (size_t)(b*Hn + h)*WFn;
    g_aux[base + (size_t)100*HWn] = fp[ia]*(1.f - fr) + fp[ib]*fr;
}

// ------------------- tiled 3x3 conv, 64px, f32x2 packed ---------------------
template<int CIN, int CSTRIDE, int COUT, bool RELU>
__global__ __launch_bounds__(256)
void conv3x3_k(const float* __restrict__ in, const float* __restrict__ wgt,
               const float* __restrict__ bias, float* __restrict__ out) {
    constexpr int NO = (COUT + 31) / 32;
    constexpr int CB = 8;
    __shared__ float tile[CB][3][72];
    __shared__ float wsh[CB][COUT*9];
    int bx = blockIdx.x;
    int seg = bx & 3; int h = (bx >> 2) & (Hn - 1); int b = bx >> 9;
    int w0 = seg * 64;
    int tid = threadIdx.x;
    int pg = tid & 7, og = tid >> 3;
    u64 pacc[NO][4];
    #pragma unroll
    for (int k = 0; k < NO; k++)
        #pragma unroll
        for (int q = 0; q < 4; q++) pacc[k][q] = 0ull;
    const float* inb = in + (size_t)b*CSTRIDE*HWn;
    for (int c0 = 0; c0 < CIN; c0 += CB) {
        for (int m = tid; m < CB*3*66; m += 256) {
            int ci = m / 198; int rem = m - ci*198; int r = rem / 66; int cc = rem - r*66;
            int hh = h + r - 1, ww = w0 + cc - 1;
            float v = 0.f;
            if (c0 + ci < CIN && hh >= 0 && hh < Hn && ww >= 0 && ww < Wn)
                v = inb[(size_t)(c0 + ci)*HWn + hh*Wn + ww];
            tile[ci][r][cc] = v;
        }
        for (int m = tid; m < CB*COUT*9; m += 256) {
            int ci = m / (COUT*9); int rem = m - ci*(COUT*9);
            float v = 0.f;
            if (c0 + ci < CIN) {
                int o = rem / 9, j = rem - o*9;
                v = wgt[((size_t)o*CIN + c0 + ci)*9 + j];
            }
            wsh[ci][rem] = v;
        }
        __syncthreads();
        #pragma unroll 2
        for (int ci = 0; ci < CB; ci++) {
            #pragma unroll
            for (int r = 0; r < 3; r++) {
                const float* trow = &tile[ci][r][pg*8];
                float t0=trow[0],t1=trow[1],t2=trow[2],t3=trow[3],t4=trow[4];
                float t5=trow[5],t6=trow[6],t7=trow[7],t8=trow[8],t9=trow[9];
                u64 pv[9];
                pv[0]=pack2(t0,t1); pv[1]=pack2(t1,t2); pv[2]=pack2(t2,t3);
                pv[3]=pack2(t3,t4); pv[4]=pack2(t4,t5); pv[5]=pack2(t5,t6);
                pv[6]=pack2(t6,t7); pv[7]=pack2(t7,t8); pv[8]=pack2(t8,t9);
                #pragma unroll
                for (int k = 0; k < NO; k++) {
                    int o = og + 32*k;
                    if ((COUT & 31) && o >= COUT) break;
                    const float* wp = &wsh[ci][o*9 + r*3];
                    u64 wb0 = pack2(wp[0], wp[0]);
                    u64 wb1 = pack2(wp[1], wp[1]);
                    u64 wb2 = pack2(wp[2], wp[2]);
                    #pragma unroll
                    for (int q = 0; q < 4; q++) {
                        pacc[k][q] = ffma2(wb0, pv[2*q],   pacc[k][q]);
                        pacc[k][q] = ffma2(wb1, pv[2*q+1], pacc[k][q]);
                        pacc[k][q] = ffma2(wb2, pv[2*q+2], pacc[k][q]);
                    }
                }
            }
        }
        __syncthreads();
    }
    #pragma unroll
    for (int k = 0; k < NO; k++) {
        int o = og + 32*k;
        if ((COUT & 31) && o >= COUT) break;
        float bb = bias[o];
        float* op = out + ((size_t)(b*COUT + o))*HWn + h*Wn + w0 + pg*8;
        #pragma unroll
        for (int q = 0; q < 4; q++) {
            float2 f = unpack2(pacc[k][q]);
            float vx = f.x + bb, vy = f.y + bb;
            if (RELU) { vx = fmaxf(vx, 0.f); vy = fmaxf(vy, 0.f); }
            op[2*q] = vx; op[2*q+1] = vy;
        }
    }
}

// ------------- merged offset(18) + dg1(50) conv with fused gate head --------
__global__ __launch_bounds__(256)
void convoffdg_k(const float* __restrict__ offw, const float* __restrict__ offbias,
                 const float* __restrict__ dg1w, const float* __restrict__ dg1b,
                 const float* __restrict__ dg2w, const float* __restrict__ dg2b) {
    constexpr int COUT = 68;
    constexpr int NO = 3;
    constexpr int CB = 8;
    __shared__ float tile[CB][3][72];
    __shared__ float wsh[CB][COUT*9];
    __shared__ float sgate[32][64];
    int bx = blockIdx.x;
    int seg = bx & 3; int h = (bx >> 2) & (Hn - 1); int b = bx >> 9;
    int w0 = seg * 64;
    int tid = threadIdx.x;
    int pg = tid & 7, og = tid >> 3;
    u64 pacc[NO][4];
    #pragma unroll
    for (int k = 0; k < NO; k++)
        #pragma unroll
        for (int q = 0; q < 4; q++) pacc[k][q] = 0ull;
    const float* inb = g_aux + (size_t)b*AUXn*HWn;
    for (int c0 = 0; c0 < AUXn; c0 += CB) {
        for (int m = tid; m < CB*3*66; m += 256) {
            int ci = m / 198; int rem = m - ci*198; int r = rem / 66; int cc = rem - r*66;
            int hh = h + r - 1, ww = w0 + cc - 1;
            float v = 0.f;
            if (c0 + ci < AUXn && hh >= 0 && hh < Hn && ww >= 0 && ww < Wn)
                v = inb[(size_t)(c0 + ci)*HWn + hh*Wn + ww];
            tile[ci][r][cc] = v;
        }
        for (int m = tid; m < CB*COUT*9; m += 256) {
            int ci = m / (COUT*9); int rem = m - ci*(COUT*9);
            float v = 0.f;
            if (c0 + ci < AUXn) {
                int o = rem / 9, j = rem - o*9;
                if (o < 18) v = offw[((size_t)o*AUXn + c0 + ci)*9 + j];
                else        v = dg1w[((size_t)(o-18)*AUXn + c0 + ci)*9 + j];
            }
            wsh[ci][rem] = v;
        }
        __syncthreads();
        #pragma unroll 2
        for (int ci = 0; ci < CB; ci++) {
            #pragma unroll
            for (int r = 0; r < 3; r++) {
                const float* trow = &tile[ci][r][pg*8];
                float t0=trow[0],t1=trow[1],t2=trow[2],t3=trow[3],t4=trow[4];
                float t5=trow[5],t6=trow[6],t7=trow[7],t8=trow[8],t9=trow[9];
                u64 pv[9];
                pv[0]=pack2(t0,t1); pv[1]=pack2(t1,t2); pv[2]=pack2(t2,t3);
                pv[3]=pack2(t3,t4); pv[4]=pack2(t4,t5); pv[5]=pack2(t5,t6);
                pv[6]=pack2(t6,t7); pv[7]=pack2(t7,t8); pv[8]=pack2(t8,t9);
                #pragma unroll
                for (int k = 0; k < NO; k++) {
                    int o = og + 32*k;
                    if (o >= COUT) break;
                    const float* wp = &wsh[ci][o*9 + r*3];
                    u64 wb0 = pack2(wp[0], wp[0]);
                    u64 wb1 = pack2(wp[1], wp[1]);
                    u64 wb2 = pack2(wp[2], wp[2]);
                    #pragma unroll
                    for (int q = 0; q < 4; q++) {
                        pacc[k][q] = ffma2(wb0, pv[2*q],   pacc[k][q]);
                        pacc[k][q] = ffma2(wb1, pv[2*q+1], pacc[k][q]);
                        pacc[k][q] = ffma2(wb2, pv[2*q+2], pacc[k][q]);
                    }
                }
            }
        }
        __syncthreads();
    }
    float part[8];
    #pragma unroll
    for (int p = 0; p < 8; p++) part[p] = 0.f;
    #pragma unroll
    for (int k = 0; k < NO; k++) {
        int o = og + 32*k;
        if (o >= COUT) break;
        if (o < 18) {
            float bb = offbias[o];
            float* op = g_offb + ((size_t)(b*18 + o))*HWn + h*Wn + w0 + pg*8;
            #pragma unroll
            for (int q = 0; q < 4; q++) {
                float2 f = unpack2(pacc[k][q]);
                op[2*q] = f.x + bb; op[2*q+1] = f.y + bb;
            }
        } else {
            float bb = dg1b[o-18];
            float wv = dg2w[o-18];
            #pragma unroll
            for (int q = 0; q < 4; q++) {
                float2 f = unpack2(pacc[k][q]);
                part[2*q]   += wv * fmaxf(f.x + bb, 0.f);
                part[2*q+1] += wv * fmaxf(f.y + bb, 0.f);
            }
        }
    }
    #pragma unroll
    for (int p = 0; p < 8; p++) sgate[og][pg*8 + p] = part[p];
    __syncthreads();
    if (tid < 64) {
        float s = dg2b[0];
        #pragma unroll 8
        for (int o2 = 0; o2 < 32; o2++) s += sgate[o2][tid];
        g_gate[(size_t)b*HWn + h*Wn + w0 + tid] = 1.f/(1.f + expf(-s));
    }
}

// ------------------------- deformable sampling + GEMM + combine -------------
__global__ __launch_bounds__(256)
void deform_combine_k(const float* __restrict__ defb) {
    extern __shared__ float dsm[];
    int*   s_idx = (int*)dsm;               // [9][64][4]  = 2304
    float* s_w   = dsm + 2304;              // [9][64][4]  = 2304
    float* samp  = dsm + 4608;              // [9][8][64]  = 4608
    float* wsh   = dsm + 9216;              // [9][8][96]  = 6912
    int bx = blockIdx.x;
    int seg = bx & 3; int h = (bx >> 2) & (Hn - 1); int b = bx >> 9;
    int w0 = seg * 64;
    int tid = threadIdx.x;
    int pg = tid & 7, og = tid >> 3;

    // tap geometry for 9 offsets x 64 pixels
    for (int e = tid; e < 576; e += 256) {
        int t9 = e >> 6, p = e & 63;
        int wpx = w0 + p;
        size_t obase = ((size_t)b*18)*HWn + (size_t)h*Wn + wpx;
        float ox = g_offb[obase + (size_t)(2*t9)*HWn];
        float oy = g_offb[obase + (size_t)(2*t9+1)*HWn];
        float px = (float)wpx + ox;
        float py = (float)h + oy;
        float x0 = floorf(px), y0 = floorf(py);
        float fx = px - x0, fy = py - y0;
        #pragma unroll
        for (int j = 0; j < 4; j++) {
            float xj = x0 + (float)(j & 1);
            float yj = y0 + (float)(j >> 1);
            float valid = (xj >= 0.f && xj <= 255.f && yj >= 0.f && yj <= 127.f) ? 1.f : 0.f;
            float xc = fminf(fmaxf(xj, 0.f), 255.f);
            float yc = fminf(fmaxf(yj, 0.f), 127.f);
            s_idx[(t9*64 + p)*4 + j] = (int)yc * Wn + (int)xc;
            float wx = (j & 1) ? fx : (1.f - fx);
            float wy = (j >> 1) ? fy : (1.f - fy);
            s_w[(t9*64 + p)*4 + j] = wx * wy * valid;
        }
    }

    u64 pacc[3][4];
    #pragma unroll
    for (int k = 0; k < 3; k++)
        #pragma unroll
        for (int q = 0; q < 4; q++) pacc[k][q] = 0ull;

    for (int c0 = 0; c0 < 96; c0 += 8) {
        __syncthreads();
        // gather all 9 taps for this channel chunk (72 independent LDGs in flight)
        for (int e = tid; e < 4608; e += 256) {
            int t9 = e >> 9, rem = e & 511;
            int c = rem >> 6, p = rem & 63;
            const float* yp = g_aux + ((size_t)(b*AUXn + c0 + c))*HWn;
            const int* ip = &s_idx[(t9*64 + p)*4];
            const float* wp = &s_w[(t9*64 + p)*4];
            samp[e] = wp[0]*yp[ip[0]] + wp[1]*yp[ip[1]]
                    + wp[2]*yp[ip[2]] + wp[3]*yp[ip[3]];
        }
        for (int e = tid; e < 6912; e += 256) {
            int t9 = e / 768; int rem = e - t9*768;
            int c = rem / 96; int o = rem - c*96;
            wsh[e] = g_defwt[((size_t)(t9*96) + c0 + c)*96 + o];
        }
        __syncthreads();
        #pragma unroll 3
        for (int t9 = 0; t9 < 9; t9++) {
            #pragma unroll
            for (int c = 0; c < 8; c++) {
                const u64* sp = (const u64*)&samp[(t9*8 + c)*64 + pg*8];
                u64 s0 = sp[0], s1 = sp[1], s2 = sp[2], s3 = sp[3];
                const float* wb = &wsh[(t9*8 + c)*96];
                #pragma unroll
                for (int k = 0; k < 3; k++) {
                    float wv = wb[og + 32*k];
                    u64 wp2 = pack2(wv, wv);
                    pacc[k][0] = ffma2(wp2, s0, pacc[k][0]);
                    pacc[k][1] = ffma2(wp2, s1, pacc[k][1]);
                    pacc[k][2] = ffma2(wp2, s2, pacc[k][2]);
                    pacc[k][3] = ffma2(wp2, s3, pacc[k][3]);
                }
            }
        }
    }
    // epilogue: z = (1-gate)*y_base + gate*(acc + def_b)
    #pragma unroll
    for (int k = 0; k < 3; k++) {
        int o = og + 32*k;
        float bb = defb[o];
        size_t rowoff = (size_t)h*Wn + w0 + pg*8;
        float* zp = g_z + ((size_t)(b*Cn + o))*HWn + rowoff;
        const float* yb = g_ybase + ((size_t)(b*Cn + o))*HWn + rowoff;
        const float* gp = g_gate + (size_t)b*HWn + rowoff;
        #pragma unroll
        for (int q = 0; q < 4; q++) {
            float2 f = unpack2(pacc[k][q]);
            float g0 = gp[2*q], g1 = gp[2*q+1];
            zp[2*q]   = (1.f - g0)*yb[2*q]   + g0*(f.x + bb);
            zp[2*q+1] = (1.f - g1)*yb[2*q+1] + g1*(f.y + bb);
        }
    }
}

// ------------------------- batchnorm ----------------------------------------
__global__ void bn_stats_k() {
    __shared__ float ss[256], ss2[256];
    int c = blockIdx.x, tid = threadIdx.x;
    float s = 0.f, s2 = 0.f;
    for (int i = tid; i < Bn*HWn; i += 256) {
        int b = i >> 15, hw = i & (HWn-1);
        float v = g_z[((size_t)(b*Cn + c))*HWn + hw];
        s += v; s2 += v*v;
    }
    ss[tid] = s; ss2[tid] = s2;
    __syncthreads();
    for (int st = 128; st > 0; st >>= 1) {
        if (tid < st) { ss[tid] += ss[tid+st]; ss2[tid] += ss2[tid+st]; }
        __syncthreads();
    }
    if (tid == 0) {
        float inv = 1.f/(float)(Bn*HWn);
        float mu = ss[0]*inv;
        float var = ss2[0]*inv - mu*mu;
        g_mu[c] = mu;
        g_istd[c] = rsqrtf(var + 1e-5f);
    }
}

__global__ void bn_apply_k(const float* __restrict__ x,
                           const float* __restrict__ gam, const float* __restrict__ bet,
                           float* __restrict__ out) {
    int hw = blockIdx.x*256 + threadIdx.x;
    int c = blockIdx.y, b = blockIdx.z;
    size_t i = ((size_t)(b*Cn + c))*HWn + hw;
    float zn = (g_z[i] - g_mu[c]) * g_istd[c] * gam[c] + bet[c];
    out[i] = fmaxf(zn + x[i], 0.f);
}

// ------------------------- launch -------------------------------------------
extern "C" void kernel_launch(void* const* d_in, const int* in_sizes, int n_in,
                              void* d_out, int out_size) {
    const float* x     = (const float*)d_in[0];
    const float* fdh_w = (const float*)d_in[1];
    const float* fdh_b = (const float*)d_in[2];
    const float* fdw_w = (const float*)d_in[3];
    const float* fdw_b = (const float*)d_in[4];
    const float* cp1_w = (const float*)d_in[5];
    const float* cp1_b = (const float*)d_in[6];
    const float* cp2_w = (const float*)d_in[7];
    const float* cp2_b = (const float*)d_in[8];
    const float* sdh_w = (const float*)d_in[9];
    const float* sdh_b = (const float*)d_in[10];
    const float* sdw_w = (const float*)d_in[11];
    const float* sdw_b = (const float*)d_in[12];
    const float* sr1_w = (const float*)d_in[13];
    const float* sr1_b = (const float*)d_in[14];
    const float* sr2_w = (const float*)d_in[15];
    const float* sr2_b = (const float*)d_in[16];
    const float* off_w = (const float*)d_in[17];
    const float* off_b = (const float*)d_in[18];
    const float* dg1_w = (const float*)d_in[19];
    const float* dg1_b = (const float*)d_in[20];
    const float* dg2_w = (const float*)d_in[21];
    const float* dg2_b = (const float*)d_in[22];
    const float* base_w = (const float*)d_in[23];
    const float* base_b = (const float*)d_in[24];
    const float* def_w = (const float*)d_in[25];
    const float* def_b = (const float*)d_in[26];
    const float* bn_g  = (const float*)d_in[27];
    const float* bn_b  = (const float*)d_in[28];
    float* out = (float*)d_out;

    float *p_fe, *p_fem, *p_aux, *p_ybase;
    cudaGetSymbolAddress((void**)&p_fe, g_fe);
    cudaGetSymbolAddress((void**)&p_fem, g_fem);
    cudaGetSymbolAddress((void**)&p_aux, g_aux);
    cudaGetSymbolAddress((void**)&p_ybase, g_ybase);

    const int FFT_SMEM  = 36104 * 4;   // 144416 B
    const int FREQ_SMEM = 128*132 * 4; // 67584 B
    const int DEF_SMEM  = 16128 * 4;   // 64512 B
    cudaFuncSetAttribute(fft2d_k, cudaFuncAttributeMaxDynamicSharedMemorySize, FFT_SMEM);
    cudaFuncSetAttribute(freq_fused_k, cudaFuncAttributeMaxDynamicSharedMemorySize, FREQ_SMEM);
    cudaFuncSetAttribute(deform_combine_k, cudaFuncAttributeMaxDynamicSharedMemorySize, DEF_SMEM);

    prep_k<<<324, 256>>>(def_w);
    // ---- FFT(x) -> mag, fe ----
    fft2d_k<<<dim3(Cn, Bn), 512, FFT_SMEM>>>(x, Cn);
    chan_mean_k<<<dim3(Hn, Bn), 160>>>(p_fe);
    // ---- freq branch ----
    freq_fused_k<<<dim3(Cn, Bn), 160, FREQ_SMEM>>>(fdh_w, fdh_b, fdw_w, fdw_b);
    ca_mlp_k<<<Bn, 96>>>(cp1_w, cp1_b, cp2_w, cp2_b);
    // ---- spatial branch ----
    spatial_in_k<<<dim3(Hn, Bn), 256>>>(x);
    dwsp_h_k<<<CDIV(Bn*3*HWn,256), 256>>>(sdh_w, sdh_b);
    dwsp_w_k<<<CDIV(Bn*3*HWn,256), 256>>>(sdw_w, sdw_b);
    sr_k<<<CDIV(Bn*HWn,256), 256>>>(sr1_w, sr1_b, sr2_w, sr2_b);
    ymul_k<<<dim3(HWn/256, Cn, Bn), 256>>>(x);
    // ---- FFT(y) -> mag, fem ----
    fft2d_k<<<dim3(Cn, Bn), 512, FFT_SMEM>>>(p_aux, AUXn);
    chan_mean_k<<<dim3(Hn, Bn), 160>>>(p_fem);
    auxmisc_k<<<dim3(Hn, Bn), 256>>>();
    // ---- convs ----
    convoffdg_k<<<1024, 256>>>(off_w, off_b, dg1_w, dg1_b, dg2_w, dg2_b);
    conv3x3_k<Cn,AUXn,96,false><<<1024, 256>>>(p_aux, base_w, base_b, p_ybase);
    // ---- deformable ----
    deform_combine_k<<<1024, 256, DEF_SMEM>>>(def_b);
    // ---- BN + residual relu ----
    bn_stats_k<<<Cn, 256>>>();
    bn_apply_k<<<dim3(HWn/256, Cn, Bn), 256>>>(x, bn_g, bn_b, out);
}

// round 5
// speedup vs baseline: 1.2017x; 1.0027x over previous
#include <cuda_runtime.h>
#include <math.h>

#define Bn 2
#define Cn 96
#define Hn 128
#define Wn 256
#define WFn 129
#define HWn (Hn*Wn)
#define AUXn 101
#define MIDn 24
#define DMIDn 50
#define NTOT (Bn*Cn*HWn)
#define NF (Bn*Cn*Hn*WFn)
#define CDIV(a,b) (((a)+(b)-1)/(b))

typedef unsigned long long u64;

__device__ __forceinline__ u64 ffma2(u64 a, u64 b, u64 c) {
    u64 d;
    asm("fma.rn.f32x2 %0, %1, %2, %3;" : "=l"(d) : "l"(a), "l"(b), "l"(c));
    return d;
}
__device__ __forceinline__ float2 unpack2(u64 v) {
    float2 d; asm("mov.b64 {%0, %1}, %2;" : "=f"(d.x), "=f"(d.y) : "l"(v)); return d;
}

// ------------------------- scratch (static device memory) -------------------
static __device__ float2 g_tw[128];
static __device__ float g_mag[NF];
static __device__ float g_fe[Bn*Hn*WFn];
static __device__ float g_fem[Bn*Hn*WFn];
static __device__ float g_gvec[Bn*3*Cn];
static __device__ float g_ca[Bn*Cn];
static __device__ float g_s0[Bn*3*HWn];
static __device__ float g_s1[Bn*3*HWn];
static __device__ float g_sa[Bn*HWn];
static __device__ float g_aux[(size_t)Bn*AUXn*HWn];
static __device__ float g_offb[Bn*18*HWn];
static __device__ float g_gate[Bn*HWn];
static __device__ float g_ybase[NTOT];
static __device__ float g_z[NTOT];
static __device__ float g_defwt[9*96*96];
static __device__ float g_mu[Cn];
static __device__ float g_istd[Cn];

// ------------------------- prep (3 tiny launches) ---------------------------
__global__ void prep_tw_k() {
    int j = threadIdx.x;           // 128
    float ang = -6.2831853071795864f * (float)j / 256.f;
    float s, c; sincosf(ang, &s, &c);
    g_tw[j] = make_float2(c, s);
}
__global__ void prep_defw_k(const float* __restrict__ defw, int i0, int i1) {
    int i = i0 + blockIdx.x*256 + threadIdx.x;
    if (i >= i1) return;
    int o = i % 96; int c = (i / 96) % 96; int t = i / (96*96);
    g_defwt[i] = defw[((size_t)o*96 + c)*9 + t];
}

// ------------------------- fused 2D FFT -> |.| ------------------------------
__global__ __launch_bounds__(512)
void fft2d_k(const float* __restrict__ in, int cstride) {
    extern __shared__ float fs[];
    float* sre = fs;                       // 129*132
    float* sim = fs + 17028;               // 129*132
    float* rwre_base = fs + 34056;         // 4*256
    float* rwim_base = fs + 35080;         // 4*256
    int c = blockIdx.x, b = blockIdx.y;
    const float* plane = in + ((size_t)(b*cstride + c))*HWn;
    int tid = threadIdx.x;
    int pr = tid >> 7;                    // 0..3
    int l  = tid & 127;
    float* rwre = rwre_base + pr*256;
    float* rwim = rwim_base + pr*256;

    for (int ob = 0; ob < 16; ob++) {
        int h0 = (ob*4 + pr)*2;
        const float* r0 = plane + (size_t)h0*Wn;
        const float* r1 = r0 + Wn;
        __syncthreads();
        for (int i = l; i < 256; i += 128) {
            int j = __brev((unsigned)i) >> 24;
            rwre[j] = r0[i]; rwim[j] = r1[i];
        }
        __syncthreads();
        #pragma unroll
        for (int s = 1; s <= 8; s++) {
            int half = 1 << (s-1);
            int off = l & (half-1);
            int a = ((l >> (s-1)) << s) + off;
            int bb = a + half;
            float2 tw = g_tw[off << (8-s)];
            float br = rwre[bb], bi = rwim[bb], ar = rwre[a], ai = rwim[a];
            float xr = br*tw.x - bi*tw.y, xi = br*tw.y + bi*tw.x;
            rwre[a] = ar+xr; rwim[a] = ai+xi;
            rwre[bb] = ar-xr; rwim[bb] = ai-xi;
            __syncthreads();
        }
        {
            int k = l;
            float zr = rwre[k], zi = rwim[k];
            int km = (256-k)&255;
            float wr = rwre[km], wi = rwim[km];
            sre[k*132 + h0]   = 0.5f*(zr+wr);
            sim[k*132 + h0]   = 0.5f*(zi-wi);
            sre[k*132 + h0+1] = 0.5f*(zi+wi);
            sim[k*132 + h0+1] = -0.5f*(zr-wr);
            if (l == 0) {
                sre[128*132 + h0] = rwre[128];   sim[128*132 + h0] = 0.f;
                sre[128*132 + h0+1] = rwim[128]; sim[128*132 + h0+1] = 0.f;
            }
        }
    }
    __syncthreads();
    for (int e = tid; e < 129*128; e += 512) {
        int col = e >> 7, hh = e & 127;
        int j = __brev((unsigned)hh) >> 25;
        if (hh < j) {
            float t = sre[col*132+hh]; sre[col*132+hh] = sre[col*132+j]; sre[col*132+j] = t;
            t = sim[col*132+hh]; sim[col*132+hh] = sim[col*132+j]; sim[col*132+j] = t;
        }
    }
    __syncthreads();
    #pragma unroll
    for (int s = 1; s <= 7; s++) {
        int half = 1 << (s-1);
        for (int e = tid; e < 129*64; e += 512) {
            int i = e & 63, col = e >> 6;
            int off = i & (half-1);
            int a = ((i >> (s-1)) << s) + off;
            int bb = a + half;
            float2 tw = g_tw[off << (8-s)];
            float* cr = sre + col*132; float* ci2 = sim + col*132;
            float br = cr[bb], bi = ci2[bb], ar = cr[a], ai = ci2[a];
            float xr = br*tw.x - bi*tw.y, xi = br*tw.y + bi*tw.x;
            cr[a]=ar+xr; ci2[a]=ai+xi; cr[bb]=ar-xr; ci2[bb]=ai-xi;
        }
        __syncthreads();
    }
    const float sc = 0.0055242717280199026f;  // 1/sqrt(128*256)
    float* mout = g_mag + (size_t)(b*Cn + c)*Hn*WFn;
    for (int e = tid; e < 128*129; e += 512) {
        int hh = e / 129, col = e - hh*129;
        float r = sre[col*132+hh], m = sim[col*132+hh];
        mout[e] = sqrtf(r*r + m*m)*sc;
    }
}

// mean over channels of g_mag -> out[b][h][k]
__global__ void chan_mean_k(float* __restrict__ out) {
    int h = blockIdx.x, b = blockIdx.y;
    for (int k = threadIdx.x; k < WFn; k += 160) {
        float s = 0.f;
        const float* p = g_mag + ((size_t)(b*Cn)*Hn + h)*WFn + k;
        #pragma unroll 4
        for (int c = 0; c < Cn; c++) s += p[(size_t)c*Hn*WFn];
        out[(size_t)(b*Hn + h)*WFn + k] = s * (1.f/Cn);
    }
}

// --------- fused freq branch: fully parallel 512-thread version -------------
__global__ __launch_bounds__(512)
void freq_fused_k(const float* __restrict__ w7h, const float* __restrict__ b7h,
                  const float* __restrict__ w7w, const float* __restrict__ b7w) {
    extern __shared__ float FS[];
    float* A  = FS;                 // [128][132]
    float* T1 = FS + 128*132;       // [128][136], data at [h][3+k], pads zero
    __shared__ float S[4][132];
    __shared__ float bins[21];
    int c = blockIdx.x, b = blockIdx.y;
    int tid = threadIdx.x;
    const float* mp = g_mag + (size_t)(b*Cn + c)*Hn*WFn;
    for (int e = tid; e < 128*129; e += 512) {
        int h = e / 129, k = e - h*129;
        A[h*132 + k] = mp[e];
    }
    for (int e = tid; e < 128*136; e += 512) T1[e] = 0.f;
    float wh[7], ww[7];
    #pragma unroll
    for (int d = 0; d < 7; d++) { wh[d] = w7h[c*7+d]; ww[d] = w7w[c*7+d]; }
    float bh = b7h[c], bw = b7w[c];
    __syncthreads();
    // vertical 7-tap -> T1
    for (int e = tid; e < 128*129; e += 512) {
        int h = e / 129, k = e - h*129;
        float a = bh;
        #pragma unroll
        for (int d = 0; d < 7; d++) {
            int h2 = h + d - 3;
            if (h2 >= 0 && h2 < 128) a += wh[d]*A[h2*132 + k];
        }
        T1[h*136 + 3 + k] = a;
    }
    __syncthreads();
    // horizontal 7-tap + per-band accumulate
    for (int e = tid; e < 4*129; e += 512) {
        int band = e / 129, k = e - band*129;
        float acc = 0.f;
        for (int hh = 0; hh < 32; hh++) {
            int h = band*32 + hh;
            float t2v = bw;
            #pragma unroll
            for (int d = 0; d < 7; d++) t2v += ww[d]*T1[h*136 + k + d];
            acc += t2v;
        }
        S[band][k] = acc;
    }
    __syncthreads();
    if (tid < 16) {
        int i = tid >> 2, j = tid & 3;
        int ws = (j*WFn)/4, we = ((j+1)*WFn + 3)/4;
        float s = 0;
        for (int k = ws; k < we; k++) s += S[i][k];
        bins[tid] = s / (32.f * (float)(we - ws));
    } else if (tid < 20) {
        int t2 = tid - 16; int i = t2 >> 1, j = t2 & 1;
        int ws = (j*WFn)/2, we = ((j+1)*WFn + 1)/2;
        float s = 0;
        for (int k = ws; k < we; k++) s += S[2*i][k] + S[2*i+1][k];
        bins[tid] = s / (64.f * (float)(we - ws));
    } else if (tid == 20) {
        float s = 0;
        for (int k = 0; k < WFn; k++) s += S[0][k]+S[1][k]+S[2][k]+S[3][k];
        bins[20] = s / (128.f*129.f);
    }
    __syncthreads();
    if (tid == 0) {
        float g2 = bins[16]+bins[17]+bins[18]+bins[19];
        float g3 = 0;
        for (int m = 0; m < 16; m++) g3 += bins[m];
        g_gvec[b*288 + c]        = bins[20];
        g_gvec[b*288 + Cn + c]   = g2 * 0.25f;
        g_gvec[b*288 + 2*Cn + c] = g3 * 0.0625f;
    }
}

// ------------------------- channel-attention MLP ----------------------------
__global__ void ca_mlp_k(const float* __restrict__ w1, const float* __restrict__ b1,
                         const float* __restrict__ w2, const float* __restrict__ b2) {
    __shared__ float gs[288], hs[MIDn];
    int b = blockIdx.x, tid = threadIdx.x;   // 96 threads
    for (int i = tid; i < 288; i += 96) gs[i] = g_gvec[b*288 + i];
    __syncthreads();
    if (tid < MIDn) {
        float a = b1[tid];
        for (int k = 0; k < 288; k++) a += w1[tid*288 + k]*gs[k];
        hs[tid] = fmaxf(a, 0.f);
    }
    __syncthreads();
    float a = b2[tid];
    #pragma unroll
    for (int m = 0; m < MIDn; m++) a += w2[tid*MIDn + m]*hs[m];
    g_ca[b*Cn + tid] = 1.f/(1.f + expf(-a));
}

// ------------------------- spatial branch -----------------------------------
__global__ void spatial_in_k(const float* __restrict__ x) {
    int h = blockIdx.x, b = blockIdx.y;
    int w = threadIdx.x;                  // 256
    int hw = h*Wn + w;
    const float* xp = x + (size_t)b*Cn*HWn + hw;
    float s = 0.f, s2 = 0.f;
    #pragma unroll 4
    for (int c = 0; c < Cn; c++) { float v = xp[(size_t)c*HWn]; s += v; s2 += v*v; }
    float mean = s * (1.f/Cn);
    float l2 = sqrtf(s2 * (1.f/Cn) + 1e-6f);
    float src = ((float)w + 0.5f)*(129.f/256.f) - 0.5f;
    float f0 = floorf(src); int i0 = (int)f0; float fr = src - f0;
    int ia = min(max(i0, 0), WFn-1), ib = min(max(i0+1, 0), WFn-1);
    const float* fp = g_fe + (size_t)(b*Hn + h)*WFn;
    float fv = fp[ia]*(1.f - fr) + fp[ib]*fr;
    g_s0[((size_t)(b*3+0))*HWn + hw] = mean;
    g_s0[((size_t)(b*3+1))*HWn + hw] = l2;
    g_s0[((size_t)(b*3+2))*HWn + hw] = fv;
}

__global__ void dwsp_h_k(const float* __restrict__ w15, const float* __restrict__ b15) {
    int i = blockIdx.x*blockDim.x + threadIdx.x;
    if (i >= Bn*3*HWn) return;
    int w = i & (Wn-1); int t = i >> 8; int h = t & (Hn-1); int bc = t >> 7; int ch = bc % 3;
    float a = b15[ch];
    #pragma unroll
    for (int d = 0; d < 15; d++) {
        int hh = h + d - 7;
        if (hh >= 0 && hh < Hn) a += w15[ch*15+d]*g_s0[((size_t)bc*Hn + hh)*Wn + w];
    }
    g_s1[i] = a;
}

__global__ void dwsp_w_k(const float* __restrict__ w15, const float* __restrict__ b15) {
    int i = blockIdx.x*blockDim.x + threadIdx.x;
    if (i >= Bn*3*HWn) return;
    int w = i & (Wn-1); int t = i >> 8; int bc = t >> 7; int ch = bc % 3;
    float a = b15[ch];
    #pragma unroll
    for (int d = 0; d < 15; d++) {
        int ww = w + d - 7;
        if (ww >= 0 && ww < Wn) a += w15[ch*15+d]*g_s1[(size_t)t*Wn + ww];
    }
    g_s0[i] = a;
}

__global__ void sr_k(const float* __restrict__ sr1w, const float* __restrict__ sr1b,
                     const float* __restrict__ sr2w, const float* __restrict__ sr2b) {
    int i = blockIdx.x*blockDim.x + threadIdx.x;
    if (i >= Bn*HWn) return;
    int b = i >> 15; int hw = i & (HWn-1); int h = hw >> 8; int w = hw & (Wn-1);
    float acc = sr2b[0];
    #pragma unroll
    for (int g3 = 0; g3 < 3; g3++) {
        float v = sr1b[g3];
        #pragma unroll
        for (int ky = 0; ky < 3; ky++) {
            int hh = h + ky - 1; if (hh < 0 || hh >= Hn) continue;
            #pragma unroll
            for (int kx = 0; kx < 3; kx++) {
                int ww = w + kx - 1; if (ww < 0 || ww >= Wn) continue;
                v += sr1w[g3*9 + ky*3 + kx]*g_s0[((size_t)(b*3+g3)*Hn + hh)*Wn + ww];
            }
        }
        acc += sr2w[g3]*fmaxf(v, 0.f);
    }
    g_sa[i] = 1.f/(1.f + expf(-acc));
}

// y = x*ca*sa written directly into aux channels [0..95]
__global__ void ymul_k(const float* __restrict__ x) {
    int hw = blockIdx.x*256 + threadIdx.x;
    int c = blockIdx.y, b = blockIdx.z;
    float v = x[((size_t)(b*Cn + c))*HWn + hw] * g_ca[b*Cn + c] * g_sa[(size_t)b*HWn + hw];
    g_aux[((size_t)(b*AUXn + c))*HWn + hw] = v;
}

__global__ void auxmisc_k() {
    int h = blockIdx.x, b = blockIdx.y;
    int w = threadIdx.x;                 // 256
    int hw = h*Wn + w;
    float theta = -3.14159265358979324f + (float)w * (6.2831853071795864f/255.f);
    float phi   = -1.57079632679489662f + (float)h * (3.14159265358979324f/127.f);
    size_t base = (size_t)b*AUXn*HWn + hw;
    g_aux[base + (size_t)96*HWn] = sinf(theta);
    g_aux[base + (size_t)97*HWn] = cosf(theta);
    g_aux[base + (size_t)98*HWn] = sinf(phi);
    g_aux[base + (size_t)99*HWn] = cosf(phi);
    float src = ((float)w + 0.5f)*(129.f/256.f) - 0.5f;
    float f0 = floorf(src); int i0 = (int)f0; float fr = src - f0;
    int ia = min(max(i0, 0), WFn-1), ib = min(max(i0+1, 0), WFn-1);
    const float* fp = g_fem + (size_t)(b*Hn + h)*WFn;
    g_aux[base + (size_t)100*HWn] = fp[ia]*(1.f - fr) + fp[ib]*fr;
}

// ------------- tiled 3x3 conv: swizzled pair-tile + packed weights ----------
// tile2 physical slot p (<64) holds logical pair l = ((p&7)<<3)|(p>>3);
// slot 64 holds pair l=64. Pair l = (t[l], t[l+1]).
// Compute: pv[j] = slot j*8+pg (conflict-free LDS.64); pv[8] = slot pg+1 / 64.
template<int CIN, int CSTRIDE, int COUT, bool RELU>
__global__ __launch_bounds__(256)
void conv3x3_k(const float* __restrict__ in, const float* __restrict__ wgt,
               const float* __restrict__ bias, float* __restrict__ out) {
    constexpr int NO = (COUT + 31) / 32;
    constexpr int CB = 8;
    __shared__ float2 tile2[CB][3][66];
    extern __shared__ float2 wdyn[];          // [CB][COUT*9] packed (w,w)
    int bx = blockIdx.x;
    int seg = bx & 3; int h = (bx >> 2) & (Hn - 1); int b = bx >> 9;
    int w0 = seg * 64;
    int tid = threadIdx.x;
    int pg = tid & 7, og = tid >> 3;
    u64 pacc[NO][4];
    #pragma unroll
    for (int k = 0; k < NO; k++)
        #pragma unroll
        for (int q = 0; q < 4; q++) pacc[k][q] = 0ull;
    const float* inb = in + (size_t)b*CSTRIDE*HWn;
    int pv8idx = (pg == 7) ? 64 : (pg + 1);
    for (int c0 = 0; c0 < CIN; c0 += CB) {
        for (int m = tid; m < CB*3*65; m += 256) {
            int ci = m / 195; int rem = m - ci*195; int r = rem / 65; int p = rem - r*65;
            int l = (p < 64) ? (((p & 7) << 3) | (p >> 3)) : 64;
            int hh = h + r - 1, ww = w0 + l - 1;
            float v0 = 0.f, v1 = 0.f;
            if (c0 + ci < CIN && hh >= 0 && hh < Hn) {
                const float* rowp = inb + (size_t)(c0 + ci)*HWn + (size_t)hh*Wn;
                if (ww >= 0 && ww < Wn) v0 = rowp[ww];
                if (ww + 1 >= 0 && ww + 1 < Wn) v1 = rowp[ww + 1];
            }
            tile2[ci][r][p] = make_float2(v0, v1);
        }
        for (int m = tid; m < CB*COUT*9; m += 256) {
            int ci = m / (COUT*9); int rem = m - ci*(COUT*9);
            float v = 0.f;
            if (c0 + ci < CIN) {
                int o = rem / 9, j = rem - o*9;
                v = wgt[((size_t)o*CIN + c0 + ci)*9 + j];
            }
            wdyn[ci*(COUT*9) + rem] = make_float2(v, v);
        }
        __syncthreads();
        #pragma unroll 2
        for (int ci = 0; ci < CB; ci++) {
            #pragma unroll
            for (int r = 0; r < 3; r++) {
                const float2* trow = tile2[ci][r];
                u64 pv[9];
                #pragma unroll
                for (int j = 0; j < 8; j++) pv[j] = *(const u64*)&trow[j*8 + pg];
                pv[8] = *(const u64*)&trow[pv8idx];
                #pragma unroll
                for (int k = 0; k < NO; k++) {
                    int o = og + 32*k;
                    if ((COUT & 31) && o >= COUT) break;
                    const u64* wp = (const u64*)&wdyn[ci*(COUT*9) + o*9 + r*3];
                    u64 wb0 = wp[0], wb1 = wp[1], wb2 = wp[2];
                    #pragma unroll
                    for (int q = 0; q < 4; q++) {
                        pacc[k][q] = ffma2(wb0, pv[2*q],   pacc[k][q]);
                        pacc[k][q] = ffma2(wb1, pv[2*q+1], pacc[k][q]);
                        pacc[k][q] = ffma2(wb2, pv[2*q+2], pacc[k][q]);
                    }
                }
            }
        }
        __syncthreads();
    }
    #pragma unroll
    for (int k = 0; k < NO; k++) {
        int o = og + 32*k;
        if ((COUT & 31) && o >= COUT) break;
        float bb = bias[o];
        float* op = out + ((size_t)(b*COUT + o))*HWn + h*Wn + w0 + pg*8;
        #pragma unroll
        for (int q = 0; q < 4; q++) {
            float2 f = unpack2(pacc[k][q]);
            float vx = f.x + bb, vy = f.y + bb;
            if (RELU) { vx = fmaxf(vx, 0.f); vy = fmaxf(vy, 0.f); }
            op[2*q] = vx; op[2*q+1] = vy;
        }
    }
}

// ------------- merged offset(18) + dg1(50) conv with fused gate head --------
__global__ __launch_bounds__(256)
void convoffdg_k(const float* __restrict__ offw, const float* __restrict__ offbias,
                 const float* __restrict__ dg1w, const float* __restrict__ dg1b,
                 const float* __restrict__ dg2w, const float* __restrict__ dg2b) {
    constexpr int COUT = 68;
    constexpr int NO = 3;
    constexpr int CB = 8;
    __shared__ float2 tile2[CB][3][66];
    __shared__ float sgate[32][64];
    extern __shared__ float2 wdyn[];          // [CB][COUT*9]
    int bx = blockIdx.x;
    int seg = bx & 3; int h = (bx >> 2) & (Hn - 1); int b = bx >> 9;
    int w0 = seg * 64;
    int tid = threadIdx.x;
    int pg = tid & 7, og = tid >> 3;
    u64 pacc[NO][4];
    #pragma unroll
    for (int k = 0; k < NO; k++)
        #pragma unroll
        for (int q = 0; q < 4; q++) pacc[k][q] = 0ull;
    const float* inb = g_aux + (size_t)b*AUXn*HWn;
    int pv8idx = (pg == 7) ? 64 : (pg + 1);
    for (int c0 = 0; c0 < AUXn; c0 += CB) {
        for (int m = tid; m < CB*3*65; m += 256) {
            int ci = m / 195; int rem = m - ci*195; int r = rem / 65; int p = rem - r*65;
            int l = (p < 64) ? (((p & 7) << 3) | (p >> 3)) : 64;
            int hh = h + r - 1, ww = w0 + l - 1;
            float v0 = 0.f, v1 = 0.f;
            if (c0 + ci < AUXn && hh >= 0 && hh < Hn) {
                const float* rowp = inb + (size_t)(c0 + ci)*HWn + (size_t)hh*Wn;
                if (ww >= 0 && ww < Wn) v0 = rowp[ww];
                if (ww + 1 >= 0 && ww + 1 < Wn) v1 = rowp[ww + 1];
            }
            tile2[ci][r][p] = make_float2(v0, v1);
        }
        for (int m = tid; m < CB*COUT*9; m += 256) {
            int ci = m / (COUT*9); int rem = m - ci*(COUT*9);
            float v = 0.f;
            if (c0 + ci < AUXn) {
                int o = rem / 9, j = rem - o*9;
                if (o < 18) v = offw[((size_t)o*AUXn + c0 + ci)*9 + j];
                else        v = dg1w[((size_t)(o-18)*AUXn + c0 + ci)*9 + j];
            }
            wdyn[ci*(COUT*9) + rem] = make_float2(v, v);
        }
        __syncthreads();
        #pragma unroll 2
        for (int ci = 0; ci < CB; ci++) {
            #pragma unroll
            for (int r = 0; r < 3; r++) {
                const float2* trow = tile2[ci][r];
                u64 pv[9];
                #pragma unroll
                for (int j = 0; j < 8; j++) pv[j] = *(const u64*)&trow[j*8 + pg];
                pv[8] = *(const u64*)&trow[pv8idx];
                #pragma unroll
                for (int k = 0; k < NO; k++) {
                    int o = og + 32*k;
                    if (o >= COUT) break;
                    const u64* wp = (const u64*)&wdyn[ci*(COUT*9) + o*9 + r*3];
                    u64 wb0 = wp[0], wb1 = wp[1], wb2 = wp[2];
                    #pragma unroll
                    for (int q = 0; q < 4; q++) {
                        pacc[k][q] = ffma2(wb0, pv[2*q],   pacc[k][q]);
                        pacc[k][q] = ffma2(wb1, pv[2*q+1], pacc[k][q]);
                        pacc[k][q] = ffma2(wb2, pv[2*q+2], pacc[k][q]);
                    }
                }
            }
        }
        __syncthreads();
    }
    float part[8];
    #pragma unroll
    for (int p = 0; p < 8; p++) part[p] = 0.f;
    #pragma unroll
    for (int k = 0; k < NO; k++) {
        int o = og + 32*k;
        if (o >= COUT) break;
        if (o < 18) {
            float bb = offbias[o];
            float* op = g_offb + ((size_t)(b*18 + o))*HWn + h*Wn + w0 + pg*8;
            #pragma unroll
            for (int q = 0; q < 4; q++) {
                float2 f = unpack2(pacc[k][q]);
                op[2*q] = f.x + bb; op[2*q+1] = f.y + bb;
            }
        } else {
            float bb = dg1b[o-18];
            float wv = dg2w[o-18];
            #pragma unroll
            for (int q = 0; q < 4; q++) {
                float2 f = unpack2(pacc[k][q]);
                part[2*q]   += wv * fmaxf(f.x + bb, 0.f);
                part[2*q+1] += wv * fmaxf(f.y + bb, 0.f);
            }
        }
    }
    #pragma unroll
    for (int p = 0; p < 8; p++) sgate[og][pg*8 + p] = part[p];
    __syncthreads();
    if (tid < 64) {
        float s = dg2b[0];
        #pragma unroll 8
        for (int o2 = 0; o2 < 32; o2++) s += sgate[o2][tid];
        g_gate[(size_t)b*HWn + h*Wn + w0 + tid] = 1.f/(1.f + expf(-s));
    }
}

// ------------------------- deformable sampling + GEMM + combine -------------
// samp2: pair P (pixels 2P,2P+1) stored at phys ((P&3)<<3)|(P>>2) per (t9,c)
__global__ __launch_bounds__(256)
void deform_combine_k(const float* __restrict__ defb) {
    extern __shared__ float dsm[];
    float2* samp2 = (float2*)dsm;                    // 2304 float2
    float2* wsh2  = (float2*)(dsm + 4608);           // 6912 float2
    float*  s_w   = dsm + 18432;                     // 2304
    int*    s_idx = (int*)(dsm + 20736);             // 2304
    int bx = blockIdx.x;
    int seg = bx & 3; int h = (bx >> 2) & (Hn - 1); int b = bx >> 9;
    int w0 = seg * 64;
    int tid = threadIdx.x;
    int pg = tid & 7, og = tid >> 3;

    for (int e = tid; e < 576; e += 256) {
        int t9 = e >> 6, p = e & 63;
        int wpx = w0 + p;
        size_t obase = ((size_t)b*18)*HWn + (size_t)h*Wn + wpx;
        float ox = g_offb[obase + (size_t)(2*t9)*HWn];
        float oy = g_offb[obase + (size_t)(2*t9+1)*HWn];
        float px = (float)wpx + ox;
        float py = (float)h + oy;
        float x0 = floorf(px), y0 = floorf(py);
        float fx = px - x0, fy = py - y0;
        #pragma unroll
        for (int j = 0; j < 4; j++) {
            float xj = x0 + (float)(j & 1);
            float yj = y0 + (float)(j >> 1);
            float valid = (xj >= 0.f && xj <= 255.f && yj >= 0.f && yj <= 127.f) ? 1.f : 0.f;
            float xc = fminf(fmaxf(xj, 0.f), 255.f);
            float yc = fminf(fmaxf(yj, 0.f), 127.f);
            s_idx[(t9*64 + p)*4 + j] = (int)yc * Wn + (int)xc;
            float wx = (j & 1) ? fx : (1.f - fx);
            float wy = (j >> 1) ? fy : (1.f - fy);
            s_w[(t9*64 + p)*4 + j] = wx * wy * valid;
        }
    }

    u64 pacc[3][4];
    #pragma unroll
    for (int k = 0; k < 3; k++)
        #pragma unroll
        for (int q = 0; q < 4; q++) pacc[k][q] = 0ull;

    for (int c0 = 0; c0 < 96; c0 += 8) {
        __syncthreads();
        // gather pairs: 2304 pairs, 8 LDG each -> deep MLP
        for (int e = tid; e < 2304; e += 256) {
            int t9 = e >> 8; int rem = e & 255; int c = rem >> 5; int P = rem & 31;
            int p0 = 2*P;
            const float* yp = g_aux + ((size_t)(b*AUXn + c0 + c))*HWn;
            const int* i0 = &s_idx[(t9*64 + p0)*4];
            const float* q0 = &s_w[(t9*64 + p0)*4];
            float v0 = q0[0]*yp[i0[0]] + q0[1]*yp[i0[1]] + q0[2]*yp[i0[2]] + q0[3]*yp[i0[3]];
            const int* i1 = i0 + 4; const float* q1 = q0 + 4;
            float v1 = q1[0]*yp[i1[0]] + q1[1]*yp[i1[1]] + q1[2]*yp[i1[2]] + q1[3]*yp[i1[3]];
            samp2[(t9*8 + c)*32 + (((P & 3) << 3) | (P >> 2))] = make_float2(v0, v1);
        }
        for (int e = tid; e < 6912; e += 256) {
            int t9 = e / 768; int rem = e - t9*768;
            int c = rem / 96; int o = rem - c*96;
            float v = g_defwt[((size_t)(t9*96) + c0 + c)*96 + o];
            wsh2[e] = make_float2(v, v);
        }
        __syncthreads();
        #pragma unroll 3
        for (int t9 = 0; t9 < 9; t9++) {
            #pragma unroll
            for (int c = 0; c < 8; c++) {
                const float2* sp = &samp2[(t9*8 + c)*32];
                u64 s0 = *(const u64*)&sp[0*8 + pg];
                u64 s1 = *(const u64*)&sp[1*8 + pg];
                u64 s2 = *(const u64*)&sp[2*8 + pg];
                u64 s3 = *(const u64*)&sp[3*8 + pg];
                const float2* wb = &wsh2[(t9*8 + c)*96];
                #pragma unroll
                for (int k = 0; k < 3; k++) {
                    u64 wp2 = *(const u64*)&wb[og + 32*k];
                    pacc[k][0] = ffma2(wp2, s0, pacc[k][0]);
                    pacc[k][1] = ffma2(wp2, s1, pacc[k][1]);
                    pacc[k][2] = ffma2(wp2, s2, pacc[k][2]);
                    pacc[k][3] = ffma2(wp2, s3, pacc[k][3]);
                }
            }
        }
    }
    // epilogue: z = (1-gate)*y_base + gate*(acc + def_b)
    // pacc[k][q] holds pixels (2*(pg*4+q), 2*(pg*4+q)+1) -> same as pg*8+2q
    #pragma unroll
    for (int k = 0; k < 3; k++) {
        int o = og + 32*k;
        float bb = defb[o];
        size_t rowoff = (size_t)h*Wn + w0 + pg*8;
        float* zp = g_z + ((size_t)(b*Cn + o))*HWn + rowoff;
        const float* yb = g_ybase + ((size_t)(b*Cn + o))*HWn + rowoff;
        const float* gp = g_gate + (size_t)b*HWn + rowoff;
        #pragma unroll
        for (int q = 0; q < 4; q++) {
            float2 f = unpack2(pacc[k][q]);
            float g0 = gp[2*q], g1 = gp[2*q+1];
            zp[2*q]   = (1.f - g0)*yb[2*q]   + g0*(f.x + bb);
            zp[2*q+1] = (1.f - g1)*yb[2*q+1] + g1*(f.y + bb);
        }
    }
}

// ------------------------- batchnorm ----------------------------------------
__global__ void bn_stats_k() {
    __shared__ float ss[256], ss2[256];
    int c = blockIdx.x, tid = threadIdx.x;
    float s = 0.f, s2 = 0.f;
    for (int i = tid; i < Bn*HWn; i += 256) {
        int b = i >> 15, hw = i & (HWn-1);
        float v = g_z[((size_t)(b*Cn + c))*HWn + hw];
        s += v; s2 += v*v;
    }
    ss[tid] = s; ss2[tid] = s2;
    __syncthreads();
    for (int st = 128; st > 0; st >>= 1) {
        if (tid < st) { ss[tid] += ss[tid+st]; ss2[tid] += ss2[tid+st]; }
        __syncthreads();
    }
    if (tid == 0) {
        float inv = 1.f/(float)(Bn*HWn);
        float mu = ss[0]*inv;
        float var = ss2[0]*inv - mu*mu;
        g_mu[c] = mu;
        g_istd[c] = rsqrtf(var + 1e-5f);
    }
}

__global__ void bn_apply_k(const float* __restrict__ x,
                           const float* __restrict__ gam, const float* __restrict__ bet,
                           float* __restrict__ out) {
    int hw = blockIdx.x*256 + threadIdx.x;
    int c = blockIdx.y, b = blockIdx.z;
    size_t i = ((size_t)(b*Cn + c))*HWn + hw;
    float zn = (g_z[i] - g_mu[c]) * g_istd[c] * gam[c] + bet[c];
    out[i] = fmaxf(zn + x[i], 0.f);
}

// ------------------------- launch -------------------------------------------
extern "C" void kernel_launch(void* const* d_in, const int* in_sizes, int n_in,
                              void* d_out, int out_size) {
    const float* x     = (const float*)d_in[0];
    const float* fdh_w = (const float*)d_in[1];
    const float* fdh_b = (const float*)d_in[2];
    const float* fdw_w = (const float*)d_in[3];
    const float* fdw_b = (const float*)d_in[4];
    const float* cp1_w = (const float*)d_in[5];
    const float* cp1_b = (const float*)d_in[6];
    const float* cp2_w = (const float*)d_in[7];
    const float* cp2_b = (const float*)d_in[8];
    const float* sdh_w = (const float*)d_in[9];
    const float* sdh_b = (const float*)d_in[10];
    const float* sdw_w = (const float*)d_in[11];
    const float* sdw_b = (const float*)d_in[12];
    const float* sr1_w = (const float*)d_in[13];
    const float* sr1_b = (const float*)d_in[14];
    const float* sr2_w = (const float*)d_in[15];
    const float* sr2_b = (const float*)d_in[16];
    const float* off_w = (const float*)d_in[17];
    const float* off_b = (const float*)d_in[18];
    const float* dg1_w = (const float*)d_in[19];
    const float* dg1_b = (const float*)d_in[20];
    const float* dg2_w = (const float*)d_in[21];
    const float* dg2_b = (const float*)d_in[22];
    const float* base_w = (const float*)d_in[23];
    const float* base_b = (const float*)d_in[24];
    const float* def_w = (const float*)d_in[25];
    const float* def_b = (const float*)d_in[26];
    const float* bn_g  = (const float*)d_in[27];
    const float* bn_b  = (const float*)d_in[28];
    float* out = (float*)d_out;

    float *p_fe, *p_fem, *p_aux, *p_ybase;
    cudaGetSymbolAddress((void**)&p_fe, g_fe);
    cudaGetSymbolAddress((void**)&p_fem, g_fem);
    cudaGetSymbolAddress((void**)&p_aux, g_aux);
    cudaGetSymbolAddress((void**)&p_ybase, g_ybase);

    const int FFT_SMEM  = 36104 * 4;         // 144416 B
    const int FREQ_SMEM = (128*132 + 128*136) * 4;  // 137216 B
    const int DEF_SMEM  = 23040 * 4;         // 92160 B
    const int C96_SMEM  = 8*96*9*8;          // 55296 B
    const int C68_SMEM  = 8*68*9*8;          // 39168 B
    cudaFuncSetAttribute(fft2d_k, cudaFuncAttributeMaxDynamicSharedMemorySize, FFT_SMEM);
    cudaFuncSetAttribute(freq_fused_k, cudaFuncAttributeMaxDynamicSharedMemorySize, FREQ_SMEM);
    cudaFuncSetAttribute(deform_combine_k, cudaFuncAttributeMaxDynamicSharedMemorySize, DEF_SMEM);
    cudaFuncSetAttribute(conv3x3_k<Cn,AUXn,96,false>, cudaFuncAttributeMaxDynamicSharedMemorySize, C96_SMEM);
    cudaFuncSetAttribute(convoffdg_k, cudaFuncAttributeMaxDynamicSharedMemorySize, C68_SMEM);

    prep_tw_k<<<1, 128>>>();
    prep_defw_k<<<CDIV(41472,256), 256>>>(def_w, 0, 41472);
    prep_defw_k<<<CDIV(41472,256), 256>>>(def_w, 41472, 82944);
    // ---- FFT(x) -> mag, fe ----   (4th launch: profiled)
    fft2d_k<<<dim3(Cn, Bn), 512, FFT_SMEM>>>(x, Cn);
    chan_mean_k<<<dim3(Hn, Bn), 160>>>(p_fe);
    // ---- freq branch ----
    freq_fused_k<<<dim3(Cn, Bn), 512, FREQ_SMEM>>>(fdh_w, fdh_b, fdw_w, fdw_b);
    ca_mlp_k<<<Bn, 96>>>(cp1_w, cp1_b, cp2_w, cp2_b);
    // ---- spatial branch ----
    spatial_in_k<<<dim3(Hn, Bn), 256>>>(x);
    dwsp_h_k<<<CDIV(Bn*3*HWn,256), 256>>>(sdh_w, sdh_b);
    dwsp_w_k<<<CDIV(Bn*3*HWn,256), 256>>>(sdw_w, sdw_b);
    sr_k<<<CDIV(Bn*HWn,256), 256>>>(sr1_w, sr1_b, sr2_w, sr2_b);
    ymul_k<<<dim3(HWn/256, Cn, Bn), 256>>>(x);
    // ---- FFT(y) -> mag, fem ----
    fft2d_k<<<dim3(Cn, Bn), 512, FFT_SMEM>>>(p_aux, AUXn);
    chan_mean_k<<<dim3(Hn, Bn), 160>>>(p_fem);
    auxmisc_k<<<dim3(Hn, Bn), 256>>>();
    // ---- convs ----
    convoffdg_k<<<1024, 256, C68_SMEM>>>(off_w, off_b, dg1_w, dg1_b, dg2_w, dg2_b);
    conv3x3_k<Cn,AUXn,96,false><<<1024, 256, C96_SMEM>>>(p_aux, base_w, base_b, p_ybase);
    // ---- deformable ----
    deform_combine_k<<<1024, 256, DEF_SMEM>>>(def_b);
    // ---- BN + residual relu ----
    bn_stats_k<<<Cn, 256>>>();
    bn_apply_k<<<dim3(HWn/256, Cn, Bn), 256>>>(x, bn_g, bn_b, out);
}

// round 6
// speedup vs baseline: 1.2129x; 1.0093x over previous
#include <cuda_runtime.h>
#include <math.h>

#define Bn 2
#define Cn 96
#define Hn 128
#define Wn 256
#define WFn 129
#define HWn (Hn*Wn)
#define AUXn 101
#define MIDn 24
#define DMIDn 50
#define NTOT (Bn*Cn*HWn)
#define NF (Bn*Cn*Hn*WFn)
#define CDIV(a,b) (((a)+(b)-1)/(b))

typedef unsigned long long u64;

__device__ __forceinline__ u64 ffma2(u64 a, u64 b, u64 c) {
    u64 d;
    asm("fma.rn.f32x2 %0, %1, %2, %3;" : "=l"(d) : "l"(a), "l"(b), "l"(c));
    return d;
}
__device__ __forceinline__ float2 unpack2(u64 v) {
    float2 d; asm("mov.b64 {%0, %1}, %2;" : "=f"(d.x), "=f"(d.y) : "l"(v)); return d;
}

// ------------------------- scratch (static device memory) -------------------
static __device__ float2 g_tw[128];
static __device__ float2 g_fft[(size_t)NF];
static __device__ float g_mag[NF];
static __device__ float g_fe[Bn*Hn*WFn];
static __device__ float g_fem[Bn*Hn*WFn];
static __device__ float g_gvec[Bn*3*Cn];
static __device__ float g_ca[Bn*Cn];
static __device__ float g_s0[Bn*3*HWn];
static __device__ float g_s1[Bn*3*HWn];
static __device__ float g_sa[Bn*HWn];
static __device__ float g_aux[(size_t)Bn*AUXn*HWn];
static __device__ float g_offb[Bn*18*HWn];
static __device__ float g_gate[Bn*HWn];
static __device__ float g_ybase[NTOT];
static __device__ float g_z[NTOT];
static __device__ float g_defwt[9*96*96];
static __device__ float g_mu[Cn];
static __device__ float g_istd[Cn];

// ------------------------- prep (3 tiny launches) ---------------------------
__global__ void prep_tw_k() {
    int j = threadIdx.x;           // 128
    float ang = -6.2831853071795864f * (float)j / 256.f;
    float s, c; sincosf(ang, &s, &c);
    g_tw[j] = make_float2(c, s);
}
__global__ void prep_defw_k(const float* __restrict__ defw, int i0, int i1) {
    int i = i0 + blockIdx.x*256 + threadIdx.x;
    if (i >= i1) return;
    int o = i % 96; int c = (i / 96) % 96; int t = i / (96*96);
    g_defwt[i] = defw[((size_t)o*96 + c)*9 + t];
}

// ------------------------- FFT kernels (split, high-parallel) ---------------
// Two real rows packed into one 256-pt complex FFT; unpack to two spectra.
__global__ void fft_rows_k(const float* __restrict__ in, int cstride) {
    __shared__ float re[256], im[256];
    __shared__ float2 tws[128];
    int h0 = blockIdx.x * 2;
    int c = blockIdx.y, b = blockIdx.z;
    const float* r0 = in + ((size_t)(b*cstride + c)*Hn + h0)*Wn;
    const float* r1 = r0 + Wn;
    int tid = threadIdx.x;                // 128
    tws[tid] = g_tw[tid];
    for (int i = tid; i < 256; i += 128) {
        int j = __brev((unsigned)i) >> 24;
        re[j] = r0[i];
        im[j] = r1[i];
    }
    __syncthreads();
    #pragma unroll
    for (int s = 1; s <= 8; s++) {
        int half = 1 << (s - 1);
        int i = tid;
        int off = i & (half - 1);
        int a = ((i >> (s - 1)) << s) + off;
        int bb = a + half;
        float2 tw = tws[off << (8 - s)];
        float br = re[bb], bi = im[bb];
        float ar = re[a],  ai = im[a];
        float xr = br*tw.x - bi*tw.y;
        float xi = br*tw.y + bi*tw.x;
        re[a] = ar + xr; im[a] = ai + xi;
        re[bb] = ar - xr; im[bb] = ai - xi;
        __syncthreads();
    }
    float2* out0 = g_fft + ((size_t)(b*Cn + c)*Hn + h0)*WFn;
    float2* out1 = out0 + WFn;
    int k = tid;
    float zr = re[k], zi = im[k];
    int km = (256 - k) & 255;
    float wr = re[km], wi = im[km];
    out0[k] = make_float2(0.5f*(zr + wr), 0.5f*(zi - wi));
    out1[k] = make_float2(0.5f*(zi + wi), -0.5f*(zr - wr));
    if (tid == 0) {
        out0[128] = make_float2(re[128], 0.f);
        out1[128] = make_float2(im[128], 0.f);
    }
}

// 128-pt FFT down columns, 16 columns per block (coalesced), |.| * 1/sqrt(HW)
__global__ void fft_cols_k() {
    __shared__ float cre[16][129];
    __shared__ float cim[16][129];
    __shared__ float2 tws[128];
    int kb = blockIdx.x;                  // 0..8
    int c = blockIdx.y, b = blockIdx.z;
    int bc = b*Cn + c;
    int k0 = kb * 16;
    int ncols = (kb < 8) ? 16 : 1;
    int lg = (kb < 8) ? 4 : 0;
    int tid = threadIdx.x;                // 128
    tws[tid] = g_tw[tid];
    int kk = tid & 15, ht = tid >> 4;
    const float2* src = g_fft + (size_t)bc*Hn*WFn;
    for (int hb = 0; hb < 16; hb++) {
        int h = hb*8 + ht;
        if (kk < ncols) {
            float2 v = src[(size_t)h*WFn + k0 + kk];
            int j = __brev((unsigned)h) >> 25;
            cre[kk][j] = v.x; cim[kk][j] = v.y;
        }
    }
    __syncthreads();
    #pragma unroll
    for (int s = 1; s <= 7; s++) {
        int half = 1 << (s - 1);
        int total = ncols << 6;
        for (int e = tid; e < total; e += 128) {
            int col = e & (ncols - 1);
            int i = e >> lg;
            int off = i & (half - 1);
            int a = ((i >> (s - 1)) << s) + off;
            int bb = a + half;
            float2 tw = tws[off << (8 - s)];
            float br = cre[col][bb], bi = cim[col][bb];
            float ar = cre[col][a],  ai = cim[col][a];
            float xr = br*tw.x - bi*tw.y;
            float xi = br*tw.y + bi*tw.x;
            cre[col][a] = ar + xr; cim[col][a] = ai + xi;
            cre[col][bb] = ar - xr; cim[col][bb] = ai - xi;
        }
        __syncthreads();
    }
    const float sc = 0.0055242717280199026f;  // 1/sqrt(128*256)
    float* dst = g_mag + (size_t)bc*Hn*WFn;
    int total = ncols << 7;
    for (int e = tid; e < total; e += 128) {
        int col = e & (ncols - 1);
        int h = e >> lg;
        float r = cre[col][h], m = cim[col][h];
        dst[(size_t)h*WFn + k0 + col] = sqrtf(r*r + m*m) * sc;
    }
}

// mean over channels of g_mag -> out[b][h][k]
__global__ void chan_mean_k(float* __restrict__ out) {
    int h = blockIdx.x, b = blockIdx.y;
    for (int k = threadIdx.x; k < WFn; k += 160) {
        float s = 0.f;
        const float* p = g_mag + ((size_t)(b*Cn)*Hn + h)*WFn + k;
        #pragma unroll 4
        for (int c = 0; c < Cn; c++) s += p[(size_t)c*Hn*WFn];
        out[(size_t)(b*Hn + h)*WFn + k] = s * (1.f/Cn);
    }
}

// --------- fused freq branch: direct 49-tap separable stencil + pools -------
__global__ __launch_bounds__(512)
void freq_fused_k(const float* __restrict__ w7h, const float* __restrict__ b7h,
                  const float* __restrict__ w7w, const float* __restrict__ b7w) {
    extern __shared__ float A[];          // [128][132]
    __shared__ float S[4][132];
    __shared__ float bins[21];
    int c = blockIdx.x, b = blockIdx.y;
    int tid = threadIdx.x;
    const float* mp = g_mag + (size_t)(b*Cn + c)*Hn*WFn;
    for (int e = tid; e < 128*129; e += 512) {
        int h = e / 129, k = e - h*129;
        A[h*132 + k] = mp[e];
    }
    float wh[7], ww[7];
    #pragma unroll
    for (int d = 0; d < 7; d++) { wh[d] = w7h[c*7+d]; ww[d] = w7w[c*7+d]; }
    float bh = b7h[c], bw = b7w[c];
    __syncthreads();
    // deterministic band sums: one (band,k) task per thread slot
    for (int t = tid; t < 4*129; t += 512) {
        int band = t / 129, k = t - band*129;
        float acc = 0.f;
        for (int hh = 0; hh < 32; hh++) {
            int h = band*32 + hh;
            float t2 = bw;
            #pragma unroll
            for (int d = 0; d < 7; d++) {
                int kk = k + d - 3;
                if (kk >= 0 && kk < 129) {
                    float t1 = bh;
                    #pragma unroll
                    for (int e = 0; e < 7; e++) {
                        int h2 = h + e - 3;
                        if (h2 >= 0 && h2 < 128) t1 += wh[e]*A[h2*132 + kk];
                    }
                    t2 += ww[d]*t1;
                }
            }
            acc += t2;
        }
        S[band][k] = acc;
    }
    __syncthreads();
    if (tid < 16) {
        int i = tid >> 2, j = tid & 3;
        int ws = (j*WFn)/4, we = ((j+1)*WFn + 3)/4;
        float s = 0;
        for (int k = ws; k < we; k++) s += S[i][k];
        bins[tid] = s / (32.f * (float)(we - ws));
    } else if (tid < 20) {
        int t2 = tid - 16; int i = t2 >> 1, j = t2 & 1;
        int ws = (j*WFn)/2, we = ((j+1)*WFn + 1)/2;
        float s = 0;
        for (int k = ws; k < we; k++) s += S[2*i][k] + S[2*i+1][k];
        bins[tid] = s / (64.f * (float)(we - ws));
    } else if (tid == 20) {
        float s = 0;
        for (int k = 0; k < WFn; k++) s += S[0][k]+S[1][k]+S[2][k]+S[3][k];
        bins[20] = s / (128.f*129.f);
    }
    __syncthreads();
    if (tid == 0) {
        float g2 = bins[16]+bins[17]+bins[18]+bins[19];
        float g3 = 0;
        for (int m = 0; m < 16; m++) g3 += bins[m];
        g_gvec[b*288 + c]        = bins[20];
        g_gvec[b*288 + Cn + c]   = g2 * 0.25f;
        g_gvec[b*288 + 2*Cn + c] = g3 * 0.0625f;
    }
}

// ------------------------- channel-attention MLP ----------------------------
__global__ void ca_mlp_k(const float* __restrict__ w1, const float* __restrict__ b1,
                         const float* __restrict__ w2, const float* __restrict__ b2) {
    __shared__ float gs[288], hs[MIDn];
    int b = blockIdx.x, tid = threadIdx.x;   // 96 threads
    for (int i = tid; i < 288; i += 96) gs[i] = g_gvec[b*288 + i];
    __syncthreads();
    if (tid < MIDn) {
        float a = b1[tid];
        for (int k = 0; k < 288; k++) a += w1[tid*288 + k]*gs[k];
        hs[tid] = fmaxf(a, 0.f);
    }
    __syncthreads();
    float a = b2[tid];
    #pragma unroll
    for (int m = 0; m < MIDn; m++) a += w2[tid*MIDn + m]*hs[m];
    g_ca[b*Cn + tid] = 1.f/(1.f + expf(-a));
}

// ------------------------- spatial branch -----------------------------------
__global__ void spatial_in_k(const float* __restrict__ x) {
    int h = blockIdx.x, b = blockIdx.y;
    int w = threadIdx.x;                  // 256
    int hw = h*Wn + w;
    const float* xp = x + (size_t)b*Cn*HWn + hw;
    float s = 0.f, s2 = 0.f;
    #pragma unroll 4
    for (int c = 0; c < Cn; c++) { float v = xp[(size_t)c*HWn]; s += v; s2 += v*v; }
    float mean = s * (1.f/Cn);
    float l2 = sqrtf(s2 * (1.f/Cn) + 1e-6f);
    float src = ((float)w + 0.5f)*(129.f/256.f) - 0.5f;
    float f0 = floorf(src); int i0 = (int)f0; float fr = src - f0;
    int ia = min(max(i0, 0), WFn-1), ib = min(max(i0+1, 0), WFn-1);
    const float* fp = g_fe + (size_t)(b*Hn + h)*WFn;
    float fv = fp[ia]*(1.f - fr) + fp[ib]*fr;
    g_s0[((size_t)(b*3+0))*HWn + hw] = mean;
    g_s0[((size_t)(b*3+1))*HWn + hw] = l2;
    g_s0[((size_t)(b*3+2))*HWn + hw] = fv;
}

__global__ void dwsp_h_k(const float* __restrict__ w15, const float* __restrict__ b15) {
    int i = blockIdx.x*blockDim.x + threadIdx.x;
    if (i >= Bn*3*HWn) return;
    int w = i & (Wn-1); int t = i >> 8; int h = t & (Hn-1); int bc = t >> 7; int ch = bc % 3;
    float a = b15[ch];
    #pragma unroll
    for (int d = 0; d < 15; d++) {
        int hh = h + d - 7;
        if (hh >= 0 && hh < Hn) a += w15[ch*15+d]*g_s0[((size_t)bc*Hn + hh)*Wn + w];
    }
    g_s1[i] = a;
}

__global__ void dwsp_w_k(const float* __restrict__ w15, const float* __restrict__ b15) {
    int i = blockIdx.x*blockDim.x + threadIdx.x;
    if (i >= Bn*3*HWn) return;
    int w = i & (Wn-1); int t = i >> 8; int bc = t >> 7; int ch = bc % 3;
    float a = b15[ch];
    #pragma unroll
    for (int d = 0; d < 15; d++) {
        int ww = w + d - 7;
        if (ww >= 0 && ww < Wn) a += w15[ch*15+d]*g_s1[(size_t)t*Wn + ww];
    }
    g_s0[i] = a;
}

__global__ void sr_k(const float* __restrict__ sr1w, const float* __restrict__ sr1b,
                     const float* __restrict__ sr2w, const float* __restrict__ sr2b) {
    int i = blockIdx.x*blockDim.x + threadIdx.x;
    if (i >= Bn*HWn) return;
    int b = i >> 15; int hw = i & (HWn-1); int h = hw >> 8; int w = hw & (Wn-1);
    float acc = sr2b[0];
    #pragma unroll
    for (int g3 = 0; g3 < 3; g3++) {
        float v = sr1b[g3];
        #pragma unroll
        for (int ky = 0; ky < 3; ky++) {
            int hh = h + ky - 1; if (hh < 0 || hh >= Hn) continue;
            #pragma unroll
            for (int kx = 0; kx < 3; kx++) {
                int ww = w + kx - 1; if (ww < 0 || ww >= Wn) continue;
                v += sr1w[g3*9 + ky*3 + kx]*g_s0[((size_t)(b*3+g3)*Hn + hh)*Wn + ww];
            }
        }
        acc += sr2w[g3]*fmaxf(v, 0.f);
    }
    g_sa[i] = 1.f/(1.f + expf(-acc));
}

// y = x*ca*sa written directly into aux channels [0..95]
__global__ void ymul_k(const float* __restrict__ x) {
    int hw = blockIdx.x*256 + threadIdx.x;
    int c = blockIdx.y, b = blockIdx.z;
    float v = x[((size_t)(b*Cn + c))*HWn + hw] * g_ca[b*Cn + c] * g_sa[(size_t)b*HWn + hw];
    g_aux[((size_t)(b*AUXn + c))*HWn + hw] = v;
}

__global__ void auxmisc_k() {
    int h = blockIdx.x, b = blockIdx.y;
    int w = threadIdx.x;                 // 256
    int hw = h*Wn + w;
    float theta = -3.14159265358979324f + (float)w * (6.2831853071795864f/255.f);
    float phi   = -1.57079632679489662f + (float)h * (3.14159265358979324f/127.f);
    size_t base = (size_t)b*AUXn*HWn + hw;
    g_aux[base + (size_t)96*HWn] = sinf(theta);
    g_aux[base + (size_t)97*HWn] = cosf(theta);
    g_aux[base + (size_t)98*HWn] = sinf(phi);
    g_aux[base + (size_t)99*HWn] = cosf(phi);
    float src = ((float)w + 0.5f)*(129.f/256.f) - 0.5f;
    float f0 = floorf(src); int i0 = (int)f0; float fr = src - f0;
    int ia = min(max(i0, 0), WFn-1), ib = min(max(i0+1, 0), WFn-1);
    const float* fp = g_fem + (size_t)(b*Hn + h)*WFn;
    g_aux[base + (size_t)100*HWn] = fp[ia]*(1.f - fr) + fp[ib]*fr;
}

// ------------- tiled 3x3 conv: swizzled pair-tile + packed weights ----------
template<int CIN, int CSTRIDE, int COUT, bool RELU>
__global__ __launch_bounds__(256)
void conv3x3_k(const float* __restrict__ in, const float* __restrict__ wgt,
               const float* __restrict__ bias, float* __restrict__ out) {
    constexpr int NO = (COUT + 31) / 32;
    constexpr int CB = 8;
    __shared__ float2 tile2[CB][3][66];
    extern __shared__ float2 wdyn[];          // [CB][COUT*9] packed (w,w)
    int bx = blockIdx.x;
    int seg = bx & 3; int h = (bx >> 2) & (Hn - 1); int b = bx >> 9;
    int w0 = seg * 64;
    int tid = threadIdx.x;
    int pg = tid & 7, og = tid >> 3;
    u64 pacc[NO][4];
    #pragma unroll
    for (int k = 0; k < NO; k++)
        #pragma unroll
        for (int q = 0; q < 4; q++) pacc[k][q] = 0ull;
    const float* inb = in + (size_t)b*CSTRIDE*HWn;
    int pv8idx = (pg == 7) ? 64 : (pg + 1);
    for (int c0 = 0; c0 < CIN; c0 += CB) {
        for (int m = tid; m < CB*3*65; m += 256) {
            int ci = m / 195; int rem = m - ci*195; int r = rem / 65; int p = rem - r*65;
            int l = (p < 64) ? (((p & 7) << 3) | (p >> 3)) : 64;
            int hh = h + r - 1, ww = w0 + l - 1;
            float v0 = 0.f, v1 = 0.f;
            if (c0 + ci < CIN && hh >= 0 && hh < Hn) {
                const float* rowp = inb + (size_t)(c0 + ci)*HWn + (size_t)hh*Wn;
                if (ww >= 0 && ww < Wn) v0 = rowp[ww];
                if (ww + 1 >= 0 && ww + 1 < Wn) v1 = rowp[ww + 1];
            }
            tile2[ci][r][p] = make_float2(v0, v1);
        }
        for (int m = tid; m < CB*COUT*9; m += 256) {
            int ci = m / (COUT*9); int rem = m - ci*(COUT*9);
            float v = 0.f;
            if (c0 + ci < CIN) {
                int o = rem / 9, j = rem - o*9;
                v = wgt[((size_t)o*CIN + c0 + ci)*9 + j];
            }
            wdyn[ci*(COUT*9) + rem] = make_float2(v, v);
        }
        __syncthreads();
        #pragma unroll 2
        for (int ci = 0; ci < CB; ci++) {
            #pragma unroll
            for (int r = 0; r < 3; r++) {
                const float2* trow = tile2[ci][r];
                u64 pv[9];
                #pragma unroll
                for (int j = 0; j < 8; j++) pv[j] = *(const u64*)&trow[j*8 + pg];
                pv[8] = *(const u64*)&trow[pv8idx];
                #pragma unroll
                for (int k = 0; k < NO; k++) {
                    int o = og + 32*k;
                    if ((COUT & 31) && o >= COUT) break;
                    const u64* wp = (const u64*)&wdyn[ci*(COUT*9) + o*9 + r*3];
                    u64 wb0 = wp[0], wb1 = wp[1], wb2 = wp[2];
                    #pragma unroll
                    for (int q = 0; q < 4; q++) {
                        pacc[k][q] = ffma2(wb0, pv[2*q],   pacc[k][q]);
                        pacc[k][q] = ffma2(wb1, pv[2*q+1], pacc[k][q]);
                        pacc[k][q] = ffma2(wb2, pv[2*q+2], pacc[k][q]);
                    }
                }
            }
        }
        __syncthreads();
    }
    #pragma unroll
    for (int k = 0; k < NO; k++) {
        int o = og + 32*k;
        if ((COUT & 31) && o >= COUT) break;
        float bb = bias[o];
        float* op = out + ((size_t)(b*COUT + o))*HWn + h*Wn + w0 + pg*8;
        #pragma unroll
        for (int q = 0; q < 4; q++) {
            float2 f = unpack2(pacc[k][q]);
            float vx = f.x + bb, vy = f.y + bb;
            if (RELU) { vx = fmaxf(vx, 0.f); vy = fmaxf(vy, 0.f); }
            op[2*q] = vx; op[2*q+1] = vy;
        }
    }
}

// ------------- merged offset(18) + dg1(50) conv with fused gate head --------
__global__ __launch_bounds__(256)
void convoffdg_k(const float* __restrict__ offw, const float* __restrict__ offbias,
                 const float* __restrict__ dg1w, const float* __restrict__ dg1b,
                 const float* __restrict__ dg2w, const float* __restrict__ dg2b) {
    constexpr int COUT = 68;
    constexpr int NO = 3;
    constexpr int CB = 8;
    __shared__ float2 tile2[CB][3][66];
    __shared__ float sgate[32][64];
    extern __shared__ float2 wdyn[];          // [CB][COUT*9]
    int bx = blockIdx.x;
    int seg = bx & 3; int h = (bx >> 2) & (Hn - 1); int b = bx >> 9;
    int w0 = seg * 64;
    int tid = threadIdx.x;
    int pg = tid & 7, og = tid >> 3;
    u64 pacc[NO][4];
    #pragma unroll
    for (int k = 0; k < NO; k++)
        #pragma unroll
        for (int q = 0; q < 4; q++) pacc[k][q] = 0ull;
    const float* inb = g_aux + (size_t)b*AUXn*HWn;
    int pv8idx = (pg == 7) ? 64 : (pg + 1);
    for (int c0 = 0; c0 < AUXn; c0 += CB) {
        for (int m = tid; m < CB*3*65; m += 256) {
            int ci = m / 195; int rem = m - ci*195; int r = rem / 65; int p = rem - r*65;
            int l = (p < 64) ? (((p & 7) << 3) | (p >> 3)) : 64;
            int hh = h + r - 1, ww = w0 + l - 1;
            float v0 = 0.f, v1 = 0.f;
            if (c0 + ci < AUXn && hh >= 0 && hh < Hn) {
                const float* rowp = inb + (size_t)(c0 + ci)*HWn + (size_t)hh*Wn;
                if (ww >= 0 && ww < Wn) v0 = rowp[ww];
                if (ww + 1 >= 0 && ww + 1 < Wn) v1 = rowp[ww + 1];
            }
            tile2[ci][r][p] = make_float2(v0, v1);
        }
        for (int m = tid; m < CB*COUT*9; m += 256) {
            int ci = m / (COUT*9); int rem = m - ci*(COUT*9);
            float v = 0.f;
            if (c0 + ci < AUXn) {
                int o = rem / 9, j = rem - o*9;
                if (o < 18) v = offw[((size_t)o*AUXn + c0 + ci)*9 + j];
                else        v = dg1w[((size_t)(o-18)*AUXn + c0 + ci)*9 + j];
            }
            wdyn[ci*(COUT*9) + rem] = make_float2(v, v);
        }
        __syncthreads();
        #pragma unroll 2
        for (int ci = 0; ci < CB; ci++) {
            #pragma unroll
            for (int r = 0; r < 3; r++) {
                const float2* trow = tile2[ci][r];
                u64 pv[9];
                #pragma unroll
                for (int j = 0; j < 8; j++) pv[j] = *(const u64*)&trow[j*8 + pg];
                pv[8] = *(const u64*)&trow[pv8idx];
                #pragma unroll
                for (int k = 0; k < NO; k++) {
                    int o = og + 32*k;
                    if (o >= COUT) break;
                    const u64* wp = (const u64*)&wdyn[ci*(COUT*9) + o*9 + r*3];
                    u64 wb0 = wp[0], wb1 = wp[1], wb2 = wp[2];
                    #pragma unroll
                    for (int q = 0; q < 4; q++) {
                        pacc[k][q] = ffma2(wb0, pv[2*q],   pacc[k][q]);
                        pacc[k][q] = ffma2(wb1, pv[2*q+1], pacc[k][q]);
                        pacc[k][q] = ffma2(wb2, pv[2*q+2], pacc[k][q]);
                    }
                }
            }
        }
        __syncthreads();
    }
    float part[8];
    #pragma unroll
    for (int p = 0; p < 8; p++) part[p] = 0.f;
    #pragma unroll
    for (int k = 0; k < NO; k++) {
        int o = og + 32*k;
        if (o >= COUT) break;
        if (o < 18) {
            float bb = offbias[o];
            float* op = g_offb + ((size_t)(b*18 + o))*HWn + h*Wn + w0 + pg*8;
            #pragma unroll
            for (int q = 0; q < 4; q++) {
                float2 f = unpack2(pacc[k][q]);
                op[2*q] = f.x + bb; op[2*q+1] = f.y + bb;
            }
        } else {
            float bb = dg1b[o-18];
            float wv = dg2w[o-18];
            #pragma unroll
            for (int q = 0; q < 4; q++) {
                float2 f = unpack2(pacc[k][q]);
                part[2*q]   += wv * fmaxf(f.x + bb, 0.f);
                part[2*q+1] += wv * fmaxf(f.y + bb, 0.f);
            }
        }
    }
    #pragma unroll
    for (int p = 0; p < 8; p++) sgate[og][pg*8 + p] = part[p];
    __syncthreads();
    if (tid < 64) {
        float s = dg2b[0];
        #pragma unroll 8
        for (int o2 = 0; o2 < 32; o2++) s += sgate[o2][tid];
        g_gate[(size_t)b*HWn + h*Wn + w0 + tid] = 1.f/(1.f + expf(-s));
    }
}

// ------------------------- deformable sampling + GEMM + combine -------------
__global__ __launch_bounds__(256)
void deform_combine_k(const float* __restrict__ defb) {
    extern __shared__ float dsm[];
    float2* samp2 = (float2*)dsm;                    // 2304 float2
    float2* wsh2  = (float2*)(dsm + 4608);           // 6912 float2
    float*  s_w   = dsm + 18432;                     // 2304
    int*    s_idx = (int*)(dsm + 20736);             // 2304
    int bx = blockIdx.x;
    int seg = bx & 3; int h = (bx >> 2) & (Hn - 1); int b = bx >> 9;
    int w0 = seg * 64;
    int tid = threadIdx.x;
    int pg = tid & 7, og = tid >> 3;

    for (int e = tid; e < 576; e += 256) {
        int t9 = e >> 6, p = e & 63;
        int wpx = w0 + p;
        size_t obase = ((size_t)b*18)*HWn + (size_t)h*Wn + wpx;
        float ox = g_offb[obase + (size_t)(2*t9)*HWn];
        float oy = g_offb[obase + (size_t)(2*t9+1)*HWn];
        float px = (float)wpx + ox;
        float py = (float)h + oy;
        float x0 = floorf(px), y0 = floorf(py);
        float fx = px - x0, fy = py - y0;
        #pragma unroll
        for (int j = 0; j < 4; j++) {
            float xj = x0 + (float)(j & 1);
            float yj = y0 + (float)(j >> 1);
            float valid = (xj >= 0.f && xj <= 255.f && yj >= 0.f && yj <= 127.f) ? 1.f : 0.f;
            float xc = fminf(fmaxf(xj, 0.f), 255.f);
            float yc = fminf(fmaxf(yj, 0.f), 127.f);
            s_idx[(t9*64 + p)*4 + j] = (int)yc * Wn + (int)xc;
            float wx = (j & 1) ? fx : (1.f - fx);
            float wy = (j >> 1) ? fy : (1.f - fy);
            s_w[(t9*64 + p)*4 + j] = wx * wy * valid;
        }
    }

    u64 pacc[3][4];
    #pragma unroll
    for (int k = 0; k < 3; k++)
        #pragma unroll
        for (int q = 0; q < 4; q++) pacc[k][q] = 0ull;

    for (int c0 = 0; c0 < 96; c0 += 8) {
        __syncthreads();
        for (int e = tid; e < 2304; e += 256) {
            int t9 = e >> 8; int rem = e & 255; int c = rem >> 5; int P = rem & 31;
            int p0 = 2*P;
            const float* yp = g_aux + ((size_t)(b*AUXn + c0 + c))*HWn;
            const int* i0 = &s_idx[(t9*64 + p0)*4];
            const float* q0 = &s_w[(t9*64 + p0)*4];
            float v0 = q0[0]*yp[i0[0]] + q0[1]*yp[i0[1]] + q0[2]*yp[i0[2]] + q0[3]*yp[i0[3]];
            const int* i1 = i0 + 4; const float* q1 = q0 + 4;
            float v1 = q1[0]*yp[i1[0]] + q1[1]*yp[i1[1]] + q1[2]*yp[i1[2]] + q1[3]*yp[i1[3]];
            samp2[(t9*8 + c)*32 + (((P & 3) << 3) | (P >> 2))] = make_float2(v0, v1);
        }
        for (int e = tid; e < 6912; e += 256) {
            int t9 = e / 768; int rem = e - t9*768;
            int c = rem / 96; int o = rem - c*96;
            float v = g_defwt[((size_t)(t9*96) + c0 + c)*96 + o];
            wsh2[e] = make_float2(v, v);
        }
        __syncthreads();
        #pragma unroll 3
        for (int t9 = 0; t9 < 9; t9++) {
            #pragma unroll
            for (int c = 0; c < 8; c++) {
                const float2* sp = &samp2[(t9*8 + c)*32];
                u64 s0 = *(const u64*)&sp[0*8 + pg];
                u64 s1 = *(const u64*)&sp[1*8 + pg];
                u64 s2 = *(const u64*)&sp[2*8 + pg];
                u64 s3 = *(const u64*)&sp[3*8 + pg];
                const float2* wb = &wsh2[(t9*8 + c)*96];
                #pragma unroll
                for (int k = 0; k < 3; k++) {
                    u64 wp2 = *(const u64*)&wb[og + 32*k];
                    pacc[k][0] = ffma2(wp2, s0, pacc[k][0]);
                    pacc[k][1] = ffma2(wp2, s1, pacc[k][1]);
                    pacc[k][2] = ffma2(wp2, s2, pacc[k][2]);
                    pacc[k][3] = ffma2(wp2, s3, pacc[k][3]);
                }
            }
        }
    }
    #pragma unroll
    for (int k = 0; k < 3; k++) {
        int o = og + 32*k;
        float bb = defb[o];
        size_t rowoff = (size_t)h*Wn + w0 + pg*8;
        float* zp = g_z + ((size_t)(b*Cn + o))*HWn + rowoff;
        const float* yb = g_ybase + ((size_t)(b*Cn + o))*HWn + rowoff;
        const float* gp = g_gate + (size_t)b*HWn + rowoff;
        #pragma unroll
        for (int q = 0; q < 4; q++) {
            float2 f = unpack2(pacc[k][q]);
            float g0 = gp[2*q], g1 = gp[2*q+1];
            zp[2*q]   = (1.f - g0)*yb[2*q]   + g0*(f.x + bb);
            zp[2*q+1] = (1.f - g1)*yb[2*q+1] + g1*(f.y + bb);
        }
    }
}

// ------------------------- batchnorm ----------------------------------------
__global__ void bn_stats_k() {
    __shared__ float ss[256], ss2[256];
    int c = blockIdx.x, tid = threadIdx.x;
    float s = 0.f, s2 = 0.f;
    for (int i = tid; i < Bn*HWn; i += 256) {
        int b = i >> 15, hw = i & (HWn-1);
        float v = g_z[((size_t)(b*Cn + c))*HWn + hw];
        s += v; s2 += v*v;
    }
    ss[tid] = s; ss2[tid] = s2;
    __syncthreads();
    for (int st = 128; st > 0; st >>= 1) {
        if (tid < st) { ss[tid] += ss[tid+st]; ss2[tid] += ss2[tid+st]; }
        __syncthreads();
    }
    if (tid == 0) {
        float inv = 1.f/(float)(Bn*HWn);
        float mu = ss[0]*inv;
        float var = ss2[0]*inv - mu*mu;
        g_mu[c] = mu;
        g_istd[c] = rsqrtf(var + 1e-5f);
    }
}

__global__ void bn_apply_k(const float* __restrict__ x,
                           const float* __restrict__ gam, const float* __restrict__ bet,
                           float* __restrict__ out) {
    int hw = blockIdx.x*256 + threadIdx.x;
    int c = blockIdx.y, b = blockIdx.z;
    size_t i = ((size_t)(b*Cn + c))*HWn + hw;
    float zn = (g_z[i] - g_mu[c]) * g_istd[c] * gam[c] + bet[c];
    out[i] = fmaxf(zn + x[i], 0.f);
}

// ------------------------- launch -------------------------------------------
extern "C" void kernel_launch(void* const* d_in, const int* in_sizes, int n_in,
                              void* d_out, int out_size) {
    const float* x     = (const float*)d_in[0];
    const float* fdh_w = (const float*)d_in[1];
    const float* fdh_b = (const float*)d_in[2];
    const float* fdw_w = (const float*)d_in[3];
    const float* fdw_b = (const float*)d_in[4];
    const float* cp1_w = (const float*)d_in[5];
    const float* cp1_b = (const float*)d_in[6];
    const float* cp2_w = (const float*)d_in[7];
    const float* cp2_b = (const float*)d_in[8];
    const float* sdh_w = (const float*)d_in[9];
    const float* sdh_b = (const float*)d_in[10];
    const float* sdw_w = (const float*)d_in[11];
    const float* sdw_b = (const float*)d_in[12];
    const float* sr1_w = (const float*)d_in[13];
    const float* sr1_b = (const float*)d_in[14];
    const float* sr2_w = (const float*)d_in[15];
    const float* sr2_b = (const float*)d_in[16];
    const float* off_w = (const float*)d_in[17];
    const float* off_b = (const float*)d_in[18];
    const float* dg1_w = (const float*)d_in[19];
    const float* dg1_b = (const float*)d_in[20];
    const float* dg2_w = (const float*)d_in[21];
    const float* dg2_b = (const float*)d_in[22];
    const float* base_w = (const float*)d_in[23];
    const float* base_b = (const float*)d_in[24];
    const float* def_w = (const float*)d_in[25];
    const float* def_b = (const float*)d_in[26];
    const float* bn_g  = (const float*)d_in[27];
    const float* bn_b  = (const float*)d_in[28];
    float* out = (float*)d_out;

    float *p_fe, *p_fem, *p_aux, *p_ybase;
    cudaGetSymbolAddress((void**)&p_fe, g_fe);
    cudaGetSymbolAddress((void**)&p_fem, g_fem);
    cudaGetSymbolAddress((void**)&p_aux, g_aux);
    cudaGetSymbolAddress((void**)&p_ybase, g_ybase);

    const int FREQ_SMEM = 128*132*4;         // 67584 B
    const int DEF_SMEM  = 23040 * 4;         // 92160 B
    const int C96_SMEM  = 8*96*9*8;          // 55296 B
    const int C68_SMEM  = 8*68*9*8;          // 39168 B
    cudaFuncSetAttribute(freq_fused_k, cudaFuncAttributeMaxDynamicSharedMemorySize, FREQ_SMEM);
    cudaFuncSetAttribute(deform_combine_k, cudaFuncAttributeMaxDynamicSharedMemorySize, DEF_SMEM);
    cudaFuncSetAttribute(conv3x3_k<Cn,AUXn,96,false>, cudaFuncAttributeMaxDynamicSharedMemorySize, C96_SMEM);
    cudaFuncSetAttribute(convoffdg_k, cudaFuncAttributeMaxDynamicSharedMemorySize, C68_SMEM);

    prep_tw_k<<<1, 128>>>();
    prep_defw_k<<<CDIV(41472,256), 256>>>(def_w, 0, 41472);
    prep_defw_k<<<CDIV(41472,256), 256>>>(def_w, 41472, 82944);
    // ---- FFT(x) -> mag, fe ----   (4th launch: profiled)
    fft_rows_k<<<dim3(Hn/2, Cn, Bn), 128>>>(x, Cn);
    fft_cols_k<<<dim3(9, Cn, Bn), 128>>>();
    chan_mean_k<<<dim3(Hn, Bn), 160>>>(p_fe);
    // ---- freq branch ----
    freq_fused_k<<<dim3(Cn, Bn), 512, FREQ_SMEM>>>(fdh_w, fdh_b, fdw_w, fdw_b);
    ca_mlp_k<<<Bn, 96>>>(cp1_w, cp1_b, cp2_w, cp2_b);
    // ---- spatial branch ----
    spatial_in_k<<<dim3(Hn, Bn), 256>>>(x);
    dwsp_h_k<<<CDIV(Bn*3*HWn,256), 256>>>(sdh_w, sdh_b);
    dwsp_w_k<<<CDIV(Bn*3*HWn,256), 256>>>(sdw_w, sdw_b);
    sr_k<<<CDIV(Bn*HWn,256), 256>>>(sr1_w, sr1_b, sr2_w, sr2_b);
    ymul_k<<<dim3(HWn/256, Cn, Bn), 256>>>(x);
    // ---- FFT(y) -> mag, fem ----
    fft_rows_k<<<dim3(Hn/2, Cn, Bn), 128>>>(p_aux, AUXn);
    fft_cols_k<<<dim3(9, Cn, Bn), 128>>>();
    chan_mean_k<<<dim3(Hn, Bn), 160>>>(p_fem);
    auxmisc_k<<<dim3(Hn, Bn), 256>>>();
    // ---- convs ----
    convoffdg_k<<<1024, 256, C68_SMEM>>>(off_w, off_b, dg1_w, dg1_b, dg2_w, dg2_b);
    conv3x3_k<Cn,AUXn,96,false><<<1024, 256, C96_SMEM>>>(p_aux, base_w, base_b, p_ybase);
    // ---- deformable ----
    deform_combine_k<<<1024, 256, DEF_SMEM>>>(def_b);
    // ---- BN + residual relu ----
    bn_stats_k<<<Cn, 256>>>();
    bn_apply_k<<<dim3(HWn/256, Cn, Bn), 256>>>(x, bn_g, bn_b, out);
}

// round 7
// speedup vs baseline: 1.2294x; 1.0136x over previous
#include <cuda_runtime.h>
#include <math.h>

#define Bn 2
#define Cn 96
#define Hn 128
#define Wn 256
#define WFn 129
#define HWn (Hn*Wn)
#define AUXn 101
#define MIDn 24
#define DMIDn 50
#define NTOT (Bn*Cn*HWn)
#define NF (Bn*Cn*Hn*WFn)
#define CDIV(a,b) (((a)+(b)-1)/(b))

typedef unsigned long long u64;

__device__ __forceinline__ u64 ffma2(u64 a, u64 b, u64 c) {
    u64 d;
    asm("fma.rn.f32x2 %0, %1, %2, %3;" : "=l"(d) : "l"(a), "l"(b), "l"(c));
    return d;
}
__device__ __forceinline__ float2 unpack2(u64 v) {
    float2 d; asm("mov.b64 {%0, %1}, %2;" : "=f"(d.x), "=f"(d.y) : "l"(v)); return d;
}

// ------------------------- scratch (static device memory) -------------------
static __device__ float2 g_tw[128];
static __device__ float2 g_fft[(size_t)NF];
static __device__ float g_mag[NF];
static __device__ float g_fe[Bn*Hn*WFn];
static __device__ float g_fem[Bn*Hn*WFn];
static __device__ float g_gvec[Bn*3*Cn];
static __device__ float g_ca[Bn*Cn];
static __device__ float g_s0[Bn*3*HWn];
static __device__ float g_sa[Bn*HWn];
static __device__ float g_aux[(size_t)Bn*AUXn*HWn];
static __device__ float g_offb[Bn*18*HWn];
static __device__ float g_gate[Bn*HWn];
static __device__ float g_ybase[NTOT];
static __device__ float g_z[NTOT];
static __device__ float g_defwt[9*96*96];
static __device__ float g_mu[Cn];
static __device__ float g_istd[Cn];

// ------------------------- prep (3 tiny launches) ---------------------------
__global__ void prep_tw_k() {
    int j = threadIdx.x;           // 128
    float ang = -6.2831853071795864f * (float)j / 256.f;
    float s, c; sincosf(ang, &s, &c);
    g_tw[j] = make_float2(c, s);
}
__global__ void prep_defw_k(const float* __restrict__ defw, int i0, int i1) {
    int i = i0 + blockIdx.x*256 + threadIdx.x;
    if (i >= i1) return;
    int o = i % 96; int c = (i / 96) % 96; int t = i / (96*96);
    g_defwt[i] = defw[((size_t)o*96 + c)*9 + t];
}

// ------------------------- FFT kernels (split, high-parallel) ---------------
// Two real rows packed into one 256-pt complex FFT; unpack to two spectra.
__global__ void fft_rows_k(const float* __restrict__ in, int cstride) {
    __shared__ float re[256], im[256];
    __shared__ float2 tws[128];
    int h0 = blockIdx.x * 2;
    int c = blockIdx.y, b = blockIdx.z;
    const float* r0 = in + ((size_t)(b*cstride + c)*Hn + h0)*Wn;
    const float* r1 = r0 + Wn;
    int tid = threadIdx.x;                // 128
    tws[tid] = g_tw[tid];
    for (int i = tid; i < 256; i += 128) {
        int j = __brev((unsigned)i) >> 24;
        re[j] = r0[i];
        im[j] = r1[i];
    }
    __syncthreads();
    #pragma unroll
    for (int s = 1; s <= 8; s++) {
        int half = 1 << (s - 1);
        int i = tid;
        int off = i & (half - 1);
        int a = ((i >> (s - 1)) << s) + off;
        int bb = a + half;
        float2 tw = tws[off << (8 - s)];
        float br = re[bb], bi = im[bb];
        float ar = re[a],  ai = im[a];
        float xr = br*tw.x - bi*tw.y;
        float xi = br*tw.y + bi*tw.x;
        re[a] = ar + xr; im[a] = ai + xi;
        re[bb] = ar - xr; im[bb] = ai - xi;
        __syncthreads();
    }
    float2* out0 = g_fft + ((size_t)(b*Cn + c)*Hn + h0)*WFn;
    float2* out1 = out0 + WFn;
    int k = tid;
    float zr = re[k], zi = im[k];
    int km = (256 - k) & 255;
    float wr = re[km], wi = im[km];
    out0[k] = make_float2(0.5f*(zr + wr), 0.5f*(zi - wi));
    out1[k] = make_float2(0.5f*(zi + wi), -0.5f*(zr - wr));
    if (tid == 0) {
        out0[128] = make_float2(re[128], 0.f);
        out1[128] = make_float2(im[128], 0.f);
    }
}

// fused: y = x*ca*sa (written to g_aux) + row FFT of y
__global__ void fft_rows_y_k(const float* __restrict__ x) {
    __shared__ float re[256], im[256];
    __shared__ float2 tws[128];
    int h0 = blockIdx.x * 2;
    int c = blockIdx.y, b = blockIdx.z;
    const float* r0 = x + ((size_t)(b*Cn + c)*Hn + h0)*Wn;
    const float* r1 = r0 + Wn;
    float* y0 = g_aux + ((size_t)(b*AUXn + c)*Hn + h0)*Wn;
    float* y1 = y0 + Wn;
    const float* sa0 = g_sa + (size_t)b*HWn + h0*Wn;
    const float* sa1 = sa0 + Wn;
    float cav = g_ca[b*Cn + c];
    int tid = threadIdx.x;                // 128
    tws[tid] = g_tw[tid];
    for (int i = tid; i < 256; i += 128) {
        int j = __brev((unsigned)i) >> 24;
        float v0 = r0[i]*cav*sa0[i];
        float v1 = r1[i]*cav*sa1[i];
        y0[i] = v0; y1[i] = v1;
        re[j] = v0;
        im[j] = v1;
    }
    __syncthreads();
    #pragma unroll
    for (int s = 1; s <= 8; s++) {
        int half = 1 << (s - 1);
        int i = tid;
        int off = i & (half - 1);
        int a = ((i >> (s - 1)) << s) + off;
        int bb = a + half;
        float2 tw = tws[off << (8 - s)];
        float br = re[bb], bi = im[bb];
        float ar = re[a],  ai = im[a];
        float xr = br*tw.x - bi*tw.y;
        float xi = br*tw.y + bi*tw.x;
        re[a] = ar + xr; im[a] = ai + xi;
        re[bb] = ar - xr; im[bb] = ai - xi;
        __syncthreads();
    }
    float2* out0 = g_fft + ((size_t)(b*Cn + c)*Hn + h0)*WFn;
    float2* out1 = out0 + WFn;
    int k = tid;
    float zr = re[k], zi = im[k];
    int km = (256 - k) & 255;
    float wr = re[km], wi = im[km];
    out0[k] = make_float2(0.5f*(zr + wr), 0.5f*(zi - wi));
    out1[k] = make_float2(0.5f*(zi + wi), -0.5f*(zr - wr));
    if (tid == 0) {
        out0[128] = make_float2(re[128], 0.f);
        out1[128] = make_float2(im[128], 0.f);
    }
}

// 128-pt FFT down columns, 16 columns per block (coalesced), |.| * 1/sqrt(HW)
__global__ void fft_cols_k() {
    __shared__ float cre[16][129];
    __shared__ float cim[16][129];
    __shared__ float2 tws[128];
    int kb = blockIdx.x;                  // 0..8
    int c = blockIdx.y, b = blockIdx.z;
    int bc = b*Cn + c;
    int k0 = kb * 16;
    int ncols = (kb < 8) ? 16 : 1;
    int lg = (kb < 8) ? 4 : 0;
    int tid = threadIdx.x;                // 128
    tws[tid] = g_tw[tid];
    int kk = tid & 15, ht = tid >> 4;
    const float2* src = g_fft + (size_t)bc*Hn*WFn;
    for (int hb = 0; hb < 16; hb++) {
        int h = hb*8 + ht;
        if (kk < ncols) {
            float2 v = src[(size_t)h*WFn + k0 + kk];
            int j = __brev((unsigned)h) >> 25;
            cre[kk][j] = v.x; cim[kk][j] = v.y;
        }
    }
    __syncthreads();
    #pragma unroll
    for (int s = 1; s <= 7; s++) {
        int half = 1 << (s - 1);
        int total = ncols << 6;
        for (int e = tid; e < total; e += 128) {
            int col = e & (ncols - 1);
            int i = e >> lg;
            int off = i & (half - 1);
            int a = ((i >> (s - 1)) << s) + off;
            int bb = a + half;
            float2 tw = tws[off << (8 - s)];
            float br = cre[col][bb], bi = cim[col][bb];
            float ar = cre[col][a],  ai = cim[col][a];
            float xr = br*tw.x - bi*tw.y;
            float xi = br*tw.y + bi*tw.x;
            cre[col][a] = ar + xr; cim[col][a] = ai + xi;
            cre[col][bb] = ar - xr; cim[col][bb] = ai - xi;
        }
        __syncthreads();
    }
    const float sc = 0.0055242717280199026f;  // 1/sqrt(128*256)
    float* dst = g_mag + (size_t)bc*Hn*WFn;
    int total = ncols << 7;
    for (int e = tid; e < total; e += 128) {
        int col = e & (ncols - 1);
        int h = e >> lg;
        float r = cre[col][h], m = cim[col][h];
        dst[(size_t)h*WFn + k0 + col] = sqrtf(r*r + m*m) * sc;
    }
}

// mean over channels of g_mag -> out[b][h][k]
__global__ void chan_mean_k(float* __restrict__ out) {
    int h = blockIdx.x, b = blockIdx.y;
    for (int k = threadIdx.x; k < WFn; k += 160) {
        float s = 0.f;
        const float* p = g_mag + ((size_t)(b*Cn)*Hn + h)*WFn + k;
        #pragma unroll 4
        for (int c = 0; c < Cn; c++) s += p[(size_t)c*Hn*WFn];
        out[(size_t)(b*Hn + h)*WFn + k] = s * (1.f/Cn);
    }
}

// --------- fused freq branch: direct 49-tap separable stencil + pools -------
__global__ __launch_bounds__(512)
void freq_fused_k(const float* __restrict__ w7h, const float* __restrict__ b7h,
                  const float* __restrict__ w7w, const float* __restrict__ b7w) {
    extern __shared__ float A[];          // [128][132]
    __shared__ float S[4][132];
    __shared__ float bins[21];
    int c = blockIdx.x, b = blockIdx.y;
    int tid = threadIdx.x;
    const float* mp = g_mag + (size_t)(b*Cn + c)*Hn*WFn;
    for (int e = tid; e < 128*129; e += 512) {
        int h = e / 129, k = e - h*129;
        A[h*132 + k] = mp[e];
    }
    float wh[7], ww[7];
    #pragma unroll
    for (int d = 0; d < 7; d++) { wh[d] = w7h[c*7+d]; ww[d] = w7w[c*7+d]; }
    float bh = b7h[c], bw = b7w[c];
    __syncthreads();
    for (int t = tid; t < 4*129; t += 512) {
        int band = t / 129, k = t - band*129;
        float acc = 0.f;
        for (int hh = 0; hh < 32; hh++) {
            int h = band*32 + hh;
            float t2 = bw;
            #pragma unroll
            for (int d = 0; d < 7; d++) {
                int kk = k + d - 3;
                if (kk >= 0 && kk < 129) {
                    float t1 = bh;
                    #pragma unroll
                    for (int e = 0; e < 7; e++) {
                        int h2 = h + e - 3;
                        if (h2 >= 0 && h2 < 128) t1 += wh[e]*A[h2*132 + kk];
                    }
                    t2 += ww[d]*t1;
                }
            }
            acc += t2;
        }
        S[band][k] = acc;
    }
    __syncthreads();
    if (tid < 16) {
        int i = tid >> 2, j = tid & 3;
        int ws = (j*WFn)/4, we = ((j+1)*WFn + 3)/4;
        float s = 0;
        for (int k = ws; k < we; k++) s += S[i][k];
        bins[tid] = s / (32.f * (float)(we - ws));
    } else if (tid < 20) {
        int t2 = tid - 16; int i = t2 >> 1, j = t2 & 1;
        int ws = (j*WFn)/2, we = ((j+1)*WFn + 1)/2;
        float s = 0;
        for (int k = ws; k < we; k++) s += S[2*i][k] + S[2*i+1][k];
        bins[tid] = s / (64.f * (float)(we - ws));
    } else if (tid == 20) {
        float s = 0;
        for (int k = 0; k < WFn; k++) s += S[0][k]+S[1][k]+S[2][k]+S[3][k];
        bins[20] = s / (128.f*129.f);
    }
    __syncthreads();
    if (tid == 0) {
        float g2 = bins[16]+bins[17]+bins[18]+bins[19];
        float g3 = 0;
        for (int m = 0; m < 16; m++) g3 += bins[m];
        g_gvec[b*288 + c]        = bins[20];
        g_gvec[b*288 + Cn + c]   = g2 * 0.25f;
        g_gvec[b*288 + 2*Cn + c] = g3 * 0.0625f;
    }
}

// ------------------------- channel-attention MLP ----------------------------
__global__ void ca_mlp_k(const float* __restrict__ w1, const float* __restrict__ b1,
                         const float* __restrict__ w2, const float* __restrict__ b2) {
    __shared__ float gs[288], hs[MIDn];
    int b = blockIdx.x, tid = threadIdx.x;   // 96 threads
    for (int i = tid; i < 288; i += 96) gs[i] = g_gvec[b*288 + i];
    __syncthreads();
    if (tid < MIDn) {
        float a = b1[tid];
        for (int k = 0; k < 288; k++) a += w1[tid*288 + k]*gs[k];
        hs[tid] = fmaxf(a, 0.f);
    }
    __syncthreads();
    float a = b2[tid];
    #pragma unroll
    for (int m = 0; m < MIDn; m++) a += w2[tid*MIDn + m]*hs[m];
    g_ca[b*Cn + tid] = 1.f/(1.f + expf(-a));
}

// ------------------------- spatial branch -----------------------------------
__global__ void spatial_in_k(const float* __restrict__ x) {
    int h = blockIdx.x, b = blockIdx.y;
    int w = threadIdx.x;                  // 256
    int hw = h*Wn + w;
    const float* xp = x + (size_t)b*Cn*HWn + hw;
    float s = 0.f, s2 = 0.f;
    #pragma unroll 4
    for (int c = 0; c < Cn; c++) { float v = xp[(size_t)c*HWn]; s += v; s2 += v*v; }
    float mean = s * (1.f/Cn);
    float l2 = sqrtf(s2 * (1.f/Cn) + 1e-6f);
    float src = ((float)w + 0.5f)*(129.f/256.f) - 0.5f;
    float f0 = floorf(src); int i0 = (int)f0; float fr = src - f0;
    int ia = min(max(i0, 0), WFn-1), ib = min(max(i0+1, 0), WFn-1);
    const float* fp = g_fe + (size_t)(b*Hn + h)*WFn;
    float fv = fp[ia]*(1.f - fr) + fp[ib]*fr;
    g_s0[((size_t)(b*3+0))*HWn + hw] = mean;
    g_s0[((size_t)(b*3+1))*HWn + hw] = l2;
    g_s0[((size_t)(b*3+2))*HWn + hw] = fv;
}

// fused dwsp_h + dwsp_w + sr: one block per (h, b); 256 threads (w)
__global__ __launch_bounds__(256)
void sp_fused_k(const float* __restrict__ w15h, const float* __restrict__ b15h,
                const float* __restrict__ w15w, const float* __restrict__ b15w,
                const float* __restrict__ sr1w, const float* __restrict__ sr1b,
                const float* __restrict__ sr2w, const float* __restrict__ sr2b) {
    __shared__ float s1buf[3][3][272];   // [ch][j(row h-1..h+1)][7-pad + 256 + 9-pad]
    __shared__ float sbuf[3][3][258];    // s rows (post w-conv), +1 pad each side
    __shared__ float wsm[3][15], wsw[3][15];
    int h = blockIdx.x, b = blockIdx.y;
    int w = threadIdx.x;                 // 256
    if (w < 45) { wsm[w/15][w%15] = w15h[w]; wsw[w/15][w%15] = w15w[w]; }
    // zero pads of s1buf
    if (w < 7) {
        #pragma unroll
        for (int ch = 0; ch < 3; ch++)
            #pragma unroll
            for (int j = 0; j < 3; j++) { s1buf[ch][j][w] = 0.f; s1buf[ch][j][263+w] = 0.f; }
    }
    if (w < 9) {
        #pragma unroll
        for (int ch = 0; ch < 3; ch++)
            #pragma unroll
            for (int j = 0; j < 3; j++) s1buf[ch][j][263+w] = 0.f;
    }
    if (w < 3) {   // sbuf column pads
        #pragma unroll
        for (int ch = 0; ch < 3; ch++) { sbuf[ch][w][0] = 0.f; sbuf[ch][w][257] = 0.f; }
    }
    __syncthreads();
    // s1 rows h-1..h+1 (vertical 15-tap over s0; taps outside -> zero)
    #pragma unroll
    for (int ch = 0; ch < 3; ch++) {
        const float* s0p = g_s0 + ((size_t)(b*3 + ch))*HWn + w;
        #pragma unroll
        for (int j = 0; j < 3; j++) {
            int hr = h + j - 1;
            float a = b15h[ch];
            #pragma unroll
            for (int d = 0; d < 15; d++) {
                int hh = hr + d - 7;
                if (hh >= 0 && hh < Hn) a += wsm[ch][d]*s0p[hh*Wn];
            }
            s1buf[ch][j][7 + w] = a;
        }
    }
    __syncthreads();
    // s rows h-1..h+1 (horizontal 15-tap over s1; zero-pads handle bounds)
    #pragma unroll
    for (int ch = 0; ch < 3; ch++) {
        #pragma unroll
        for (int j = 0; j < 3; j++) {
            float a = b15w[ch];
            #pragma unroll
            for (int d = 0; d < 15; d++) a += wsw[ch][d]*s1buf[ch][j][w + d];
            sbuf[ch][j][1 + w] = a;
        }
    }
    __syncthreads();
    // sr: 3x3 conv (groups=3) + relu + 1x1 + sigmoid. Row validity mask.
    float acc = sr2b[0];
    #pragma unroll
    for (int ch = 0; ch < 3; ch++) {
        float v = sr1b[ch];
        #pragma unroll
        for (int ky = 0; ky < 3; ky++) {
            int hh = h + ky - 1; if (hh < 0 || hh >= Hn) continue;
            #pragma unroll
            for (int kx = 0; kx < 3; kx++) {
                // sbuf col pad handles w bounds (zeros)
                v += sr1w[ch*9 + ky*3 + kx]*sbuf[ch][ky][w + kx];
            }
        }
        acc += sr2w[ch]*fmaxf(v, 0.f);
    }
    g_sa[(size_t)b*HWn + h*Wn + w] = 1.f/(1.f + expf(-acc));
}

__global__ void auxmisc_k() {
    int h = blockIdx.x, b = blockIdx.y;
    int w = threadIdx.x;                 // 256
    int hw = h*Wn + w;
    float theta = -3.14159265358979324f + (float)w * (6.2831853071795864f/255.f);
    float phi   = -1.57079632679489662f + (float)h * (3.14159265358979324f/127.f);
    size_t base = (size_t)b*AUXn*HWn + hw;
    g_aux[base + (size_t)96*HWn] = sinf(theta);
    g_aux[base + (size_t)97*HWn] = cosf(theta);
    g_aux[base + (size_t)98*HWn] = sinf(phi);
    g_aux[base + (size_t)99*HWn] = cosf(phi);
    float src = ((float)w + 0.5f)*(129.f/256.f) - 0.5f;
    float f0 = floorf(src); int i0 = (int)f0; float fr = src - f0;
    int ia = min(max(i0, 0), WFn-1), ib = min(max(i0+1, 0), WFn-1);
    const float* fp = g_fem + (size_t)(b*Hn + h)*WFn;
    g_aux[base + (size_t)100*HWn] = fp[ia]*(1.f - fr) + fp[ib]*fr;
}

// ------------- tiled 3x3 conv: swizzled pair-tile + packed weights ----------
template<int CIN, int CSTRIDE, int COUT, bool RELU>
__global__ __launch_bounds__(256)
void conv3x3_k(const float* __restrict__ in, const float* __restrict__ wgt,
               const float* __restrict__ bias, float* __restrict__ out) {
    constexpr int NO = (COUT + 31) / 32;
    constexpr int CB = 8;
    __shared__ float2 tile2[CB][3][66];
    extern __shared__ float2 wdyn[];          // [CB][COUT*9] packed (w,w)
    int bx = blockIdx.x;
    int seg = bx & 3; int h = (bx >> 2) & (Hn - 1); int b = bx >> 9;
    int w0 = seg * 64;
    int tid = threadIdx.x;
    int pg = tid & 7, og = tid >> 3;
    u64 pacc[NO][4];
    #pragma unroll
    for (int k = 0; k < NO; k++)
        #pragma unroll
        for (int q = 0; q < 4; q++) pacc[k][q] = 0ull;
    const float* inb = in + (size_t)b*CSTRIDE*HWn;
    int pv8idx = (pg == 7) ? 64 : (pg + 1);
    for (int c0 = 0; c0 < CIN; c0 += CB) {
        for (int m = tid; m < CB*3*65; m += 256) {
            int ci = m / 195; int rem = m - ci*195; int r = rem / 65; int p = rem - r*65;
            int l = (p < 64) ? (((p & 7) << 3) | (p >> 3)) : 64;
            int hh = h + r - 1, ww = w0 + l - 1;
            float v0 = 0.f, v1 = 0.f;
            if (c0 + ci < CIN && hh >= 0 && hh < Hn) {
                const float* rowp = inb + (size_t)(c0 + ci)*HWn + (size_t)hh*Wn;
                if (ww >= 0 && ww < Wn) v0 = rowp[ww];
                if (ww + 1 >= 0 && ww + 1 < Wn) v1 = rowp[ww + 1];
            }
            tile2[ci][r][p] = make_float2(v0, v1);
        }
        for (int m = tid; m < CB*COUT*9; m += 256) {
            int ci = m / (COUT*9); int rem = m - ci*(COUT*9);
            float v = 0.f;
            if (c0 + ci < CIN) {
                int o = rem / 9, j = rem - o*9;
                v = wgt[((size_t)o*CIN + c0 + ci)*9 + j];
            }
            wdyn[ci*(COUT*9) + rem] = make_float2(v, v);
        }
        __syncthreads();
        #pragma unroll 2
        for (int ci = 0; ci < CB; ci++) {
            #pragma unroll
            for (int r = 0; r < 3; r++) {
                const float2* trow = tile2[ci][r];
                u64 pv[9];
                #pragma unroll
                for (int j = 0; j < 8; j++) pv[j] = *(const u64*)&trow[j*8 + pg];
                pv[8] = *(const u64*)&trow[pv8idx];
                #pragma unroll
                for (int k = 0; k < NO; k++) {
                    int o = og + 32*k;
                    if ((COUT & 31) && o >= COUT) break;
                    const u64* wp = (const u64*)&wdyn[ci*(COUT*9) + o*9 + r*3];
                    u64 wb0 = wp[0], wb1 = wp[1], wb2 = wp[2];
                    #pragma unroll
                    for (int q = 0; q < 4; q++) {
                        pacc[k][q] = ffma2(wb0, pv[2*q],   pacc[k][q]);
                        pacc[k][q] = ffma2(wb1, pv[2*q+1], pacc[k][q]);
                        pacc[k][q] = ffma2(wb2, pv[2*q+2], pacc[k][q]);
                    }
                }
            }
        }
        __syncthreads();
    }
    #pragma unroll
    for (int k = 0; k < NO; k++) {
        int o = og + 32*k;
        if ((COUT & 31) && o >= COUT) break;
        float bb = bias[o];
        float* op = out + ((size_t)(b*COUT + o))*HWn + h*Wn + w0 + pg*8;
        #pragma unroll
        for (int q = 0; q < 4; q++) {
            float2 f = unpack2(pacc[k][q]);
            float vx = f.x + bb, vy = f.y + bb;
            if (RELU) { vx = fmaxf(vx, 0.f); vy = fmaxf(vy, 0.f); }
            op[2*q] = vx; op[2*q+1] = vy;
        }
    }
}

// ------------- merged offset(18) + dg1(50) conv with fused gate head --------
__global__ __launch_bounds__(256)
void convoffdg_k(const float* __restrict__ offw, const float* __restrict__ offbias,
                 const float* __restrict__ dg1w, const float* __restrict__ dg1b,
                 const float* __restrict__ dg2w, const float* __restrict__ dg2b) {
    constexpr int COUT = 68;
    constexpr int NO = 3;
    constexpr int CB = 8;
    __shared__ float2 tile2[CB][3][66];
    __shared__ float sgate[32][64];
    extern __shared__ float2 wdyn[];          // [CB][COUT*9]
    int bx = blockIdx.x;
    int seg = bx & 3; int h = (bx >> 2) & (Hn - 1); int b = bx >> 9;
    int w0 = seg * 64;
    int tid = threadIdx.x;
    int pg = tid & 7, og = tid >> 3;
    u64 pacc[NO][4];
    #pragma unroll
    for (int k = 0; k < NO; k++)
        #pragma unroll
        for (int q = 0; q < 4; q++) pacc[k][q] = 0ull;
    const float* inb = g_aux + (size_t)b*AUXn*HWn;
    int pv8idx = (pg == 7) ? 64 : (pg + 1);
    for (int c0 = 0; c0 < AUXn; c0 += CB) {
        for (int m = tid; m < CB*3*65; m += 256) {
            int ci = m / 195; int rem = m - ci*195; int r = rem / 65; int p = rem - r*65;
            int l = (p < 64) ? (((p & 7) << 3) | (p >> 3)) : 64;
            int hh = h + r - 1, ww = w0 + l - 1;
            float v0 = 0.f, v1 = 0.f;
            if (c0 + ci < AUXn && hh >= 0 && hh < Hn) {
                const float* rowp = inb + (size_t)(c0 + ci)*HWn + (size_t)hh*Wn;
                if (ww >= 0 && ww < Wn) v0 = rowp[ww];
                if (ww + 1 >= 0 && ww + 1 < Wn) v1 = rowp[ww + 1];
            }
            tile2[ci][r][p] = make_float2(v0, v1);
        }
        for (int m = tid; m < CB*COUT*9; m += 256) {
            int ci = m / (COUT*9); int rem = m - ci*(COUT*9);
            float v = 0.f;
            if (c0 + ci < AUXn) {
                int o = rem / 9, j = rem - o*9;
                if (o < 18) v = offw[((size_t)o*AUXn + c0 + ci)*9 + j];
                else        v = dg1w[((size_t)(o-18)*AUXn + c0 + ci)*9 + j];
            }
            wdyn[ci*(COUT*9) + rem] = make_float2(v, v);
        }
        __syncthreads();
        #pragma unroll 2
        for (int ci = 0; ci < CB; ci++) {
            #pragma unroll
            for (int r = 0; r < 3; r++) {
                const float2* trow = tile2[ci][r];
                u64 pv[9];
                #pragma unroll
                for (int j = 0; j < 8; j++) pv[j] = *(const u64*)&trow[j*8 + pg];
                pv[8] = *(const u64*)&trow[pv8idx];
                #pragma unroll
                for (int k = 0; k < NO; k++) {
                    int o = og + 32*k;
                    if (o >= COUT) break;
                    const u64* wp = (const u64*)&wdyn[ci*(COUT*9) + o*9 + r*3];
                    u64 wb0 = wp[0], wb1 = wp[1], wb2 = wp[2];
                    #pragma unroll
                    for (int q = 0; q < 4; q++) {
                        pacc[k][q] = ffma2(wb0, pv[2*q],   pacc[k][q]);
                        pacc[k][q] = ffma2(wb1, pv[2*q+1], pacc[k][q]);
                        pacc[k][q] = ffma2(wb2, pv[2*q+2], pacc[k][q]);
                    }
                }
            }
        }
        __syncthreads();
    }
    float part[8];
    #pragma unroll
    for (int p = 0; p < 8; p++) part[p] = 0.f;
    #pragma unroll
    for (int k = 0; k < NO; k++) {
        int o = og + 32*k;
        if (o >= COUT) break;
        if (o < 18) {
            float bb = offbias[o];
            float* op = g_offb + ((size_t)(b*18 + o))*HWn + h*Wn + w0 + pg*8;
            #pragma unroll
            for (int q = 0; q < 4; q++) {
                float2 f = unpack2(pacc[k][q]);
                op[2*q] = f.x + bb; op[2*q+1] = f.y + bb;
            }
        } else {
            float bb = dg1b[o-18];
            float wv = dg2w[o-18];
            #pragma unroll
            for (int q = 0; q < 4; q++) {
                float2 f = unpack2(pacc[k][q]);
                part[2*q]   += wv * fmaxf(f.x + bb, 0.f);
                part[2*q+1] += wv * fmaxf(f.y + bb, 0.f);
            }
        }
    }
    #pragma unroll
    for (int p = 0; p < 8; p++) sgate[og][pg*8 + p] = part[p];
    __syncthreads();
    if (tid < 64) {
        float s = dg2b[0];
        #pragma unroll 8
        for (int o2 = 0; o2 < 32; o2++) s += sgate[o2][tid];
        g_gate[(size_t)b*HWn + h*Wn + w0 + tid] = 1.f/(1.f + expf(-s));
    }
}

// ------------------------- deformable sampling + GEMM + combine -------------
__global__ __launch_bounds__(256)
void deform_combine_k(const float* __restrict__ defb) {
    extern __shared__ float dsm[];
    float2* samp2 = (float2*)dsm;                    // 2304 float2
    float2* wsh2  = (float2*)(dsm + 4608);           // 6912 float2
    float*  s_w   = dsm + 18432;                     // 2304
    int*    s_idx = (int*)(dsm + 20736);             // 2304
    int bx = blockIdx.x;
    int seg = bx & 3; int h = (bx >> 2) & (Hn - 1); int b = bx >> 9;
    int w0 = seg * 64;
    int tid = threadIdx.x;
    int pg = tid & 7, og = tid >> 3;

    for (int e = tid; e < 576; e += 256) {
        int t9 = e >> 6, p = e & 63;
        int wpx = w0 + p;
        size_t obase = ((size_t)b*18)*HWn + (size_t)h*Wn + wpx;
        float ox = g_offb[obase + (size_t)(2*t9)*HWn];
        float oy = g_offb[obase + (size_t)(2*t9+1)*HWn];
        float px = (float)wpx + ox;
        float py = (float)h + oy;
        float x0 = floorf(px), y0 = floorf(py);
        float fx = px - x0, fy = py - y0;
        #pragma unroll
        for (int j = 0; j < 4; j++) {
            float xj = x0 + (float)(j & 1);
            float yj = y0 + (float)(j >> 1);
            float valid = (xj >= 0.f && xj <= 255.f && yj >= 0.f && yj <= 127.f) ? 1.f : 0.f;
            float xc = fminf(fmaxf(xj, 0.f), 255.f);
            float yc = fminf(fmaxf(yj, 0.f), 127.f);
            s_idx[(t9*64 + p)*4 + j] = (int)yc * Wn + (int)xc;
            float wx = (j & 1) ? fx : (1.f - fx);
            float wy = (j >> 1) ? fy : (1.f - fy);
            s_w[(t9*64 + p)*4 + j] = wx * wy * valid;
        }
    }

    u64 pacc[3][4];
    #pragma unroll
    for (int k = 0; k < 3; k++)
        #pragma unroll
        for (int q = 0; q < 4; q++) pacc[k][q] = 0ull;

    for (int c0 = 0; c0 < 96; c0 += 8) {
        __syncthreads();
        for (int e = tid; e < 2304; e += 256) {
            int t9 = e >> 8; int rem = e & 255; int c = rem >> 5; int P = rem & 31;
            int p0 = 2*P;
            const float* yp = g_aux + ((size_t)(b*AUXn + c0 + c))*HWn;
            const int* i0 = &s_idx[(t9*64 + p0)*4];
            const float* q0 = &s_w[(t9*64 + p0)*4];
            float v0 = q0[0]*yp[i0[0]] + q0[1]*yp[i0[1]] + q0[2]*yp[i0[2]] + q0[3]*yp[i0[3]];
            const int* i1 = i0 + 4; const float* q1 = q0 + 4;
            float v1 = q1[0]*yp[i1[0]] + q1[1]*yp[i1[1]] + q1[2]*yp[i1[2]] + q1[3]*yp[i1[3]];
            samp2[(t9*8 + c)*32 + (((P & 3) << 3) | (P >> 2))] = make_float2(v0, v1);
        }
        for (int e = tid; e < 6912; e += 256) {
            int t9 = e / 768; int rem = e - t9*768;
            int c = rem / 96; int o = rem - c*96;
            float v = g_defwt[((size_t)(t9*96) + c0 + c)*96 + o];
            wsh2[e] = make_float2(v, v);
        }
        __syncthreads();
        #pragma unroll 3
        for (int t9 = 0; t9 < 9; t9++) {
            #pragma unroll
            for (int c = 0; c < 8; c++) {
                const float2* sp = &samp2[(t9*8 + c)*32];
                u64 s0 = *(const u64*)&sp[0*8 + pg];
                u64 s1 = *(const u64*)&sp[1*8 + pg];
                u64 s2 = *(const u64*)&sp[2*8 + pg];
                u64 s3 = *(const u64*)&sp[3*8 + pg];
                const float2* wb = &wsh2[(t9*8 + c)*96];
                #pragma unroll
                for (int k = 0; k < 3; k++) {
                    u64 wp2 = *(const u64*)&wb[og + 32*k];
                    pacc[k][0] = ffma2(wp2, s0, pacc[k][0]);
                    pacc[k][1] = ffma2(wp2, s1, pacc[k][1]);
                    pacc[k][2] = ffma2(wp2, s2, pacc[k][2]);
                    pacc[k][3] = ffma2(wp2, s3, pacc[k][3]);
                }
            }
        }
    }
    #pragma unroll
    for (int k = 0; k < 3; k++) {
        int o = og + 32*k;
        float bb = defb[o];
        size_t rowoff = (size_t)h*Wn + w0 + pg*8;
        float* zp = g_z + ((size_t)(b*Cn + o))*HWn + rowoff;
        const float* yb = g_ybase + ((size_t)(b*Cn + o))*HWn + rowoff;
        const float* gp = g_gate + (size_t)b*HWn + rowoff;
        #pragma unroll
        for (int q = 0; q < 4; q++) {
            float2 f = unpack2(pacc[k][q]);
            float g0 = gp[2*q], g1 = gp[2*q+1];
            zp[2*q]   = (1.f - g0)*yb[2*q]   + g0*(f.x + bb);
            zp[2*q+1] = (1.f - g1)*yb[2*q+1] + g1*(f.y + bb);
        }
    }
}

// ------------------------- batchnorm (float4) -------------------------------
__global__ void bn_stats_k() {
    __shared__ float ss[256], ss2[256];
    int c = blockIdx.x, tid = threadIdx.x;
    float s = 0.f, s2 = 0.f;
    for (int b = 0; b < Bn; b++) {
        const float4* zp = (const float4*)(g_z + ((size_t)(b*Cn + c))*HWn);
        for (int i = tid; i < HWn/4; i += 256) {
            float4 v = zp[i];
            s += v.x + v.y + v.z + v.w;
            s2 += v.x*v.x + v.y*v.y + v.z*v.z + v.w*v.w;
        }
    }
    ss[tid] = s; ss2[tid] = s2;
    __syncthreads();
    for (int st = 128; st > 0; st >>= 1) {
        if (tid < st) { ss[tid] += ss[tid+st]; ss2[tid] += ss2[tid+st]; }
        __syncthreads();
    }
    if (tid == 0) {
        float inv = 1.f/(float)(Bn*HWn);
        float mu = ss[0]*inv;
        float var = ss2[0]*inv - mu*mu;
        g_mu[c] = mu;
        g_istd[c] = rsqrtf(var + 1e-5f);
    }
}

__global__ void bn_apply_k(const float* __restrict__ x,
                           const float* __restrict__ gam, const float* __restrict__ bet,
                           float* __restrict__ out) {
    int e = blockIdx.x*256 + threadIdx.x;          // float4 index within plane
    int c = blockIdx.y, b = blockIdx.z;
    size_t i4 = ((size_t)(b*Cn + c))*(HWn/4) + e;
    float sc2 = g_istd[c]*gam[c];
    float sh = bet[c] - g_mu[c]*sc2;
    float4 z = ((const float4*)g_z)[i4];
    float4 xv = ((const float4*)x)[i4];
    float4 o;
    o.x = fmaxf(z.x*sc2 + sh + xv.x, 0.f);
    o.y = fmaxf(z.y*sc2 + sh + xv.y, 0.f);
    o.z = fmaxf(z.z*sc2 + sh + xv.z, 0.f);
    o.w = fmaxf(z.w*sc2 + sh + xv.w, 0.f);
    ((float4*)out)[i4] = o;
}

// ------------------------- launch -------------------------------------------
extern "C" void kernel_launch(void* const* d_in, const int* in_sizes, int n_in,
                              void* d_out, int out_size) {
    const float* x     = (const float*)d_in[0];
    const float* fdh_w = (const float*)d_in[1];
    const float* fdh_b = (const float*)d_in[2];
    const float* fdw_w = (const float*)d_in[3];
    const float* fdw_b = (const float*)d_in[4];
    const float* cp1_w = (const float*)d_in[5];
    const float* cp1_b = (const float*)d_in[6];
    const float* cp2_w = (const float*)d_in[7];
    const float* cp2_b = (const float*)d_in[8];
    const float* sdh_w = (const float*)d_in[9];
    const float* sdh_b = (const float*)d_in[10];
    const float* sdw_w = (const float*)d_in[11];
    const float* sdw_b = (const float*)d_in[12];
    const float* sr1_w = (const float*)d_in[13];
    const float* sr1_b = (const float*)d_in[14];
    const float* sr2_w = (const float*)d_in[15];
    const float* sr2_b = (const float*)d_in[16];
    const float* off_w = (const float*)d_in[17];
    const float* off_b = (const float*)d_in[18];
    const float* dg1_w = (const float*)d_in[19];
    const float* dg1_b = (const float*)d_in[20];
    const float* dg2_w = (const float*)d_in[21];
    const float* dg2_b = (const float*)d_in[22];
    const float* base_w = (const float*)d_in[23];
    const float* base_b = (const float*)d_in[24];
    const float* def_w = (const float*)d_in[25];
    const float* def_b = (const float*)d_in[26];
    const float* bn_g  = (const float*)d_in[27];
    const float* bn_b  = (const float*)d_in[28];
    float* out = (float*)d_out;

    float *p_fe, *p_fem, *p_aux, *p_ybase;
    cudaGetSymbolAddress((void**)&p_fe, g_fe);
    cudaGetSymbolAddress((void**)&p_fem, g_fem);
    cudaGetSymbolAddress((void**)&p_aux, g_aux);
    cudaGetSymbolAddress((void**)&p_ybase, g_ybase);

    const int FREQ_SMEM = 128*132*4;         // 67584 B
    const int DEF_SMEM  = 23040 * 4;         // 92160 B
    const int C96_SMEM  = 8*96*9*8;          // 55296 B
    const int C68_SMEM  = 8*68*9*8;          // 39168 B
    cudaFuncSetAttribute(freq_fused_k, cudaFuncAttributeMaxDynamicSharedMemorySize, FREQ_SMEM);
    cudaFuncSetAttribute(deform_combine_k, cudaFuncAttributeMaxDynamicSharedMemorySize, DEF_SMEM);
    cudaFuncSetAttribute(conv3x3_k<Cn,AUXn,96,false>, cudaFuncAttributeMaxDynamicSharedMemorySize, C96_SMEM);
    cudaFuncSetAttribute(convoffdg_k, cudaFuncAttributeMaxDynamicSharedMemorySize, C68_SMEM);

    prep_tw_k<<<1, 128>>>();
    prep_defw_k<<<CDIV(41472,256), 256>>>(def_w, 0, 41472);
    prep_defw_k<<<CDIV(41472,256), 256>>>(def_w, 41472, 82944);
    // ---- FFT(x) -> mag, fe ----
    fft_rows_k<<<dim3(Hn/2, Cn, Bn), 128>>>(x, Cn);
    fft_cols_k<<<dim3(9, Cn, Bn), 128>>>();
    chan_mean_k<<<dim3(Hn, Bn), 160>>>(p_fe);
    // ---- freq branch ----
    freq_fused_k<<<dim3(Cn, Bn), 512, FREQ_SMEM>>>(fdh_w, fdh_b, fdw_w, fdw_b);
    ca_mlp_k<<<Bn, 96>>>(cp1_w, cp1_b, cp2_w, cp2_b);
    // ---- spatial branch (fused) ----
    spatial_in_k<<<dim3(Hn, Bn), 256>>>(x);
    sp_fused_k<<<dim3(Hn, Bn), 256>>>(sdh_w, sdh_b, sdw_w, sdw_b,
                                      sr1_w, sr1_b, sr2_w, sr2_b);
    // ---- y = x*ca*sa (into aux) + FFT(y) rows, fused ----
    fft_rows_y_k<<<dim3(Hn/2, Cn, Bn), 128>>>(x);
    fft_cols_k<<<dim3(9, Cn, Bn), 128>>>();
    chan_mean_k<<<dim3(Hn, Bn), 160>>>(p_fem);
    auxmisc_k<<<dim3(Hn, Bn), 256>>>();
    // ---- convs ----
    convoffdg_k<<<1024, 256, C68_SMEM>>>(off_w, off_b, dg1_w, dg1_b, dg2_w, dg2_b);
    conv3x3_k<Cn,AUXn,96,false><<<1024, 256, C96_SMEM>>>(p_aux, base_w, base_b, p_ybase);
    // ---- deformable ----
    deform_combine_k<<<1024, 256, DEF_SMEM>>>(def_b);
    // ---- BN + residual relu ----
    bn_stats_k<<<Cn, 256>>>();
    bn_apply_k<<<dim3(HWn/1024, Cn, Bn), 256>>>(x, bn_g, bn_b, out);
}